// round 11
// baseline (speedup 1.0000x reference)
#include <cuda_runtime.h>
#include <cuda_fp16.h>
#include <math.h>
#include <cstdint>

// ============================================================
// Problem constants
// ============================================================
#define B_      8
#define SQ_     768
#define SKV1_   1024
#define D_      512
#define DF_     2048
#define H_      8
#define DH_     64
#define MQ_     (B_*SQ_)      // 6144
#define MKV1_   (B_*SKV1_)    // 8192

#if defined(__CUDA_ARCH__) && (defined(__CUDA_ARCH_FEAT_SM103_ALL) || \
                               defined(__CUDA_ARCH_FEAT_SM100_ALL) || \
                               (defined(__CUDA_ARCH_SPECIFIC__) && \
                                (__CUDA_ARCH_SPECIFIC__ == 1030 || __CUDA_ARCH_SPECIFIC__ == 1000)))
#define HAS_TCGEN05 1
#else
#define HAS_TCGEN05 0
#endif

// ------------------------------------------------------------
// Scratch (device globals; 16B+ alignment for cp.async.bulk)
// f16 GEMM operands in TILED layout: 8KB SW64-swizzled blocks
// keyed (128-row panel, 32-half k-slice).  v/v2 row-major.
// ------------------------------------------------------------
__device__ __align__(256) __half g_ca_h [MQ_  * D_];  __device__ __align__(256) __half g_ca_l [MQ_  * D_];
__device__ __align__(256) __half g_sp_h [MKV1_* D_];  __device__ __align__(256) __half g_sp_l [MKV1_* D_];
__device__ __align__(256) __half g_spd_h[MQ_  * D_];  __device__ __align__(256) __half g_spd_l[MQ_  * D_];
__device__ __align__(256) __half g_wq1h[D_*D_]; __device__ __align__(256) __half g_wq1l[D_*D_];
__device__ __align__(256) __half g_wk1h[D_*D_]; __device__ __align__(256) __half g_wk1l[D_*D_];
__device__ __align__(256) __half g_wv1h[D_*D_]; __device__ __align__(256) __half g_wv1l[D_*D_];
__device__ __align__(256) __half g_wo1h[D_*D_]; __device__ __align__(256) __half g_wo1l[D_*D_];
__device__ __align__(256) __half g_wq2h[D_*D_]; __device__ __align__(256) __half g_wq2l[D_*D_];
__device__ __align__(256) __half g_wk2h[D_*D_]; __device__ __align__(256) __half g_wk2l[D_*D_];
__device__ __align__(256) __half g_wv2h[D_*D_]; __device__ __align__(256) __half g_wv2l[D_*D_];
__device__ __align__(256) __half g_wo2h[D_*D_]; __device__ __align__(256) __half g_wo2l[D_*D_];
__device__ __align__(256) __half g_fw1h[DF_*D_]; __device__ __align__(256) __half g_fw1l[DF_*D_];
__device__ __align__(256) __half g_fw2h[DF_*D_]; __device__ __align__(256) __half g_fw2l[DF_*D_];
__device__ __align__(256) __half g_q_h [MQ_  * D_];  __device__ __align__(256) __half g_q_l [MQ_  * D_];
__device__ __align__(256) __half g_k_h [MKV1_* D_];  __device__ __align__(256) __half g_k_l [MKV1_* D_];
__device__ __align__(256) __half g_v   [MKV1_* D_];
__device__ __align__(256) __half g_k2h [MQ_  * D_];  __device__ __align__(256) __half g_k2l [MQ_  * D_];
__device__ __align__(256) __half g_v2  [MQ_  * D_];
__device__ __align__(256) __half g_at_h[MQ_  * D_];  __device__ __align__(256) __half g_at_l[MQ_  * D_];
__device__ __align__(256) __half g_x1h [MQ_  * D_];  __device__ __align__(256) __half g_x1l [MQ_  * D_];
__device__ __align__(256) __half g_x2h [MQ_  * D_];  __device__ __align__(256) __half g_x2l [MQ_  * D_];
__device__ __align__(256) __half g_h_h [MQ_  * DF_]; __device__ __align__(256) __half g_h_l [MQ_  * DF_];
__device__ float g_tmp[MQ_ * D_];
__device__ float g_x1 [MQ_ * D_];
__device__ float g_x2 [MQ_ * D_];
// fp32 fallback scratch (SIMT path)
__device__ float g_fa[MKV1_*D_];
__device__ float g_fb[MKV1_*D_];
__device__ float g_fc[MKV1_*D_];
__device__ float g_fd[MQ_*DF_];

// ============================================================
// Common helpers
// ============================================================
__device__ __forceinline__ float gelu_exact(float x) {
    return 0.5f * x * (1.0f + erff(x * 0.70710678118654752f));
}
__device__ __forceinline__ void h_split(float x, __half& h, __half& l) {
    h = __float2half_rn(x);
    l = __float2half_rn(x - __half2float(h));
}
__device__ __forceinline__ uint32_t pack2(__half a, __half b) {
    __half2 t = __halves2half2(a, b);
    return *(const uint32_t*)&t;
}
// Tiled layout: byte offset of (row, kcol) in [rows x K] f16 tensor
// stored as 8KB SW64-swizzled panel blocks.
__device__ __forceinline__ size_t tiled_off(int row, int kcol, int K) {
    size_t blk = (size_t)(row >> 7) * (K >> 5) + (kcol >> 5);
    uint32_t ib = (uint32_t)((row & 127) * 64 + (kcol & 31) * 2);
    ib ^= (ib >> 3) & 0x30;      // SW64 swizzle
    return blk * 8192 + ib;
}

// ============================================================
// Batched hi/lo split kernel (13 jobs) -> TILED outputs
// ============================================================
#define NSPLIT 13
struct SplitJobs {
    const float4* s[NSPLIT];
    char* h[NSPLIT];
    char* l[NSPLIT];
    int end[NSPLIT];
    int ksh[NSPLIT];   // log2(K)
};

__global__ __launch_bounds__(256)
void split_batch(SplitJobs jb)
{
    const int blk = blockIdx.x;
    int j = 0;
    #pragma unroll
    for (int t = 0; t < NSPLIT; t++) if (blk >= jb.end[t]) j = t + 1;
    const int b0 = (j == 0) ? 0 : jb.end[j - 1];
    const int idx = (blk - b0) * 256 + threadIdx.x;
    float4 x = jb.s[j][idx];
    __half h0, h1, h2, h3, l0, l1, l2, l3;
    h_split(x.x, h0, l0); h_split(x.y, h1, l1);
    h_split(x.z, h2, l2); h_split(x.w, h3, l3);
    const int ksh = jb.ksh[j];
    const int e0 = idx * 4;
    const int row = e0 >> ksh;
    const int kcol = e0 & ((1 << ksh) - 1);
    const size_t off = tiled_off(row, kcol, 1 << ksh);
    *(uint2*)(jb.h[j] + off) = make_uint2(pack2(h0, h1), pack2(h2, h3));
    *(uint2*)(jb.l[j] + off) = make_uint2(pack2(l0, l1), pack2(l2, l3));
}

#if HAS_TCGEN05
// ------------------------------------------------------------
// PTX helpers (sm_103a pass only)
// ------------------------------------------------------------
__device__ __forceinline__ uint32_t smem_u32(const void* smem_ptr) {
    uint32_t addr;
    asm("{ .reg .u64 tmp; cvta.to.shared.u64 tmp, %1; cvt.u32.u64 %0, tmp; }"
        : "=r"(addr) : "l"(smem_ptr));
    return addr;
}

#define MBARRIER_INIT(mbar, count) \
    asm volatile("mbarrier.init.shared.b64 [%0], %1;" \
        :: "r"((uint32_t)(mbar)), "r"((uint32_t)(count)) : "memory")

#define MBARRIER_EXPECT_TX(mbar, bytes) \
    asm volatile("mbarrier.arrive.expect_tx.shared.b64 _, [%0], %1;" \
        :: "r"((uint32_t)(mbar)), "r"((uint32_t)(bytes)) : "memory")

#define CP_BULK_G2S(dst, src, bytes, mbar) \
    asm volatile("cp.async.bulk.shared::cluster.global.mbarrier::complete_tx::bytes [%0], [%1], %2, [%3];" \
        :: "r"((uint32_t)(dst)), "l"(src), "r"((uint32_t)(bytes)), "r"((uint32_t)(mbar)) : "memory")

#define MBARRIER_WAIT_PARITY(mbar_smem_addr, phase_parity) do { \
    uint32_t _mbar = (uint32_t)(mbar_smem_addr); \
    uint32_t _parity = (uint32_t)(phase_parity); \
    uint32_t _done; \
    asm volatile( \
        "{\n\t" \
        ".reg .pred p;\n\t" \
        "mbarrier.try_wait.parity.acquire.cta.shared::cta.b64 p, [%1], %2;\n\t" \
        "selp.b32 %0, 1, 0, p;\n\t" \
        "}" \
        : "=r"(_done) : "r"(_mbar), "r"(_parity) : "memory"); \
    if (!_done) { \
        asm volatile( \
            "{\n\t" \
            ".reg .pred P1;\n\t" \
            "WAIT_LOOP_%=:\n\t" \
            "mbarrier.try_wait.parity.acquire.cta.shared::cta.b64 P1, [%0], %1, 0x989680;\n\t" \
            "@P1 bra.uni WAIT_DONE_%=;\n\t" \
            "bra.uni WAIT_LOOP_%=;\n\t" \
            "WAIT_DONE_%=:\n\t" \
            "}" \
            :: "r"(_mbar), "r"(_parity) : "memory"); \
    } \
} while(0)

#define TCGEN05_ALLOC(smem_result_addr, nCols) \
    asm volatile("tcgen05.alloc.cta_group::1.sync.aligned.shared::cta.b32 [%0], %1;" \
        :: "r"((uint32_t)(smem_result_addr)), "r"((uint32_t)(nCols)) : "memory")
#define TCGEN05_DEALLOC(tmem_addr, nCols) \
    asm volatile("tcgen05.dealloc.cta_group::1.sync.aligned.b32 %0, %1;" \
        :: "r"(tmem_addr), "r"(nCols))
#define TCGEN05_RELINQUISH() \
    asm volatile("tcgen05.relinquish_alloc_permit.cta_group::1.sync.aligned;")
#define TCGEN05_COMMIT(mbar_smem_addr) \
    asm volatile("tcgen05.commit.cta_group::1.mbarrier::arrive::one.shared::cluster.b64 [%0];" \
        :: "r"((uint32_t)(mbar_smem_addr)) : "memory")
#define TCGEN05_FENCE_AFTER() \
    asm volatile("tcgen05.fence::after_thread_sync;" ::: "memory")
#define TCGEN05_FENCE_BEFORE() \
    asm volatile("tcgen05.fence::before_thread_sync;" ::: "memory")
#define TCGEN05_WAIT_LD() \
    asm volatile("tcgen05.wait::ld.sync.aligned;" ::: "memory")
#define FENCE_PROXY_ASYNC_SHARED_CTA() \
    asm volatile("fence.proxy.async.shared::cta;" ::: "memory")

#define TCGEN05_LD_32X32B_X32(r, tmem_addr) \
    asm volatile( \
        "tcgen05.ld.sync.aligned.32x32b.x32.b32 " \
        "{%0, %1, %2, %3, %4, %5, %6, %7, " \
        " %8, %9, %10, %11, %12, %13, %14, %15, " \
        " %16, %17, %18, %19, %20, %21, %22, %23, " \
        " %24, %25, %26, %27, %28, %29, %30, %31}, [%32];" \
        : "=r"((r)[0]),  "=r"((r)[1]),  "=r"((r)[2]),  "=r"((r)[3]), \
          "=r"((r)[4]),  "=r"((r)[5]),  "=r"((r)[6]),  "=r"((r)[7]), \
          "=r"((r)[8]),  "=r"((r)[9]),  "=r"((r)[10]), "=r"((r)[11]), \
          "=r"((r)[12]), "=r"((r)[13]), "=r"((r)[14]), "=r"((r)[15]), \
          "=r"((r)[16]), "=r"((r)[17]), "=r"((r)[18]), "=r"((r)[19]), \
          "=r"((r)[20]), "=r"((r)[21]), "=r"((r)[22]), "=r"((r)[23]), \
          "=r"((r)[24]), "=r"((r)[25]), "=r"((r)[26]), "=r"((r)[27]), \
          "=r"((r)[28]), "=r"((r)[29]), "=r"((r)[30]), "=r"((r)[31]) \
        : "r"(tmem_addr))

#define SMEM_DESC_BASE_SW128 \
    ((uint64_t(2)  << 61) | (uint64_t(1) << 46) | \
     (uint64_t(64) << 32) | (uint64_t(1) << 16))
#define MAKE_SMEM_DESC(base_addr) \
    (SMEM_DESC_BASE_SW128 | ((uint64_t)((base_addr) >> 4) & 0x3FFF))
#define SMEM_DESC_BASE_SW64 \
    ((uint64_t(4)  << 61) | (uint64_t(1) << 46) | \
     (uint64_t(32) << 32) | (uint64_t(1) << 16))
#define MAKE_SMEM_DESC_SW64(base_addr) \
    (SMEM_DESC_BASE_SW64 | ((uint64_t)((base_addr) >> 4) & 0x3FFF))

#define SMEM_SWIZZLE_128B(byte_offset) \
    ((byte_offset) ^ (((byte_offset) >> 3) & 0x70))

__device__ __forceinline__ void tcgen05_mma_f16_ss(
    uint32_t d_tmem, uint64_t a_desc, uint64_t b_desc,
    uint32_t idesc, uint32_t enable)
{
    asm volatile(
        "{\n\t"
        ".reg .pred p;\n\t"
        "setp.ne.u32 p, %6, 0;\n\t"
        "tcgen05.mma.cta_group::1.kind::f16 [%0], %1, %2, %3, "
        "{%4, %4, %4, %4}, p;\n\t"
        "}"
        :: "r"(d_tmem), "l"(a_desc), "l"(b_desc), "r"(idesc),
           "r"(0u), "r"(0u), "r"(enable)
        : "memory");
}

#define IDESC_G2 0x8400010u   // M=128, N=256
#define IDESC_G  0x8200010u   // M=128, N=128
#define IDESC_PV 0x8100010u   // M=128, N=64
#endif  // HAS_TCGEN05

// ============================================================
// tcgen05 F16 3-term GEMM, BN=256 tiles (N=256 MMA).
//   TILED A/W inputs, bulk-copy, 2-stage pipeline (48KB/stage),
//   occ 2, TMEM 256 cols.  EPI: 1 +bias+res f32 | 2 gelu->tiled
//   split | 3 tiled split | 4 row-major f16 round
// ============================================================
#define GT_STAGE(buf) (1024 + (buf) * 49152)
// within stage: Ah +0, Al +8K, Wh +16K (2 panels, 16KB), Wl +32K (16KB)
#define GT_SMEM_BYTES (1024 + 2 * 49152)   // 99328 -> 2 CTAs/SM

template<int EPI>
__global__ __launch_bounds__(256, 2)
void tc_gemm(void* __restrict__ Cp, void* __restrict__ C2p,
             const __half* __restrict__ Ah, const __half* __restrict__ Al,
             const __half* __restrict__ Wh, const __half* __restrict__ Wl,
             const float* __restrict__ bias, const float* __restrict__ res,
             int M, int N, int K)
{
#if HAS_TCGEN05
    extern __shared__ __align__(1024) char gsm[];
    const uint32_t sb = smem_u32(gsm);
    const int tid  = threadIdx.x;
    const int wid  = tid >> 5;
    const int lane = tid & 31;

    if (tid == 0) {
        MBARRIER_INIT(sb + 8, 1);   // mma buf0
        MBARRIER_INIT(sb + 16, 1);  // mma buf1
        MBARRIER_INIT(sb + 32, 1);  // load buf0
        MBARRIER_INIT(sb + 40, 1);  // load buf1
        FENCE_PROXY_ASYNC_SHARED_CTA();
    }
    if (wid == 0) {
        TCGEN05_ALLOC(sb + 0, 256);
        TCGEN05_RELINQUISH();
    }
    __syncthreads();
    uint32_t tmem;
    asm volatile("ld.shared.b32 %0, [%1];" : "=r"(tmem) : "r"(sb + 0));

    const int iters = K >> 5;
    const int kb = K >> 5;

    if (tid == 0) {
        const char* Ahc  = (const char*)Ah + (size_t)(blockIdx.y) * kb * 8192;
        const char* Alc  = (const char*)Al + (size_t)(blockIdx.y) * kb * 8192;
        const char* Whc0 = (const char*)Wh + (size_t)(2 * blockIdx.x)     * kb * 8192;
        const char* Whc1 = (const char*)Wh + (size_t)(2 * blockIdx.x + 1) * kb * 8192;
        const char* Wlc0 = (const char*)Wl + (size_t)(2 * blockIdx.x)     * kb * 8192;
        const char* Wlc1 = (const char*)Wl + (size_t)(2 * blockIdx.x + 1) * kb * 8192;

        // Prologue: stages 0 and 1
        #pragma unroll
        for (int s = 0; s < 2; s++) {
            MBARRIER_EXPECT_TX(sb + 32 + s * 8, 49152);
            CP_BULK_G2S(sb + GT_STAGE(s) + 0,     Ahc  + (size_t)s * 8192, 8192, sb + 32 + s * 8);
            CP_BULK_G2S(sb + GT_STAGE(s) + 8192,  Alc  + (size_t)s * 8192, 8192, sb + 32 + s * 8);
            CP_BULK_G2S(sb + GT_STAGE(s) + 16384, Whc0 + (size_t)s * 8192, 8192, sb + 32 + s * 8);
            CP_BULK_G2S(sb + GT_STAGE(s) + 24576, Whc1 + (size_t)s * 8192, 8192, sb + 32 + s * 8);
            CP_BULK_G2S(sb + GT_STAGE(s) + 32768, Wlc0 + (size_t)s * 8192, 8192, sb + 32 + s * 8);
            CP_BULK_G2S(sb + GT_STAGE(s) + 40960, Wlc1 + (size_t)s * 8192, 8192, sb + 32 + s * 8);
        }

        for (int i = 0; i < iters; i++) {
            const int b = i & 1;
            MBARRIER_WAIT_PARITY(sb + 32 + b * 8, (i >> 1) & 1);

            const uint64_t dAh = MAKE_SMEM_DESC_SW64(sb + GT_STAGE(b) + 0);
            const uint64_t dAl = MAKE_SMEM_DESC_SW64(sb + GT_STAGE(b) + 8192);
            const uint64_t dBh = MAKE_SMEM_DESC_SW64(sb + GT_STAGE(b) + 16384);
            const uint64_t dBl = MAKE_SMEM_DESC_SW64(sb + GT_STAGE(b) + 32768);
            #pragma unroll
            for (int kk = 0; kk < 2; kk++) {
                const uint64_t o = kk * 2;
                tcgen05_mma_f16_ss(tmem, dAh + o, dBh + o, IDESC_G2,
                                   (i > 0 || kk > 0) ? 1u : 0u);
                tcgen05_mma_f16_ss(tmem, dAl + o, dBh + o, IDESC_G2, 1u);
                tcgen05_mma_f16_ss(tmem, dAh + o, dBl + o, IDESC_G2, 1u);
            }
            TCGEN05_COMMIT(sb + 8 + b * 8);

            const int j2 = i + 2;
            if (j2 < iters) {
                // buffer b reused for tile j2: needs MMA(i) done
                MBARRIER_WAIT_PARITY(sb + 8 + b * 8, (i >> 1) & 1);
                MBARRIER_EXPECT_TX(sb + 32 + b * 8, 49152);
                CP_BULK_G2S(sb + GT_STAGE(b) + 0,     Ahc  + (size_t)j2 * 8192, 8192, sb + 32 + b * 8);
                CP_BULK_G2S(sb + GT_STAGE(b) + 8192,  Alc  + (size_t)j2 * 8192, 8192, sb + 32 + b * 8);
                CP_BULK_G2S(sb + GT_STAGE(b) + 16384, Whc0 + (size_t)j2 * 8192, 8192, sb + 32 + b * 8);
                CP_BULK_G2S(sb + GT_STAGE(b) + 24576, Whc1 + (size_t)j2 * 8192, 8192, sb + 32 + b * 8);
                CP_BULK_G2S(sb + GT_STAGE(b) + 32768, Wlc0 + (size_t)j2 * 8192, 8192, sb + 32 + b * 8);
                CP_BULK_G2S(sb + GT_STAGE(b) + 40960, Wlc1 + (size_t)j2 * 8192, 8192, sb + 32 + b * 8);
            }
        }
    }

    __syncthreads();
    MBARRIER_WAIT_PARITY(sb + 8 + ((iters - 1) & 1) * 8, ((iters - 1) >> 1) & 1);
    TCGEN05_FENCE_AFTER();

    // Epilogue: warp (sub, h2); h2 picks a 128-col half; 4 LDTM x32 each.
    {
        const int bm = blockIdx.y * 128;
        const int bn = blockIdx.x * 256;
        const int sub = wid & 3;
        const int h2  = wid >> 2;
        const int row = bm + sub * 32 + lane;
        #pragma unroll
        for (int q = 0; q < 4; q++) {
            uint32_t r[32];
            TCGEN05_LD_32X32B_X32(r, tmem + h2 * 128 + q * 32);
            TCGEN05_WAIT_LD();
            #pragma unroll
            for (int c4 = 0; c4 < 8; c4++) {
                const int col = bn + h2 * 128 + q * 32 + c4 * 4;
                float4 v;
                v.x = __uint_as_float(r[c4 * 4 + 0]);
                v.y = __uint_as_float(r[c4 * 4 + 1]);
                v.z = __uint_as_float(r[c4 * 4 + 2]);
                v.w = __uint_as_float(r[c4 * 4 + 3]);
                if (EPI == 1 || EPI == 2) {
                    float4 bi = *(const float4*)&bias[col];
                    v.x += bi.x; v.y += bi.y; v.z += bi.z; v.w += bi.w;
                }
                if (EPI == 1) {
                    float4 rv = *(const float4*)&res[(size_t)row * N + col];
                    v.x += rv.x; v.y += rv.y; v.z += rv.z; v.w += rv.w;
                    *(float4*)((float*)Cp + (size_t)row * N + col) = v;
                }
                if (EPI == 2) {
                    v.x = gelu_exact(v.x); v.y = gelu_exact(v.y);
                    v.z = gelu_exact(v.z); v.w = gelu_exact(v.w);
                }
                if (EPI == 2 || EPI == 3) {   // tiled f16 split
                    __half h0,h1,h2_,h3,l0,l1,l2,l3;
                    h_split(v.x,h0,l0); h_split(v.y,h1,l1);
                    h_split(v.z,h2_,l2); h_split(v.w,h3,l3);
                    const size_t off = tiled_off(row, col, N);
                    *(uint2*)((char*)Cp  + off) = make_uint2(pack2(h0,h1), pack2(h2_,h3));
                    *(uint2*)((char*)C2p + off) = make_uint2(pack2(l0,l1), pack2(l2,l3));
                }
                if (EPI == 4) {               // row-major f16 (v for flash)
                    *(uint2*)((__half*)Cp + (size_t)row * N + col) =
                        make_uint2(pack2(__float2half_rn(v.x), __float2half_rn(v.y)),
                                   pack2(__float2half_rn(v.z), __float2half_rn(v.w)));
                }
            }
        }
    }

    __syncthreads();
    if (wid == 0) TCGEN05_DEALLOC(tmem, 256);
#endif
}

// ============================================================
// tcgen05 f16 flash attention — unchanged R10 (bulk Q/K, SW64 S,
// SW128 P/V^T, unnormalized softmax, tiled split O).
// ============================================================
#define TF_QH    1024
#define TF_QL    (TF_QH + 16384)
#define TF_KH    (TF_QH + 32768)
#define TF_KL    (TF_QH + 49152)
#define TF_VT    (TF_QH + 65536)
#define TF_P     (TF_QH + 81920)
#define TF_SMEM_BYTES (TF_P + 32768)  // 115712

template<int MASK>
__global__ __launch_bounds__(256, 2)
void tc_flash(__half* __restrict__ Oh, __half* __restrict__ Ol,
              const __half* __restrict__ Qh, const __half* __restrict__ Ql,
              const __half* __restrict__ Kh, const __half* __restrict__ Kl,
              const __half* __restrict__ Vp, int kvlen)
{
#if HAS_TCGEN05
    extern __shared__ __align__(1024) char fsm[];
    const uint32_t sb = smem_u32(fsm);
    const int tid  = threadIdx.x;
    const int wid  = tid >> 5;
    const int lane = tid & 31;
    const int sub  = wid & 3;
    const int h2   = wid >> 2;
    const int q0   = blockIdx.x * 128;
    const int h    = blockIdx.y;
    const int b    = blockIdx.z;

    if (tid == 0) {
        MBARRIER_INIT(sb + 8, 1);    // S done
        MBARRIER_INIT(sb + 16, 1);   // PV done
        MBARRIER_INIT(sb + 24, 1);   // Q loaded
        MBARRIER_INIT(sb + 32, 1);   // K loaded
        FENCE_PROXY_ASYNC_SHARED_CTA();
    }
    if (wid == 0) {
        TCGEN05_ALLOC(sb + 0, 256);
        TCGEN05_RELINQUISH();
    }
    __syncthreads();
    uint32_t tmem;
    asm volatile("ld.shared.b32 %0, [%1];" : "=r"(tmem) : "r"(sb + 0));

    const size_t qblk = ((size_t)((b * SQ_ + q0) >> 7) * 16 + 2 * h) * 8192;
    if (tid == 0) {
        MBARRIER_EXPECT_TX(sb + 24, 32768);
        CP_BULK_G2S(sb + TF_QH, (const char*)Qh + qblk, 16384, sb + 24);
        CP_BULK_G2S(sb + TF_QL, (const char*)Ql + qblk, 16384, sb + 24);
        const size_t kblk = ((size_t)((b * kvlen) >> 7) * 16 + 2 * h) * 8192;
        MBARRIER_EXPECT_TX(sb + 32, 32768);
        CP_BULK_G2S(sb + TF_KH, (const char*)Kh + kblk, 16384, sb + 32);
        CP_BULK_G2S(sb + TF_KL, (const char*)Kl + kblk, 16384, sb + 32);
    }

    float lsum = 0.f;
    const int qrow = sub * 32 + lane;
    const int qg   = q0 + qrow;

    const int ntiles = kvlen >> 7;
    for (int t = 0; t < ntiles; t++) {
        const int kv0 = t << 7;

        if (tid == 0) {
            if (t == 0) MBARRIER_WAIT_PARITY(sb + 24, 0);
            MBARRIER_WAIT_PARITY(sb + 32, t & 1);
            #pragma unroll
            for (int blk = 0; blk < 2; blk++) {
                const uint64_t dQh = MAKE_SMEM_DESC_SW64(sb + TF_QH + blk * 8192);
                const uint64_t dQl = MAKE_SMEM_DESC_SW64(sb + TF_QL + blk * 8192);
                const uint64_t dKh = MAKE_SMEM_DESC_SW64(sb + TF_KH + blk * 8192);
                const uint64_t dKl = MAKE_SMEM_DESC_SW64(sb + TF_KL + blk * 8192);
                #pragma unroll
                for (int kk = 0; kk < 2; kk++) {
                    const uint64_t o = kk * 2;
                    tcgen05_mma_f16_ss(tmem + 64, dQh + o, dKh + o, IDESC_G,
                                       (blk == 0 && kk == 0) ? 0u : 1u);
                    tcgen05_mma_f16_ss(tmem + 64, dQl + o, dKh + o, IDESC_G, 1u);
                    tcgen05_mma_f16_ss(tmem + 64, dQh + o, dKl + o, IDESC_G, 1u);
                }
            }
            TCGEN05_COMMIT(sb + 8);
        }

        if (t > 0) {
            MBARRIER_WAIT_PARITY(sb + 16, (t - 1) & 1);
        }
        {
            const int row  = tid >> 1;
            const int half = tid & 1;
            const __half* vb = Vp + (size_t)(b * kvlen + kv0 + row) * D_ + h * DH_ + half * 32;
            char* VT = fsm + TF_VT + (row >> 6) * 8192;
            const int kvin = row & 63;
            #pragma unroll
            for (int c4 = 0; c4 < 4; c4++) {
                uint4 u = *(const uint4*)(vb + c4 * 8);
                const __half2* hp = (const __half2*)&u;
                #pragma unroll
                for (int p = 0; p < 4; p++) {
                    const int d0 = half * 32 + c4 * 8 + p * 2;
                    *(__half*)(VT + SMEM_SWIZZLE_128B((uint32_t)((d0 + 0) * 128 + kvin * 2))) = __low2half(hp[p]);
                    *(__half*)(VT + SMEM_SWIZZLE_128B((uint32_t)((d0 + 1) * 128 + kvin * 2))) = __high2half(hp[p]);
                }
            }
        }

        MBARRIER_WAIT_PARITY(sb + 8, t & 1);
        TCGEN05_FENCE_AFTER();
        if (tid == 0 && t + 1 < ntiles) {
            const size_t kblk = ((size_t)((b * kvlen + kv0 + 128) >> 7) * 16 + 2 * h) * 8192;
            MBARRIER_EXPECT_TX(sb + 32, 32768);
            CP_BULK_G2S(sb + TF_KH, (const char*)Kh + kblk, 16384, sb + 32);
            CP_BULK_G2S(sb + TF_KL, (const char*)Kl + kblk, 16384, sb + 32);
        }

        #pragma unroll
        for (int chunk = 0; chunk < 2; chunk++) {
            uint32_t r[32];
            TCGEN05_LD_32X32B_X32(r, tmem + 64 + h2 * 64 + chunk * 32);
            TCGEN05_WAIT_LD();
            const int kvb = h2 * 64 + chunk * 32;
            char* Pp = fsm + TF_P + h2 * 16384;
            #pragma unroll
            for (int c16 = 0; c16 < 4; c16++) {
                uint32_t w[4];
                #pragma unroll
                for (int pr = 0; pr < 4; pr++) {
                    __half hs[2];
                    #pragma unroll
                    for (int j = 0; j < 2; j++) {
                        const float s = __uint_as_float(r[c16 * 8 + pr * 2 + j]);
                        const int kg = kv0 + kvb + c16 * 8 + pr * 2 + j;
                        float wm;
                        if (MASK == 1) wm = ((qg < 512) == (kg < 512)) ? 1.25f : 1.0f;
                        else           wm = ((qg >> 8)  == (kg >> 8))  ? 1.25f : 1.0f;
                        const float p = __expf(s * (0.125f * wm));
                        hs[j] = __float2half_rn(p);
                        lsum += __half2float(hs[j]);
                    }
                    w[pr] = pack2(hs[0], hs[1]);
                }
                const uint32_t sw = SMEM_SWIZZLE_128B(
                    (uint32_t)(qrow * 128 + chunk * 64 + c16 * 16));
                *(uint4*)(Pp + sw) = make_uint4(w[0], w[1], w[2], w[3]);
            }
        }
        TCGEN05_FENCE_BEFORE();
        __syncthreads();

        if (tid == 0) {
            FENCE_PROXY_ASYNC_SHARED_CTA();
            #pragma unroll
            for (int p2 = 0; p2 < 2; p2++) {
                const uint64_t dP = MAKE_SMEM_DESC(sb + TF_P  + p2 * 16384);
                const uint64_t dV = MAKE_SMEM_DESC(sb + TF_VT + p2 * 8192);
                #pragma unroll
                for (int kk = 0; kk < 4; kk++) {
                    const uint64_t o = kk * 2;
                    tcgen05_mma_f16_ss(tmem, dP + o, dV + o, IDESC_PV,
                                       (t == 0 && p2 == 0 && kk == 0) ? 0u : 1u);
                }
            }
            TCGEN05_COMMIT(sb + 16);
        }
    }

    MBARRIER_WAIT_PARITY(sb + 16, (ntiles - 1) & 1);
    TCGEN05_FENCE_AFTER();

    {
        float* lx = (float*)(fsm + TF_VT);
        lx[wid * 32 + lane] = lsum;
    }
    __syncthreads();
    const float lother = ((float*)(fsm + TF_VT))[(wid ^ 4) * 32 + lane];
    const float inv = 1.0f / (lsum + lother);

    {
        uint32_t r[32];
        TCGEN05_LD_32X32B_X32(r, tmem + h2 * 32);
        TCGEN05_WAIT_LD();
        const int orow = b * SQ_ + qg;
        #pragma unroll
        for (int c4 = 0; c4 < 8; c4++) {
            __half h0,h1,h2_,h3,l0,l1,l2,l3;
            h_split(__uint_as_float(r[c4*4+0]) * inv, h0, l0);
            h_split(__uint_as_float(r[c4*4+1]) * inv, h1, l1);
            h_split(__uint_as_float(r[c4*4+2]) * inv, h2_, l2);
            h_split(__uint_as_float(r[c4*4+3]) * inv, h3, l3);
            const size_t off = tiled_off(orow, h * DH_ + h2 * 32 + c4 * 4, D_);
            *(uint2*)((char*)Oh + off) = make_uint2(pack2(h0,h1), pack2(h2_,h3));
            *(uint2*)((char*)Ol + off) = make_uint2(pack2(l0,l1), pack2(l2,l3));
        }
    }

    __syncthreads();
    if (wid == 0) TCGEN05_DEALLOC(tmem, 256);
#endif  // HAS_TCGEN05
}

// ============================================================
// SIMT SGEMM fallback (round-1 proven, fp32)
// ============================================================
template<int EPI>
__global__ __launch_bounds__(256)
void sgemm_kernel(float* __restrict__ C,
                  const float* __restrict__ A,
                  const float* __restrict__ W,
                  const float* __restrict__ bias,
                  const float* __restrict__ res,
                  int M, int N, int K)
{
    __shared__ float As[8][128];
    __shared__ float Bs[8][128];

    const int tid = threadIdx.x;
    const int bm  = blockIdx.y * 128;
    const int bn  = blockIdx.x * 128;

    const int lr = tid >> 1;
    const int lc = (tid & 1) * 4;
    const float* Aptr = A + (size_t)(bm + lr) * K + lc;
    const float* Wptr = W + (size_t)(bn + lr) * K + lc;

    const int ty = tid >> 4;
    const int tx = tid & 15;

    float acc[8][8];
    #pragma unroll
    for (int i = 0; i < 8; i++)
        #pragma unroll
        for (int j = 0; j < 8; j++) acc[i][j] = 0.f;

    for (int k0 = 0; k0 < K; k0 += 8) {
        float4 a4 = *(const float4*)(Aptr + k0);
        float4 b4 = *(const float4*)(Wptr + k0);
        As[lc + 0][lr] = a4.x; As[lc + 1][lr] = a4.y;
        As[lc + 2][lr] = a4.z; As[lc + 3][lr] = a4.w;
        Bs[lc + 0][lr] = b4.x; Bs[lc + 1][lr] = b4.y;
        Bs[lc + 2][lr] = b4.z; Bs[lc + 3][lr] = b4.w;
        __syncthreads();

        #pragma unroll
        for (int kk = 0; kk < 8; kk++) {
            float ra[8], rb[8];
            *(float4*)(ra)     = *(const float4*)&As[kk][ty * 4];
            *(float4*)(ra + 4) = *(const float4*)&As[kk][ty * 4 + 64];
            *(float4*)(rb)     = *(const float4*)&Bs[kk][tx * 4];
            *(float4*)(rb + 4) = *(const float4*)&Bs[kk][tx * 4 + 64];
            #pragma unroll
            for (int i = 0; i < 8; i++)
                #pragma unroll
                for (int j = 0; j < 8; j++)
                    acc[i][j] += ra[i] * rb[j];
        }
        __syncthreads();
    }

    #pragma unroll
    for (int i = 0; i < 8; i++) {
        const int row = bm + ty * 4 + (i & 3) + (i >> 2) * 64;
        #pragma unroll
        for (int jh = 0; jh < 2; jh++) {
            const int col = bn + tx * 4 + jh * 64;
            float4 v;
            v.x = acc[i][jh * 4 + 0];
            v.y = acc[i][jh * 4 + 1];
            v.z = acc[i][jh * 4 + 2];
            v.w = acc[i][jh * 4 + 3];
            if (EPI >= 1) {
                float4 bi = *(const float4*)&bias[col];
                v.x += bi.x; v.y += bi.y; v.z += bi.z; v.w += bi.w;
            }
            if (EPI == 1) {
                float4 rv = *(const float4*)&res[(size_t)row * N + col];
                v.x += rv.x; v.y += rv.y; v.z += rv.z; v.w += rv.w;
            }
            if (EPI == 2) {
                v.x = gelu_exact(v.x); v.y = gelu_exact(v.y);
                v.z = gelu_exact(v.z); v.w = gelu_exact(v.w);
            }
            *(float4*)&C[(size_t)row * N + col] = v;
        }
    }
}

// ============================================================
// SIMT flash attention fallback (round-1 proven, fp32)
// ============================================================
#define FA_STRIDE 68
#define FA_SMEM_FLOATS ((128 + 64 + 64 + 128) * FA_STRIDE)
#define FA_SMEM_BYTES  (FA_SMEM_FLOATS * 4)

template<int MASK>
__global__ __launch_bounds__(256)
void flash_kernel(float* __restrict__ O,
                  const float* __restrict__ Q,
                  const float* __restrict__ Kp,
                  const float* __restrict__ Vp,
                  int kvlen)
{
    extern __shared__ float fsm2[];
    float* Qs = fsm2;
    float* Ks = Qs + 128 * FA_STRIDE;
    float* Vt = Ks + 64  * FA_STRIDE;
    float* Ps = Vt + 64  * FA_STRIDE;

    const int tid = threadIdx.x;
    const int q0  = blockIdx.x * 128;
    const int h   = blockIdx.y;
    const int b   = blockIdx.z;
    const int rg  = tid >> 4;
    const int cg  = tid & 15;

    {
        const int qrow = tid >> 1;
        const int half = tid & 1;
        const float* qbase = Q + (size_t)(b * SQ_ + q0 + qrow) * D_ + h * DH_;
        #pragma unroll
        for (int i = 0; i < 8; i++) {
            const int f4 = half * 8 + i;
            *(float4*)&Qs[qrow * FA_STRIDE + f4 * 4] = *(const float4*)&qbase[f4 * 4];
        }
    }

    float m_i[8], l_i[8], oacc[8][4];
    #pragma unroll
    for (int u = 0; u < 8; u++) {
        m_i[u] = -1e30f; l_i[u] = 0.f;
        #pragma unroll
        for (int t = 0; t < 4; t++) oacc[u][t] = 0.f;
    }

    const int ntiles = kvlen >> 6;
    for (int t0 = 0; t0 < ntiles; t0++) {
        const int kv0 = t0 * 64;
        __syncthreads();

        {
            const int lrow = tid >> 2;
            const int lq   = tid & 3;
            const float* kbase = Kp + (size_t)(b * kvlen + kv0 + lrow) * D_ + h * DH_;
            const float* vbase = Vp + (size_t)(b * kvlen + kv0 + lrow) * D_ + h * DH_;
            #pragma unroll
            for (int i = 0; i < 4; i++) {
                const int f4 = lq * 4 + i;
                float4 k4 = *(const float4*)&kbase[f4 * 4];
                *(float4*)&Ks[lrow * FA_STRIDE + f4 * 4] = k4;
                float4 v4 = *(const float4*)&vbase[f4 * 4];
                const int d0 = f4 * 4;
                Vt[(d0 + 0) * FA_STRIDE + lrow] = v4.x;
                Vt[(d0 + 1) * FA_STRIDE + lrow] = v4.y;
                Vt[(d0 + 2) * FA_STRIDE + lrow] = v4.z;
                Vt[(d0 + 3) * FA_STRIDE + lrow] = v4.w;
            }
        }
        __syncthreads();

        float sacc[8][4];
        #pragma unroll
        for (int u = 0; u < 8; u++)
            #pragma unroll
            for (int t = 0; t < 4; t++) sacc[u][t] = 0.f;

        #pragma unroll
        for (int d4 = 0; d4 < 16; d4++) {
            float4 qv[8];
            #pragma unroll
            for (int u = 0; u < 8; u++)
                qv[u] = *(const float4*)&Qs[(rg + 16 * u) * FA_STRIDE + d4 * 4];
            #pragma unroll
            for (int t = 0; t < 4; t++) {
                float4 kk = *(const float4*)&Ks[(cg + 16 * t) * FA_STRIDE + d4 * 4];
                #pragma unroll
                for (int u = 0; u < 8; u++)
                    sacc[u][t] += qv[u].x * kk.x + qv[u].y * kk.y
                                + qv[u].z * kk.z + qv[u].w * kk.w;
            }
        }

        #pragma unroll
        for (int u = 0; u < 8; u++) {
            const int qg = q0 + rg + 16 * u;
            #pragma unroll
            for (int t = 0; t < 4; t++) {
                const int kg = kv0 + cg + 16 * t;
                float wm;
                if (MASK == 1) wm = ((qg < 512) == (kg < 512)) ? 1.25f : 1.0f;
                else           wm = ((qg >> 8)  == (kg >> 8))  ? 1.25f : 1.0f;
                sacc[u][t] *= 0.125f * wm;
            }
        }

        #pragma unroll
        for (int u = 0; u < 8; u++) {
            float rmax = fmaxf(fmaxf(sacc[u][0], sacc[u][1]),
                               fmaxf(sacc[u][2], sacc[u][3]));
            #pragma unroll
            for (int off = 8; off >= 1; off >>= 1)
                rmax = fmaxf(rmax, __shfl_xor_sync(0xffffffffu, rmax, off));
            const float mnew  = fmaxf(m_i[u], rmax);
            const float alpha = __expf(m_i[u] - mnew);
            m_i[u] = mnew;
            float rsum = 0.f;
            #pragma unroll
            for (int t = 0; t < 4; t++) {
                const float p = __expf(sacc[u][t] - mnew);
                Ps[(rg + 16 * u) * FA_STRIDE + cg + 16 * t] = p;
                rsum += p;
            }
            #pragma unroll
            for (int off = 8; off >= 1; off >>= 1)
                rsum += __shfl_xor_sync(0xffffffffu, rsum, off);
            l_i[u] = l_i[u] * alpha + rsum;
            #pragma unroll
            for (int t = 0; t < 4; t++) oacc[u][t] *= alpha;
        }
        __syncthreads();

        #pragma unroll
        for (int j4 = 0; j4 < 16; j4++) {
            float4 pv[8];
            #pragma unroll
            for (int u = 0; u < 8; u++)
                pv[u] = *(const float4*)&Ps[(rg + 16 * u) * FA_STRIDE + j4 * 4];
            #pragma unroll
            for (int t = 0; t < 4; t++) {
                float4 vv = *(const float4*)&Vt[(cg + 16 * t) * FA_STRIDE + j4 * 4];
                #pragma unroll
                for (int u = 0; u < 8; u++)
                    oacc[u][t] += pv[u].x * vv.x + pv[u].y * vv.y
                                + pv[u].z * vv.z + pv[u].w * vv.w;
            }
        }
    }

    #pragma unroll
    for (int u = 0; u < 8; u++) {
        const float inv = 1.0f / l_i[u];
        const size_t row = (size_t)(b * SQ_ + q0 + rg + 16 * u);
        #pragma unroll
        for (int t = 0; t < 4; t++)
            O[row * D_ + h * DH_ + cg + 16 * t] = oacc[u][t] * inv;
    }
}

// ============================================================
// LayerNorm over D=512; SPLIT=1 also emits TILED f16 hi/lo split
// ============================================================
template<int SPLIT>
__global__ __launch_bounds__(256)
void layernorm_kernel(float* __restrict__ out,
                      __half* __restrict__ oh, __half* __restrict__ ol,
                      const float* __restrict__ in,
                      const float* __restrict__ g, const float* __restrict__ b,
                      int rows)
{
    const int gt   = blockIdx.x * 256 + threadIdx.x;
    const int row  = gt >> 5;
    const int lane = gt & 31;
    if (row >= rows) return;

    const float* x = in + (size_t)row * D_;
    float4 v[4];
    float s = 0.f;
    #pragma unroll
    for (int i = 0; i < 4; i++) {
        v[i] = *(const float4*)&x[(lane + i * 32) * 4];
        s += v[i].x + v[i].y + v[i].z + v[i].w;
    }
    #pragma unroll
    for (int o = 16; o; o >>= 1) s += __shfl_xor_sync(0xffffffffu, s, o);
    const float mean = s * (1.0f / 512.0f);

    float var = 0.f;
    #pragma unroll
    for (int i = 0; i < 4; i++) {
        float dx = v[i].x - mean; var += dx * dx;
        dx = v[i].y - mean; var += dx * dx;
        dx = v[i].z - mean; var += dx * dx;
        dx = v[i].w - mean; var += dx * dx;
    }
    #pragma unroll
    for (int o = 16; o; o >>= 1) var += __shfl_xor_sync(0xffffffffu, var, o);
    const float rstd = rsqrtf(var * (1.0f / 512.0f) + 1e-5f);

    #pragma unroll
    for (int i = 0; i < 4; i++) {
        const int c = (lane + i * 32) * 4;
        float4 gv = *(const float4*)&g[c];
        float4 bv = *(const float4*)&b[c];
        float4 o4;
        o4.x = (v[i].x - mean) * rstd * gv.x + bv.x;
        o4.y = (v[i].y - mean) * rstd * gv.y + bv.y;
        o4.z = (v[i].z - mean) * rstd * gv.z + bv.z;
        o4.w = (v[i].w - mean) * rstd * gv.w + bv.w;
        *(float4*)&out[(size_t)row * D_ + c] = o4;
        if (SPLIT) {
            __half h0,h1,h2,h3,l0,l1,l2,l3;
            h_split(o4.x,h0,l0); h_split(o4.y,h1,l1);
            h_split(o4.z,h2,l2); h_split(o4.w,h3,l3);
            const size_t off = tiled_off(row, c, D_);
            *(uint2*)((char*)oh + off) = make_uint2(pack2(h0,h1), pack2(h2,h3));
            *(uint2*)((char*)ol + off) = make_uint2(pack2(l0,l1), pack2(l2,l3));
        }
    }
}

// ============================================================
// Launch
// ============================================================
static void* sym(const void* symbol) {
    void* p = nullptr;
    cudaGetSymbolAddress(&p, symbol);
    return p;
}

extern "C" void kernel_launch(void* const* d_in, const int* in_sizes, int n_in,
                              void* d_out, int out_size)
{
    const float* cords   = (const float*)d_in[0];
    const float* spatial = (const float*)d_in[1];
    const float* speed   = (const float*)d_in[2];
    const float* wq1 = (const float*)d_in[3];
    const float* wk1 = (const float*)d_in[4];
    const float* wv1 = (const float*)d_in[5];
    const float* wo1 = (const float*)d_in[6];
    const float* bo1 = (const float*)d_in[7];
    const float* wq2 = (const float*)d_in[8];
    const float* wk2 = (const float*)d_in[9];
    const float* wv2 = (const float*)d_in[10];
    const float* wo2 = (const float*)d_in[11];
    const float* bo2 = (const float*)d_in[12];
    const float* ln1_g = (const float*)d_in[13];
    const float* ln1_b = (const float*)d_in[14];
    const float* ln2_g = (const float*)d_in[15];
    const float* ln2_b = (const float*)d_in[16];
    const float* ln3_g = (const float*)d_in[17];
    const float* ln3_b = (const float*)d_in[18];
    const float* ffn_w1 = (const float*)d_in[19];
    const float* ffn_b1 = (const float*)d_in[20];
    const float* ffn_w2 = (const float*)d_in[21];
    const float* ffn_b2 = (const float*)d_in[22];
    float* out = (float*)d_out;

    cudaFuncAttributes fa{};
    bool tc1 = false, tc2 = false;
    if (cudaFuncGetAttributes(&fa, (const void*)tc_gemm<1>) == cudaSuccess)
        tc1 = (fa.numRegs >= 32);
    if (cudaFuncGetAttributes(&fa, (const void*)tc_flash<1>) == cudaSuccess)
        tc2 = (fa.numRegs >= 32);
    const bool use_tc = tc1 && tc2;

    static cudaStream_t s1 = nullptr, s2 = nullptr, s3 = nullptr;
    static cudaEvent_t  evF = nullptr, ev1 = nullptr, ev2 = nullptr, ev3 = nullptr;
    static int sinit = 0;
    if (sinit == 0) {
        bool ok = true;
        ok &= (cudaStreamCreateWithFlags(&s1, cudaStreamNonBlocking) == cudaSuccess);
        ok &= (cudaStreamCreateWithFlags(&s2, cudaStreamNonBlocking) == cudaSuccess);
        ok &= (cudaStreamCreateWithFlags(&s3, cudaStreamNonBlocking) == cudaSuccess);
        ok &= (cudaEventCreateWithFlags(&evF, cudaEventDisableTiming) == cudaSuccess);
        ok &= (cudaEventCreateWithFlags(&ev1, cudaEventDisableTiming) == cudaSuccess);
        ok &= (cudaEventCreateWithFlags(&ev2, cudaEventDisableTiming) == cudaSuccess);
        ok &= (cudaEventCreateWithFlags(&ev3, cudaEventDisableTiming) == cudaSuccess);
        sinit = ok ? 1 : -1;
    }
    const bool multi = (sinit == 1) && use_tc;
    cudaStream_t t1 = multi ? s1 : 0;
    cudaStream_t t2 = multi ? s2 : 0;
    cudaStream_t t3 = multi ? s3 : 0;

    // BN=256 grids
    const dim3 gProj(D_ / 256, MQ_ / 128);     // (2, 48)
    const dim3 gKV1 (D_ / 256, MKV1_ / 128);   // (2, 64)
    const dim3 gFFN1(DF_ / 256, MQ_ / 128);    // (8, 48)
    const dim3 gFA  (SQ_ / 128, H_, B_);       // (6, 8, 8)
    const int  lnBlocks = MQ_ * 32 / 256;      // 768

    float* tmp = (float*)sym(g_tmp);
    float* x1  = (float*)sym(g_x1);
    float* x2  = (float*)sym(g_x2);

    if (use_tc) {
        cudaFuncSetAttribute((const void*)tc_gemm<1>, cudaFuncAttributeMaxDynamicSharedMemorySize, GT_SMEM_BYTES);
        cudaFuncSetAttribute((const void*)tc_gemm<2>, cudaFuncAttributeMaxDynamicSharedMemorySize, GT_SMEM_BYTES);
        cudaFuncSetAttribute((const void*)tc_gemm<3>, cudaFuncAttributeMaxDynamicSharedMemorySize, GT_SMEM_BYTES);
        cudaFuncSetAttribute((const void*)tc_gemm<4>, cudaFuncAttributeMaxDynamicSharedMemorySize, GT_SMEM_BYTES);
        cudaFuncSetAttribute((const void*)tc_flash<1>, cudaFuncAttributeMaxDynamicSharedMemorySize, TF_SMEM_BYTES);
        cudaFuncSetAttribute((const void*)tc_flash<2>, cudaFuncAttributeMaxDynamicSharedMemorySize, TF_SMEM_BYTES);

        // ---- split inputs + weights -> tiled f16 hi/lo (one launch) ----
        SplitJobs jb{};
        const float* srcs[NSPLIT] = {cords, spatial, speed,
                                     wq1, wk1, wv1, wo1, wq2, wk2, wv2, wo2,
                                     ffn_w1, ffn_w2};
        void* dsth[NSPLIT] = {sym(g_ca_h), sym(g_sp_h), sym(g_spd_h),
                              sym(g_wq1h), sym(g_wk1h), sym(g_wv1h), sym(g_wo1h),
                              sym(g_wq2h), sym(g_wk2h), sym(g_wv2h), sym(g_wo2h),
                              sym(g_fw1h), sym(g_fw2h)};
        void* dstl[NSPLIT] = {sym(g_ca_l), sym(g_sp_l), sym(g_spd_l),
                              sym(g_wq1l), sym(g_wk1l), sym(g_wv1l), sym(g_wo1l),
                              sym(g_wq2l), sym(g_wk2l), sym(g_wv2l), sym(g_wo2l),
                              sym(g_fw1l), sym(g_fw2l)};
        const int nelts[NSPLIT] = {MQ_*D_, MKV1_*D_, MQ_*D_,
                                   D_*D_, D_*D_, D_*D_, D_*D_,
                                   D_*D_, D_*D_, D_*D_, D_*D_,
                                   DF_*D_, DF_*D_};
        const int kshs[NSPLIT] = {9,9,9, 9,9,9,9, 9,9,9,9, 9,11};
        int acc = 0;
        for (int j = 0; j < NSPLIT; j++) {
            jb.s[j] = (const float4*)srcs[j];
            jb.h[j] = (char*)dsth[j];
            jb.l[j] = (char*)dstl[j];
            acc += nelts[j] / 1024;
            jb.end[j] = acc;
            jb.ksh[j] = kshs[j];
        }
        split_batch<<<acc, 256>>>(jb);

        __half* qh = (__half*)sym(g_q_h), *ql = (__half*)sym(g_q_l);
        __half* kh = (__half*)sym(g_k_h), *kl = (__half*)sym(g_k_l);
        __half* vv = (__half*)sym(g_v);
        __half* k2h = (__half*)sym(g_k2h), *k2l = (__half*)sym(g_k2l);
        __half* v2 = (__half*)sym(g_v2);
        __half* ath = (__half*)sym(g_at_h), *atl = (__half*)sym(g_at_l);
        __half* x1h = (__half*)sym(g_x1h), *x1l = (__half*)sym(g_x1l);
        __half* x2h = (__half*)sym(g_x2h), *x2l = (__half*)sym(g_x2l);
        __half* hh = (__half*)sym(g_h_h), *hl = (__half*)sym(g_h_l);

        // ---- Fork: q1 on 0; k1/v1 on s1/s2; k2/v2 on s3 ----
        if (multi) {
            cudaEventRecord(evF, 0);
            cudaStreamWaitEvent(s1, evF, 0);
            cudaStreamWaitEvent(s2, evF, 0);
            cudaStreamWaitEvent(s3, evF, 0);
        }
        tc_gemm<3><<<gProj, 256, GT_SMEM_BYTES, 0 >>>(qh, ql, (__half*)sym(g_ca_h), (__half*)sym(g_ca_l), (__half*)sym(g_wq1h), (__half*)sym(g_wq1l), nullptr, nullptr, MQ_, D_, D_);
        tc_gemm<3><<<gKV1,  256, GT_SMEM_BYTES, t1>>>(kh, kl, (__half*)sym(g_sp_h), (__half*)sym(g_sp_l), (__half*)sym(g_wk1h), (__half*)sym(g_wk1l), nullptr, nullptr, MKV1_, D_, D_);
        tc_gemm<4><<<gKV1,  256, GT_SMEM_BYTES, t2>>>(vv, nullptr, (__half*)sym(g_sp_h), (__half*)sym(g_sp_l), (__half*)sym(g_wv1h), (__half*)sym(g_wv1l), nullptr, nullptr, MKV1_, D_, D_);
        tc_gemm<3><<<gProj, 256, GT_SMEM_BYTES, t3>>>(k2h, k2l, (__half*)sym(g_spd_h), (__half*)sym(g_spd_l), (__half*)sym(g_wk2h), (__half*)sym(g_wk2l), nullptr, nullptr, MQ_, D_, D_);
        tc_gemm<4><<<gProj, 256, GT_SMEM_BYTES, t3>>>(v2, nullptr, (__half*)sym(g_spd_h), (__half*)sym(g_spd_l), (__half*)sym(g_wv2h), (__half*)sym(g_wv2l), nullptr, nullptr, MQ_, D_, D_);
        if (multi) {
            cudaEventRecord(ev1, s1);
            cudaEventRecord(ev2, s2);
            cudaEventRecord(ev3, s3);
            cudaStreamWaitEvent(0, ev1, 0);
            cudaStreamWaitEvent(0, ev2, 0);
        }

        // ---- Stage 1 tail ----
        tc_flash<1><<<gFA, 256, TF_SMEM_BYTES>>>(ath, atl, qh, ql, kh, kl, vv, SKV1_);
        tc_gemm<1><<<gProj, 256, GT_SMEM_BYTES>>>(tmp, nullptr, ath, atl, (__half*)sym(g_wo1h), (__half*)sym(g_wo1l), bo1, cords, MQ_, D_, D_);
        layernorm_kernel<1><<<lnBlocks, 256>>>(x1, x1h, x1l, tmp, ln1_g, ln1_b, MQ_);

        // ---- Stage 2 ----
        tc_gemm<3><<<gProj, 256, GT_SMEM_BYTES>>>(qh, ql, x1h, x1l, (__half*)sym(g_wq2h), (__half*)sym(g_wq2l), nullptr, nullptr, MQ_, D_, D_);
        if (multi) cudaStreamWaitEvent(0, ev3, 0);
        tc_flash<2><<<gFA, 256, TF_SMEM_BYTES>>>(ath, atl, qh, ql, k2h, k2l, v2, SQ_);
        tc_gemm<1><<<gProj, 256, GT_SMEM_BYTES>>>(tmp, nullptr, ath, atl, (__half*)sym(g_wo2h), (__half*)sym(g_wo2l), bo2, x1, MQ_, D_, D_);
        layernorm_kernel<1><<<lnBlocks, 256>>>(x2, x2h, x2l, tmp, ln2_g, ln2_b, MQ_);

        // ---- Stage 3: FFN ----
        tc_gemm<2><<<gFFN1, 256, GT_SMEM_BYTES>>>(hh, hl, x2h, x2l, (__half*)sym(g_fw1h), (__half*)sym(g_fw1l), ffn_b1, nullptr, MQ_, DF_, D_);
        tc_gemm<1><<<gProj, 256, GT_SMEM_BYTES>>>(tmp, nullptr, hh, hl, (__half*)sym(g_fw2h), (__half*)sym(g_fw2l), ffn_b2, x2, MQ_, D_, DF_);
        layernorm_kernel<0><<<lnBlocks, 256>>>(out, nullptr, nullptr, tmp, ln3_g, ln3_b, MQ_);
    } else {
        // -------- full SIMT fallback (round-1 proven path) --------
        cudaFuncSetAttribute((const void*)flash_kernel<1>, cudaFuncAttributeMaxDynamicSharedMemorySize, FA_SMEM_BYTES);
        cudaFuncSetAttribute((const void*)flash_kernel<2>, cudaFuncAttributeMaxDynamicSharedMemorySize, FA_SMEM_BYTES);
        float* q = (float*)sym(g_fa);
        float* k = (float*)sym(g_fb);
        float* v = (float*)sym(g_fc);
        float* attn = (float*)sym(g_fd);
        float* hbuf = (float*)sym(g_fd);

        const dim3 fProj(D_ / 128, MQ_ / 128);
        const dim3 fKV1 (D_ / 128, MKV1_ / 128);
        const dim3 fFFN1(DF_ / 128, MQ_ / 128);

        sgemm_kernel<0><<<fProj, 256>>>(q, cords,   wq1, nullptr, nullptr, MQ_,   D_, D_);
        sgemm_kernel<0><<<fKV1,  256>>>(k, spatial, wk1, nullptr, nullptr, MKV1_, D_, D_);
        sgemm_kernel<0><<<fKV1,  256>>>(v, spatial, wv1, nullptr, nullptr, MKV1_, D_, D_);
        flash_kernel<1><<<gFA, 256, FA_SMEM_BYTES>>>(attn, q, k, v, SKV1_);
        sgemm_kernel<1><<<fProj, 256>>>(tmp, attn, wo1, bo1, cords, MQ_, D_, D_);
        layernorm_kernel<0><<<lnBlocks, 256>>>(x1, nullptr, nullptr, tmp, ln1_g, ln1_b, MQ_);

        sgemm_kernel<0><<<fProj, 256>>>(q, x1,    wq2, nullptr, nullptr, MQ_, D_, D_);
        sgemm_kernel<0><<<fProj, 256>>>(k, speed, wk2, nullptr, nullptr, MQ_, D_, D_);
        sgemm_kernel<0><<<fProj, 256>>>(v, speed, wv2, nullptr, nullptr, MQ_, D_, D_);
        flash_kernel<2><<<gFA, 256, FA_SMEM_BYTES>>>(attn, q, k, v, SQ_);
        sgemm_kernel<1><<<fProj, 256>>>(tmp, attn, wo2, bo2, x1, MQ_, D_, D_);
        layernorm_kernel<0><<<lnBlocks, 256>>>(x2, nullptr, nullptr, tmp, ln2_g, ln2_b, MQ_);

        sgemm_kernel<2><<<fFFN1, 256>>>(hbuf, x2, ffn_w1, ffn_b1, nullptr, MQ_, DF_, D_);
        sgemm_kernel<1><<<fProj, 256>>>(tmp, hbuf, ffn_w2, ffn_b2, x2, MQ_, D_, DF_);
        layernorm_kernel<0><<<lnBlocks, 256>>>(out, nullptr, nullptr, tmp, ln3_g, ln3_b, MQ_);
    }
}

// round 12
// speedup vs baseline: 1.1579x; 1.1579x over previous
#include <cuda_runtime.h>
#include <cuda_fp16.h>
#include <math.h>
#include <cstdint>

// ============================================================
// Problem constants
// ============================================================
#define B_      8
#define SQ_     768
#define SKV1_   1024
#define D_      512
#define DF_     2048
#define H_      8
#define DH_     64
#define MQ_     (B_*SQ_)      // 6144
#define MKV1_   (B_*SKV1_)    // 8192

#if defined(__CUDA_ARCH__) && (defined(__CUDA_ARCH_FEAT_SM103_ALL) || \
                               defined(__CUDA_ARCH_FEAT_SM100_ALL) || \
                               (defined(__CUDA_ARCH_SPECIFIC__) && \
                                (__CUDA_ARCH_SPECIFIC__ == 1030 || __CUDA_ARCH_SPECIFIC__ == 1000)))
#define HAS_TCGEN05 1
#else
#define HAS_TCGEN05 0
#endif

// ------------------------------------------------------------
// Scratch (device globals; 16B+ alignment for cp.async.bulk)
// f16 GEMM operands in TILED layout: 8KB SW64-swizzled blocks
// keyed (128-row panel, 32-half k-slice).
// V is stored PRE-TRANSPOSED: 8KB SW128 panels [64 kv-rows x head],
// byte image identical to flash's smem V^T tile.
// ------------------------------------------------------------
__device__ __align__(256) __half g_ca_h [MQ_  * D_];  __device__ __align__(256) __half g_ca_l [MQ_  * D_];
__device__ __align__(256) __half g_sp_h [MKV1_* D_];  __device__ __align__(256) __half g_sp_l [MKV1_* D_];
__device__ __align__(256) __half g_spd_h[MQ_  * D_];  __device__ __align__(256) __half g_spd_l[MQ_  * D_];
__device__ __align__(256) __half g_wq1h[D_*D_]; __device__ __align__(256) __half g_wq1l[D_*D_];
__device__ __align__(256) __half g_wk1h[D_*D_]; __device__ __align__(256) __half g_wk1l[D_*D_];
__device__ __align__(256) __half g_wv1h[D_*D_]; __device__ __align__(256) __half g_wv1l[D_*D_];
__device__ __align__(256) __half g_wo1h[D_*D_]; __device__ __align__(256) __half g_wo1l[D_*D_];
__device__ __align__(256) __half g_wq2h[D_*D_]; __device__ __align__(256) __half g_wq2l[D_*D_];
__device__ __align__(256) __half g_wk2h[D_*D_]; __device__ __align__(256) __half g_wk2l[D_*D_];
__device__ __align__(256) __half g_wv2h[D_*D_]; __device__ __align__(256) __half g_wv2l[D_*D_];
__device__ __align__(256) __half g_wo2h[D_*D_]; __device__ __align__(256) __half g_wo2l[D_*D_];
__device__ __align__(256) __half g_fw1h[DF_*D_]; __device__ __align__(256) __half g_fw1l[DF_*D_];
__device__ __align__(256) __half g_fw2h[DF_*D_]; __device__ __align__(256) __half g_fw2l[DF_*D_];
__device__ __align__(256) __half g_q_h [MQ_  * D_];  __device__ __align__(256) __half g_q_l [MQ_  * D_];
__device__ __align__(256) __half g_k_h [MKV1_* D_];  __device__ __align__(256) __half g_k_l [MKV1_* D_];
__device__ __align__(256) __half g_v   [MKV1_* D_];   // vT panels
__device__ __align__(256) __half g_k2h [MQ_  * D_];  __device__ __align__(256) __half g_k2l [MQ_  * D_];
__device__ __align__(256) __half g_v2  [MQ_  * D_];   // vT panels
__device__ __align__(256) __half g_at_h[MQ_  * D_];  __device__ __align__(256) __half g_at_l[MQ_  * D_];
__device__ __align__(256) __half g_x1h [MQ_  * D_];  __device__ __align__(256) __half g_x1l [MQ_  * D_];
__device__ __align__(256) __half g_x2h [MQ_  * D_];  __device__ __align__(256) __half g_x2l [MQ_  * D_];
__device__ __align__(256) __half g_h_h [MQ_  * DF_]; __device__ __align__(256) __half g_h_l [MQ_  * DF_];
__device__ float g_tmp[MQ_ * D_];
__device__ float g_x1 [MQ_ * D_];
__device__ float g_x2 [MQ_ * D_];
// fp32 fallback scratch (SIMT path)
__device__ float g_fa[MKV1_*D_];
__device__ float g_fb[MKV1_*D_];
__device__ float g_fc[MKV1_*D_];
__device__ float g_fd[MQ_*DF_];

// ============================================================
// Common helpers
// ============================================================
__device__ __forceinline__ float gelu_exact(float x) {
    return 0.5f * x * (1.0f + erff(x * 0.70710678118654752f));
}
__device__ __forceinline__ void h_split(float x, __half& h, __half& l) {
    h = __float2half_rn(x);
    l = __float2half_rn(x - __half2float(h));
}
__device__ __forceinline__ uint32_t pack2(__half a, __half b) {
    __half2 t = __halves2half2(a, b);
    return *(const uint32_t*)&t;
}
// Tiled layout: byte offset of (row, kcol) in [rows x K] f16 tensor
// stored as 8KB SW64-swizzled panel blocks.
__device__ __forceinline__ size_t tiled_off(int row, int kcol, int K) {
    size_t blk = (size_t)(row >> 7) * (K >> 5) + (kcol >> 5);
    uint32_t ib = (uint32_t)((row & 127) * 64 + (kcol & 31) * 2);
    ib ^= (ib >> 3) & 0x30;      // SW64 swizzle
    return blk * 8192 + ib;
}
#define SWZ128(x) ((x) ^ (((x) >> 3) & 0x70))
// vT layout: 8KB SW128 panel per (64-row kv panel, head).
// byte offset of (absolute kv row, col=h*64+d):
__device__ __forceinline__ size_t vt_off(int row, int col) {
    size_t blk = (size_t)(row >> 6) * 8 + (col >> 6);
    uint32_t ib = SWZ128((uint32_t)((col & 63) * 128 + (row & 63) * 2));
    return blk * 8192 + ib;
}

// ============================================================
// Batched hi/lo split kernel (13 jobs) -> TILED outputs
// ============================================================
#define NSPLIT 13
struct SplitJobs {
    const float4* s[NSPLIT];
    char* h[NSPLIT];
    char* l[NSPLIT];
    int end[NSPLIT];
    int ksh[NSPLIT];   // log2(K)
};

__global__ __launch_bounds__(256)
void split_batch(SplitJobs jb)
{
    const int blk = blockIdx.x;
    int j = 0;
    #pragma unroll
    for (int t = 0; t < NSPLIT; t++) if (blk >= jb.end[t]) j = t + 1;
    const int b0 = (j == 0) ? 0 : jb.end[j - 1];
    const int idx = (blk - b0) * 256 + threadIdx.x;
    float4 x = jb.s[j][idx];
    __half h0, h1, h2, h3, l0, l1, l2, l3;
    h_split(x.x, h0, l0); h_split(x.y, h1, l1);
    h_split(x.z, h2, l2); h_split(x.w, h3, l3);
    const int ksh = jb.ksh[j];
    const int e0 = idx * 4;
    const int row = e0 >> ksh;
    const int kcol = e0 & ((1 << ksh) - 1);
    const size_t off = tiled_off(row, kcol, 1 << ksh);
    *(uint2*)(jb.h[j] + off) = make_uint2(pack2(h0, h1), pack2(h2, h3));
    *(uint2*)(jb.l[j] + off) = make_uint2(pack2(l0, l1), pack2(l2, l3));
}

#if HAS_TCGEN05
// ------------------------------------------------------------
// PTX helpers (sm_103a pass only)
// ------------------------------------------------------------
__device__ __forceinline__ uint32_t smem_u32(const void* smem_ptr) {
    uint32_t addr;
    asm("{ .reg .u64 tmp; cvta.to.shared.u64 tmp, %1; cvt.u32.u64 %0, tmp; }"
        : "=r"(addr) : "l"(smem_ptr));
    return addr;
}

#define MBARRIER_INIT(mbar, count) \
    asm volatile("mbarrier.init.shared.b64 [%0], %1;" \
        :: "r"((uint32_t)(mbar)), "r"((uint32_t)(count)) : "memory")

#define MBARRIER_EXPECT_TX(mbar, bytes) \
    asm volatile("mbarrier.arrive.expect_tx.shared.b64 _, [%0], %1;" \
        :: "r"((uint32_t)(mbar)), "r"((uint32_t)(bytes)) : "memory")

#define CP_BULK_G2S(dst, src, bytes, mbar) \
    asm volatile("cp.async.bulk.shared::cluster.global.mbarrier::complete_tx::bytes [%0], [%1], %2, [%3];" \
        :: "r"((uint32_t)(dst)), "l"(src), "r"((uint32_t)(bytes)), "r"((uint32_t)(mbar)) : "memory")

#define MBARRIER_WAIT_PARITY(mbar_smem_addr, phase_parity) do { \
    uint32_t _mbar = (uint32_t)(mbar_smem_addr); \
    uint32_t _parity = (uint32_t)(phase_parity); \
    uint32_t _done; \
    asm volatile( \
        "{\n\t" \
        ".reg .pred p;\n\t" \
        "mbarrier.try_wait.parity.acquire.cta.shared::cta.b64 p, [%1], %2;\n\t" \
        "selp.b32 %0, 1, 0, p;\n\t" \
        "}" \
        : "=r"(_done) : "r"(_mbar), "r"(_parity) : "memory"); \
    if (!_done) { \
        asm volatile( \
            "{\n\t" \
            ".reg .pred P1;\n\t" \
            "WAIT_LOOP_%=:\n\t" \
            "mbarrier.try_wait.parity.acquire.cta.shared::cta.b64 P1, [%0], %1, 0x989680;\n\t" \
            "@P1 bra.uni WAIT_DONE_%=;\n\t" \
            "bra.uni WAIT_LOOP_%=;\n\t" \
            "WAIT_DONE_%=:\n\t" \
            "}" \
            :: "r"(_mbar), "r"(_parity) : "memory"); \
    } \
} while(0)

#define TCGEN05_ALLOC(smem_result_addr, nCols) \
    asm volatile("tcgen05.alloc.cta_group::1.sync.aligned.shared::cta.b32 [%0], %1;" \
        :: "r"((uint32_t)(smem_result_addr)), "r"((uint32_t)(nCols)) : "memory")
#define TCGEN05_DEALLOC(tmem_addr, nCols) \
    asm volatile("tcgen05.dealloc.cta_group::1.sync.aligned.b32 %0, %1;" \
        :: "r"(tmem_addr), "r"(nCols))
#define TCGEN05_RELINQUISH() \
    asm volatile("tcgen05.relinquish_alloc_permit.cta_group::1.sync.aligned;")
#define TCGEN05_COMMIT(mbar_smem_addr) \
    asm volatile("tcgen05.commit.cta_group::1.mbarrier::arrive::one.shared::cluster.b64 [%0];" \
        :: "r"((uint32_t)(mbar_smem_addr)) : "memory")
#define TCGEN05_FENCE_AFTER() \
    asm volatile("tcgen05.fence::after_thread_sync;" ::: "memory")
#define TCGEN05_FENCE_BEFORE() \
    asm volatile("tcgen05.fence::before_thread_sync;" ::: "memory")
#define TCGEN05_WAIT_LD() \
    asm volatile("tcgen05.wait::ld.sync.aligned;" ::: "memory")
#define FENCE_PROXY_ASYNC_SHARED_CTA() \
    asm volatile("fence.proxy.async.shared::cta;" ::: "memory")

#define TCGEN05_LD_32X32B_X32(r, tmem_addr) \
    asm volatile( \
        "tcgen05.ld.sync.aligned.32x32b.x32.b32 " \
        "{%0, %1, %2, %3, %4, %5, %6, %7, " \
        " %8, %9, %10, %11, %12, %13, %14, %15, " \
        " %16, %17, %18, %19, %20, %21, %22, %23, " \
        " %24, %25, %26, %27, %28, %29, %30, %31}, [%32];" \
        : "=r"((r)[0]),  "=r"((r)[1]),  "=r"((r)[2]),  "=r"((r)[3]), \
          "=r"((r)[4]),  "=r"((r)[5]),  "=r"((r)[6]),  "=r"((r)[7]), \
          "=r"((r)[8]),  "=r"((r)[9]),  "=r"((r)[10]), "=r"((r)[11]), \
          "=r"((r)[12]), "=r"((r)[13]), "=r"((r)[14]), "=r"((r)[15]), \
          "=r"((r)[16]), "=r"((r)[17]), "=r"((r)[18]), "=r"((r)[19]), \
          "=r"((r)[20]), "=r"((r)[21]), "=r"((r)[22]), "=r"((r)[23]), \
          "=r"((r)[24]), "=r"((r)[25]), "=r"((r)[26]), "=r"((r)[27]), \
          "=r"((r)[28]), "=r"((r)[29]), "=r"((r)[30]), "=r"((r)[31]) \
        : "r"(tmem_addr))

#define SMEM_DESC_BASE_SW128 \
    ((uint64_t(2)  << 61) | (uint64_t(1) << 46) | \
     (uint64_t(64) << 32) | (uint64_t(1) << 16))
#define MAKE_SMEM_DESC(base_addr) \
    (SMEM_DESC_BASE_SW128 | ((uint64_t)((base_addr) >> 4) & 0x3FFF))
#define SMEM_DESC_BASE_SW64 \
    ((uint64_t(4)  << 61) | (uint64_t(1) << 46) | \
     (uint64_t(32) << 32) | (uint64_t(1) << 16))
#define MAKE_SMEM_DESC_SW64(base_addr) \
    (SMEM_DESC_BASE_SW64 | ((uint64_t)((base_addr) >> 4) & 0x3FFF))

#define SMEM_SWIZZLE_128B(byte_offset) \
    ((byte_offset) ^ (((byte_offset) >> 3) & 0x70))

__device__ __forceinline__ void tcgen05_mma_f16_ss(
    uint32_t d_tmem, uint64_t a_desc, uint64_t b_desc,
    uint32_t idesc, uint32_t enable)
{
    asm volatile(
        "{\n\t"
        ".reg .pred p;\n\t"
        "setp.ne.u32 p, %6, 0;\n\t"
        "tcgen05.mma.cta_group::1.kind::f16 [%0], %1, %2, %3, "
        "{%4, %4, %4, %4}, p;\n\t"
        "}"
        :: "r"(d_tmem), "l"(a_desc), "l"(b_desc), "r"(idesc),
           "r"(0u), "r"(0u), "r"(enable)
        : "memory");
}

#define IDESC_G  0x8200010u   // M=128, N=128
#define IDESC_PV 0x8100010u   // M=128, N=64
#endif  // HAS_TCGEN05

// ============================================================
// tcgen05 F16 3-term GEMM (R10 proven): TILED A/W, bulk-copy,
// BK=32, 3 stages, occ 2, single-producer-thread mainloop.
//   EPI: 1 +bias+res f32 | 2 gelu->tiled split | 3 tiled split |
//        4 -> vT panels (pre-transposed f16 for flash)
// ============================================================
#define GT_TILE(buf, which) (1024 + (buf) * 32768 + (which) * 8192)
#define GT_SMEM_BYTES (1024 + 3 * 32768)   // 99328 -> 2 CTAs/SM

template<int EPI>
__global__ __launch_bounds__(256, 2)
void tc_gemm(void* __restrict__ Cp, void* __restrict__ C2p,
             const __half* __restrict__ Ah, const __half* __restrict__ Al,
             const __half* __restrict__ Wh, const __half* __restrict__ Wl,
             const float* __restrict__ bias, const float* __restrict__ res,
             int M, int N, int K)
{
#if HAS_TCGEN05
    extern __shared__ __align__(1024) char gsm[];
    const uint32_t sb = smem_u32(gsm);
    const int tid  = threadIdx.x;
    const int wid  = tid >> 5;
    const int lane = tid & 31;

    if (tid == 0) {
        MBARRIER_INIT(sb + 8, 1);   // mma buf0
        MBARRIER_INIT(sb + 16, 1);  // mma buf1
        MBARRIER_INIT(sb + 24, 1);  // mma buf2
        MBARRIER_INIT(sb + 32, 1);  // load buf0
        MBARRIER_INIT(sb + 40, 1);  // load buf1
        MBARRIER_INIT(sb + 48, 1);  // load buf2
        FENCE_PROXY_ASYNC_SHARED_CTA();
    }
    if (wid == 0) {
        TCGEN05_ALLOC(sb + 0, 128);
        TCGEN05_RELINQUISH();
    }
    __syncthreads();
    uint32_t tmem;
    asm volatile("ld.shared.b32 %0, [%1];" : "=r"(tmem) : "r"(sb + 0));

    const int iters = K >> 5;
    const int kb = K >> 5;

    if (tid == 0) {
        const char* Ahc = (const char*)Ah + (size_t)(blockIdx.y) * kb * 8192;
        const char* Alc = (const char*)Al + (size_t)(blockIdx.y) * kb * 8192;
        const char* Whc = (const char*)Wh + (size_t)(blockIdx.x) * kb * 8192;
        const char* Wlc = (const char*)Wl + (size_t)(blockIdx.x) * kb * 8192;

        #pragma unroll
        for (int s = 0; s < 2; s++) {
            MBARRIER_EXPECT_TX(sb + 32 + s * 8, 32768);
            CP_BULK_G2S(sb + GT_TILE(s, 0), Ahc + (size_t)s * 8192, 8192, sb + 32 + s * 8);
            CP_BULK_G2S(sb + GT_TILE(s, 1), Alc + (size_t)s * 8192, 8192, sb + 32 + s * 8);
            CP_BULK_G2S(sb + GT_TILE(s, 2), Whc + (size_t)s * 8192, 8192, sb + 32 + s * 8);
            CP_BULK_G2S(sb + GT_TILE(s, 3), Wlc + (size_t)s * 8192, 8192, sb + 32 + s * 8);
        }

        for (int i = 0; i < iters; i++) {
            const int b = i % 3;
            MBARRIER_WAIT_PARITY(sb + 32 + b * 8, (i / 3) & 1);

            const uint64_t dAh = MAKE_SMEM_DESC_SW64(sb + GT_TILE(b, 0));
            const uint64_t dAl = MAKE_SMEM_DESC_SW64(sb + GT_TILE(b, 1));
            const uint64_t dBh = MAKE_SMEM_DESC_SW64(sb + GT_TILE(b, 2));
            const uint64_t dBl = MAKE_SMEM_DESC_SW64(sb + GT_TILE(b, 3));
            #pragma unroll
            for (int kk = 0; kk < 2; kk++) {
                const uint64_t o = kk * 2;
                tcgen05_mma_f16_ss(tmem, dAh + o, dBh + o, IDESC_G,
                                   (i > 0 || kk > 0) ? 1u : 0u);
                tcgen05_mma_f16_ss(tmem, dAl + o, dBh + o, IDESC_G, 1u);
                tcgen05_mma_f16_ss(tmem, dAh + o, dBl + o, IDESC_G, 1u);
            }
            TCGEN05_COMMIT(sb + 8 + b * 8);

            const int j2 = i + 2;
            if (j2 < iters) {
                const int b2 = j2 % 3;
                if (i >= 1)
                    MBARRIER_WAIT_PARITY(sb + 8 + ((i - 1) % 3) * 8,
                                         ((i - 1) / 3) & 1);
                MBARRIER_EXPECT_TX(sb + 32 + b2 * 8, 32768);
                CP_BULK_G2S(sb + GT_TILE(b2, 0), Ahc + (size_t)j2 * 8192, 8192, sb + 32 + b2 * 8);
                CP_BULK_G2S(sb + GT_TILE(b2, 1), Alc + (size_t)j2 * 8192, 8192, sb + 32 + b2 * 8);
                CP_BULK_G2S(sb + GT_TILE(b2, 2), Whc + (size_t)j2 * 8192, 8192, sb + 32 + b2 * 8);
                CP_BULK_G2S(sb + GT_TILE(b2, 3), Wlc + (size_t)j2 * 8192, 8192, sb + 32 + b2 * 8);
            }
        }
    }

    __syncthreads();
    MBARRIER_WAIT_PARITY(sb + 8 + ((iters - 1) % 3) * 8, ((iters - 1) / 3) & 1);
    TCGEN05_FENCE_AFTER();

    // Epilogue
    {
        const int bm = blockIdx.y * 128;
        const int bn = blockIdx.x * 128;
        const int sub = wid & 3;
        const int h2  = wid >> 2;
        const int row = bm + sub * 32 + lane;
        #pragma unroll
        for (int q = 0; q < 2; q++) {
            uint32_t r[32];
            TCGEN05_LD_32X32B_X32(r, tmem + h2 * 64 + q * 32);
            TCGEN05_WAIT_LD();
            #pragma unroll
            for (int c4 = 0; c4 < 8; c4++) {
                const int col = bn + h2 * 64 + q * 32 + c4 * 4;
                float4 v;
                v.x = __uint_as_float(r[c4 * 4 + 0]);
                v.y = __uint_as_float(r[c4 * 4 + 1]);
                v.z = __uint_as_float(r[c4 * 4 + 2]);
                v.w = __uint_as_float(r[c4 * 4 + 3]);
                if (EPI == 1 || EPI == 2) {
                    float4 bi = *(const float4*)&bias[col];
                    v.x += bi.x; v.y += bi.y; v.z += bi.z; v.w += bi.w;
                }
                if (EPI == 1) {
                    float4 rv = *(const float4*)&res[(size_t)row * N + col];
                    v.x += rv.x; v.y += rv.y; v.z += rv.z; v.w += rv.w;
                    *(float4*)((float*)Cp + (size_t)row * N + col) = v;
                }
                if (EPI == 2) {
                    v.x = gelu_exact(v.x); v.y = gelu_exact(v.y);
                    v.z = gelu_exact(v.z); v.w = gelu_exact(v.w);
                }
                if (EPI == 2 || EPI == 3) {   // tiled f16 split
                    __half h0,h1,h2_,h3,l0,l1,l2,l3;
                    h_split(v.x,h0,l0); h_split(v.y,h1,l1);
                    h_split(v.z,h2_,l2); h_split(v.w,h3,l3);
                    const size_t off = tiled_off(row, col, N);
                    *(uint2*)((char*)Cp  + off) = make_uint2(pack2(h0,h1), pack2(h2_,h3));
                    *(uint2*)((char*)C2p + off) = make_uint2(pack2(l0,l1), pack2(l2,l3));
                }
                if (EPI == 4) {   // pre-transposed vT panels (f16 round)
                    char* base = (char*)Cp;
                    *(__half*)(base + vt_off(row, col + 0)) = __float2half_rn(v.x);
                    *(__half*)(base + vt_off(row, col + 1)) = __float2half_rn(v.y);
                    *(__half*)(base + vt_off(row, col + 2)) = __float2half_rn(v.z);
                    *(__half*)(base + vt_off(row, col + 3)) = __float2half_rn(v.w);
                }
            }
        }
    }

    __syncthreads();
    if (wid == 0) TCGEN05_DEALLOC(tmem, 128);
#endif
}

// ============================================================
// tcgen05 f16 flash attention: Q/K TILED bulk (SW64 S) and now
// V^T PRE-TRANSPOSED bulk (SW128 PV) — no in-kernel transpose.
// ============================================================
#define TF_QH    1024
#define TF_QL    (TF_QH + 16384)
#define TF_KH    (TF_QH + 32768)
#define TF_KL    (TF_QH + 49152)
#define TF_VT    (TF_QH + 65536)   // 2 panels x 8 KB (SW128)
#define TF_P     (TF_QH + 81920)   // 2 panels x 16 KB (SW128)
#define TF_SMEM_BYTES (TF_P + 32768)  // 115712

template<int MASK>
__global__ __launch_bounds__(256, 2)
void tc_flash(__half* __restrict__ Oh, __half* __restrict__ Ol,
              const __half* __restrict__ Qh, const __half* __restrict__ Ql,
              const __half* __restrict__ Kh, const __half* __restrict__ Kl,
              const __half* __restrict__ Vp, int kvlen)
{
#if HAS_TCGEN05
    extern __shared__ __align__(1024) char fsm[];
    const uint32_t sb = smem_u32(fsm);
    const int tid  = threadIdx.x;
    const int wid  = tid >> 5;
    const int lane = tid & 31;
    const int sub  = wid & 3;
    const int h2   = wid >> 2;
    const int q0   = blockIdx.x * 128;
    const int h    = blockIdx.y;
    const int b    = blockIdx.z;

    if (tid == 0) {
        MBARRIER_INIT(sb + 8, 1);    // S done
        MBARRIER_INIT(sb + 16, 1);   // PV done
        MBARRIER_INIT(sb + 24, 1);   // Q loaded
        MBARRIER_INIT(sb + 32, 1);   // K loaded
        MBARRIER_INIT(sb + 48, 1);   // V loaded
        FENCE_PROXY_ASYNC_SHARED_CTA();
    }
    if (wid == 0) {
        TCGEN05_ALLOC(sb + 0, 256);
        TCGEN05_RELINQUISH();
    }
    __syncthreads();
    uint32_t tmem;
    asm volatile("ld.shared.b32 %0, [%1];" : "=r"(tmem) : "r"(sb + 0));

    const size_t qblk = ((size_t)((b * SQ_ + q0) >> 7) * 16 + 2 * h) * 8192;
    if (tid == 0) {
        MBARRIER_EXPECT_TX(sb + 24, 32768);
        CP_BULK_G2S(sb + TF_QH, (const char*)Qh + qblk, 16384, sb + 24);
        CP_BULK_G2S(sb + TF_QL, (const char*)Ql + qblk, 16384, sb + 24);
        const size_t kblk = ((size_t)((b * kvlen) >> 7) * 16 + 2 * h) * 8192;
        MBARRIER_EXPECT_TX(sb + 32, 32768);
        CP_BULK_G2S(sb + TF_KH, (const char*)Kh + kblk, 16384, sb + 32);
        CP_BULK_G2S(sb + TF_KL, (const char*)Kl + kblk, 16384, sb + 32);
    }

    float lsum = 0.f;
    const int qrow = sub * 32 + lane;
    const int qg   = q0 + qrow;

    const int ntiles = kvlen >> 7;
    for (int t = 0; t < ntiles; t++) {
        const int kv0 = t << 7;

        // ---- S = Q @ K^T (SW64 tiles, 12 dispatches) ----
        if (tid == 0) {
            if (t == 0) MBARRIER_WAIT_PARITY(sb + 24, 0);
            MBARRIER_WAIT_PARITY(sb + 32, t & 1);
            #pragma unroll
            for (int blk = 0; blk < 2; blk++) {
                const uint64_t dQh = MAKE_SMEM_DESC_SW64(sb + TF_QH + blk * 8192);
                const uint64_t dQl = MAKE_SMEM_DESC_SW64(sb + TF_QL + blk * 8192);
                const uint64_t dKh = MAKE_SMEM_DESC_SW64(sb + TF_KH + blk * 8192);
                const uint64_t dKl = MAKE_SMEM_DESC_SW64(sb + TF_KL + blk * 8192);
                #pragma unroll
                for (int kk = 0; kk < 2; kk++) {
                    const uint64_t o = kk * 2;
                    tcgen05_mma_f16_ss(tmem + 64, dQh + o, dKh + o, IDESC_G,
                                       (blk == 0 && kk == 0) ? 0u : 1u);
                    tcgen05_mma_f16_ss(tmem + 64, dQl + o, dKh + o, IDESC_G, 1u);
                    tcgen05_mma_f16_ss(tmem + 64, dQh + o, dKl + o, IDESC_G, 1u);
                }
            }
            TCGEN05_COMMIT(sb + 8);
        }

        // ---- PV(t-1) drain frees VT/P, then bulk-load V(t) ----
        if (t > 0) {
            MBARRIER_WAIT_PARITY(sb + 16, (t - 1) & 1);
        }
        if (tid == 0) {
            const size_t vblk = ((size_t)((b * kvlen + kv0) >> 6) * 8 + h) * 8192;
            MBARRIER_EXPECT_TX(sb + 48, 16384);
            CP_BULK_G2S(sb + TF_VT,        (const char*)Vp + vblk,             8192, sb + 48);
            CP_BULK_G2S(sb + TF_VT + 8192, (const char*)Vp + vblk + 8 * 8192,  8192, sb + 48);
        }

        // ---- Wait S (all); prefetch next K (tid0) ----
        MBARRIER_WAIT_PARITY(sb + 8, t & 1);
        TCGEN05_FENCE_AFTER();
        if (tid == 0 && t + 1 < ntiles) {
            const size_t kblk = ((size_t)((b * kvlen + kv0 + 128) >> 7) * 16 + 2 * h) * 8192;
            MBARRIER_EXPECT_TX(sb + 32, 32768);
            CP_BULK_G2S(sb + TF_KH, (const char*)Kh + kblk, 16384, sb + 32);
            CP_BULK_G2S(sb + TF_KL, (const char*)Kl + kblk, 16384, sb + 32);
        }

        // ---- softmax (unnormalized) -> f16 P (SW128) ----
        #pragma unroll
        for (int chunk = 0; chunk < 2; chunk++) {
            uint32_t r[32];
            TCGEN05_LD_32X32B_X32(r, tmem + 64 + h2 * 64 + chunk * 32);
            TCGEN05_WAIT_LD();
            const int kvb = h2 * 64 + chunk * 32;
            char* Pp = fsm + TF_P + h2 * 16384;
            #pragma unroll
            for (int c16 = 0; c16 < 4; c16++) {
                uint32_t w[4];
                #pragma unroll
                for (int pr = 0; pr < 4; pr++) {
                    __half hs[2];
                    #pragma unroll
                    for (int j = 0; j < 2; j++) {
                        const float s = __uint_as_float(r[c16 * 8 + pr * 2 + j]);
                        const int kg = kv0 + kvb + c16 * 8 + pr * 2 + j;
                        float wm;
                        if (MASK == 1) wm = ((qg < 512) == (kg < 512)) ? 1.25f : 1.0f;
                        else           wm = ((qg >> 8)  == (kg >> 8))  ? 1.25f : 1.0f;
                        const float p = __expf(s * (0.125f * wm));
                        hs[j] = __float2half_rn(p);
                        lsum += __half2float(hs[j]);
                    }
                    w[pr] = pack2(hs[0], hs[1]);
                }
                const uint32_t sw = SMEM_SWIZZLE_128B(
                    (uint32_t)(qrow * 128 + chunk * 64 + c16 * 16));
                *(uint4*)(Pp + sw) = make_uint4(w[0], w[1], w[2], w[3]);
            }
        }
        TCGEN05_FENCE_BEFORE();
        __syncthreads();

        // ---- O += P @ V^T (SW128, 8 dispatches) ----
        if (tid == 0) {
            FENCE_PROXY_ASYNC_SHARED_CTA();
            MBARRIER_WAIT_PARITY(sb + 48, t & 1);   // V(t) landed
            #pragma unroll
            for (int p2 = 0; p2 < 2; p2++) {
                const uint64_t dP = MAKE_SMEM_DESC(sb + TF_P  + p2 * 16384);
                const uint64_t dV = MAKE_SMEM_DESC(sb + TF_VT + p2 * 8192);
                #pragma unroll
                for (int kk = 0; kk < 4; kk++) {
                    const uint64_t o = kk * 2;
                    tcgen05_mma_f16_ss(tmem, dP + o, dV + o, IDESC_PV,
                                       (t == 0 && p2 == 0 && kk == 0) ? 0u : 1u);
                }
            }
            TCGEN05_COMMIT(sb + 16);
        }
    }

    MBARRIER_WAIT_PARITY(sb + 16, (ntiles - 1) & 1);
    TCGEN05_FENCE_AFTER();

    // combine row sums across column-half warpgroups
    {
        float* lx = (float*)(fsm + TF_VT);
        lx[wid * 32 + lane] = lsum;
    }
    __syncthreads();
    const float lother = ((float*)(fsm + TF_VT))[(wid ^ 4) * 32 + lane];
    const float inv = 1.0f / (lsum + lother);

    // O epilogue: tiled f16 split (feeds wo GEMM)
    {
        uint32_t r[32];
        TCGEN05_LD_32X32B_X32(r, tmem + h2 * 32);
        TCGEN05_WAIT_LD();
        const int orow = b * SQ_ + qg;
        #pragma unroll
        for (int c4 = 0; c4 < 8; c4++) {
            __half h0,h1,h2_,h3,l0,l1,l2,l3;
            h_split(__uint_as_float(r[c4*4+0]) * inv, h0, l0);
            h_split(__uint_as_float(r[c4*4+1]) * inv, h1, l1);
            h_split(__uint_as_float(r[c4*4+2]) * inv, h2_, l2);
            h_split(__uint_as_float(r[c4*4+3]) * inv, h3, l3);
            const size_t off = tiled_off(orow, h * DH_ + h2 * 32 + c4 * 4, D_);
            *(uint2*)((char*)Oh + off) = make_uint2(pack2(h0,h1), pack2(h2_,h3));
            *(uint2*)((char*)Ol + off) = make_uint2(pack2(l0,l1), pack2(l2,l3));
        }
    }

    __syncthreads();
    if (wid == 0) TCGEN05_DEALLOC(tmem, 256);
#endif  // HAS_TCGEN05
}

// ============================================================
// SIMT SGEMM fallback (round-1 proven, fp32)
// ============================================================
template<int EPI>
__global__ __launch_bounds__(256)
void sgemm_kernel(float* __restrict__ C,
                  const float* __restrict__ A,
                  const float* __restrict__ W,
                  const float* __restrict__ bias,
                  const float* __restrict__ res,
                  int M, int N, int K)
{
    __shared__ float As[8][128];
    __shared__ float Bs[8][128];

    const int tid = threadIdx.x;
    const int bm  = blockIdx.y * 128;
    const int bn  = blockIdx.x * 128;

    const int lr = tid >> 1;
    const int lc = (tid & 1) * 4;
    const float* Aptr = A + (size_t)(bm + lr) * K + lc;
    const float* Wptr = W + (size_t)(bn + lr) * K + lc;

    const int ty = tid >> 4;
    const int tx = tid & 15;

    float acc[8][8];
    #pragma unroll
    for (int i = 0; i < 8; i++)
        #pragma unroll
        for (int j = 0; j < 8; j++) acc[i][j] = 0.f;

    for (int k0 = 0; k0 < K; k0 += 8) {
        float4 a4 = *(const float4*)(Aptr + k0);
        float4 b4 = *(const float4*)(Wptr + k0);
        As[lc + 0][lr] = a4.x; As[lc + 1][lr] = a4.y;
        As[lc + 2][lr] = a4.z; As[lc + 3][lr] = a4.w;
        Bs[lc + 0][lr] = b4.x; Bs[lc + 1][lr] = b4.y;
        Bs[lc + 2][lr] = b4.z; Bs[lc + 3][lr] = b4.w;
        __syncthreads();

        #pragma unroll
        for (int kk = 0; kk < 8; kk++) {
            float ra[8], rb[8];
            *(float4*)(ra)     = *(const float4*)&As[kk][ty * 4];
            *(float4*)(ra + 4) = *(const float4*)&As[kk][ty * 4 + 64];
            *(float4*)(rb)     = *(const float4*)&Bs[kk][tx * 4];
            *(float4*)(rb + 4) = *(const float4*)&Bs[kk][tx * 4 + 64];
            #pragma unroll
            for (int i = 0; i < 8; i++)
                #pragma unroll
                for (int j = 0; j < 8; j++)
                    acc[i][j] += ra[i] * rb[j];
        }
        __syncthreads();
    }

    #pragma unroll
    for (int i = 0; i < 8; i++) {
        const int row = bm + ty * 4 + (i & 3) + (i >> 2) * 64;
        #pragma unroll
        for (int jh = 0; jh < 2; jh++) {
            const int col = bn + tx * 4 + jh * 64;
            float4 v;
            v.x = acc[i][jh * 4 + 0];
            v.y = acc[i][jh * 4 + 1];
            v.z = acc[i][jh * 4 + 2];
            v.w = acc[i][jh * 4 + 3];
            if (EPI >= 1) {
                float4 bi = *(const float4*)&bias[col];
                v.x += bi.x; v.y += bi.y; v.z += bi.z; v.w += bi.w;
            }
            if (EPI == 1) {
                float4 rv = *(const float4*)&res[(size_t)row * N + col];
                v.x += rv.x; v.y += rv.y; v.z += rv.z; v.w += rv.w;
            }
            if (EPI == 2) {
                v.x = gelu_exact(v.x); v.y = gelu_exact(v.y);
                v.z = gelu_exact(v.z); v.w = gelu_exact(v.w);
            }
            *(float4*)&C[(size_t)row * N + col] = v;
        }
    }
}

// ============================================================
// SIMT flash attention fallback (round-1 proven, fp32)
// ============================================================
#define FA_STRIDE 68
#define FA_SMEM_FLOATS ((128 + 64 + 64 + 128) * FA_STRIDE)
#define FA_SMEM_BYTES  (FA_SMEM_FLOATS * 4)

template<int MASK>
__global__ __launch_bounds__(256)
void flash_kernel(float* __restrict__ O,
                  const float* __restrict__ Q,
                  const float* __restrict__ Kp,
                  const float* __restrict__ Vp,
                  int kvlen)
{
    extern __shared__ float fsm2[];
    float* Qs = fsm2;
    float* Ks = Qs + 128 * FA_STRIDE;
    float* Vt = Ks + 64  * FA_STRIDE;
    float* Ps = Vt + 64  * FA_STRIDE;

    const int tid = threadIdx.x;
    const int q0  = blockIdx.x * 128;
    const int h   = blockIdx.y;
    const int b   = blockIdx.z;
    const int rg  = tid >> 4;
    const int cg  = tid & 15;

    {
        const int qrow = tid >> 1;
        const int half = tid & 1;
        const float* qbase = Q + (size_t)(b * SQ_ + q0 + qrow) * D_ + h * DH_;
        #pragma unroll
        for (int i = 0; i < 8; i++) {
            const int f4 = half * 8 + i;
            *(float4*)&Qs[qrow * FA_STRIDE + f4 * 4] = *(const float4*)&qbase[f4 * 4];
        }
    }

    float m_i[8], l_i[8], oacc[8][4];
    #pragma unroll
    for (int u = 0; u < 8; u++) {
        m_i[u] = -1e30f; l_i[u] = 0.f;
        #pragma unroll
        for (int t = 0; t < 4; t++) oacc[u][t] = 0.f;
    }

    const int ntiles = kvlen >> 6;
    for (int t0 = 0; t0 < ntiles; t0++) {
        const int kv0 = t0 * 64;
        __syncthreads();

        {
            const int lrow = tid >> 2;
            const int lq   = tid & 3;
            const float* kbase = Kp + (size_t)(b * kvlen + kv0 + lrow) * D_ + h * DH_;
            const float* vbase = Vp + (size_t)(b * kvlen + kv0 + lrow) * D_ + h * DH_;
            #pragma unroll
            for (int i = 0; i < 4; i++) {
                const int f4 = lq * 4 + i;
                float4 k4 = *(const float4*)&kbase[f4 * 4];
                *(float4*)&Ks[lrow * FA_STRIDE + f4 * 4] = k4;
                float4 v4 = *(const float4*)&vbase[f4 * 4];
                const int d0 = f4 * 4;
                Vt[(d0 + 0) * FA_STRIDE + lrow] = v4.x;
                Vt[(d0 + 1) * FA_STRIDE + lrow] = v4.y;
                Vt[(d0 + 2) * FA_STRIDE + lrow] = v4.z;
                Vt[(d0 + 3) * FA_STRIDE + lrow] = v4.w;
            }
        }
        __syncthreads();

        float sacc[8][4];
        #pragma unroll
        for (int u = 0; u < 8; u++)
            #pragma unroll
            for (int t = 0; t < 4; t++) sacc[u][t] = 0.f;

        #pragma unroll
        for (int d4 = 0; d4 < 16; d4++) {
            float4 qv[8];
            #pragma unroll
            for (int u = 0; u < 8; u++)
                qv[u] = *(const float4*)&Qs[(rg + 16 * u) * FA_STRIDE + d4 * 4];
            #pragma unroll
            for (int t = 0; t < 4; t++) {
                float4 kk = *(const float4*)&Ks[(cg + 16 * t) * FA_STRIDE + d4 * 4];
                #pragma unroll
                for (int u = 0; u < 8; u++)
                    sacc[u][t] += qv[u].x * kk.x + qv[u].y * kk.y
                                + qv[u].z * kk.z + qv[u].w * kk.w;
            }
        }

        #pragma unroll
        for (int u = 0; u < 8; u++) {
            const int qg = q0 + rg + 16 * u;
            #pragma unroll
            for (int t = 0; t < 4; t++) {
                const int kg = kv0 + cg + 16 * t;
                float wm;
                if (MASK == 1) wm = ((qg < 512) == (kg < 512)) ? 1.25f : 1.0f;
                else           wm = ((qg >> 8)  == (kg >> 8))  ? 1.25f : 1.0f;
                sacc[u][t] *= 0.125f * wm;
            }
        }

        #pragma unroll
        for (int u = 0; u < 8; u++) {
            float rmax = fmaxf(fmaxf(sacc[u][0], sacc[u][1]),
                               fmaxf(sacc[u][2], sacc[u][3]));
            #pragma unroll
            for (int off = 8; off >= 1; off >>= 1)
                rmax = fmaxf(rmax, __shfl_xor_sync(0xffffffffu, rmax, off));
            const float mnew  = fmaxf(m_i[u], rmax);
            const float alpha = __expf(m_i[u] - mnew);
            m_i[u] = mnew;
            float rsum = 0.f;
            #pragma unroll
            for (int t = 0; t < 4; t++) {
                const float p = __expf(sacc[u][t] - mnew);
                Ps[(rg + 16 * u) * FA_STRIDE + cg + 16 * t] = p;
                rsum += p;
            }
            #pragma unroll
            for (int off = 8; off >= 1; off >>= 1)
                rsum += __shfl_xor_sync(0xffffffffu, rsum, off);
            l_i[u] = l_i[u] * alpha + rsum;
            #pragma unroll
            for (int t = 0; t < 4; t++) oacc[u][t] *= alpha;
        }
        __syncthreads();

        #pragma unroll
        for (int j4 = 0; j4 < 16; j4++) {
            float4 pv[8];
            #pragma unroll
            for (int u = 0; u < 8; u++)
                pv[u] = *(const float4*)&Ps[(rg + 16 * u) * FA_STRIDE + j4 * 4];
            #pragma unroll
            for (int t = 0; t < 4; t++) {
                float4 vv = *(const float4*)&Vt[(cg + 16 * t) * FA_STRIDE + j4 * 4];
                #pragma unroll
                for (int u = 0; u < 8; u++)
                    oacc[u][t] += pv[u].x * vv.x + pv[u].y * vv.y
                                + pv[u].z * vv.z + pv[u].w * vv.w;
            }
        }
    }

    #pragma unroll
    for (int u = 0; u < 8; u++) {
        const float inv = 1.0f / l_i[u];
        const size_t row = (size_t)(b * SQ_ + q0 + rg + 16 * u);
        #pragma unroll
        for (int t = 0; t < 4; t++)
            O[row * D_ + h * DH_ + cg + 16 * t] = oacc[u][t] * inv;
    }
}

// ============================================================
// LayerNorm over D=512; SPLIT=1 also emits TILED f16 hi/lo split
// ============================================================
template<int SPLIT>
__global__ __launch_bounds__(256)
void layernorm_kernel(float* __restrict__ out,
                      __half* __restrict__ oh, __half* __restrict__ ol,
                      const float* __restrict__ in,
                      const float* __restrict__ g, const float* __restrict__ b,
                      int rows)
{
    const int gt   = blockIdx.x * 256 + threadIdx.x;
    const int row  = gt >> 5;
    const int lane = gt & 31;
    if (row >= rows) return;

    const float* x = in + (size_t)row * D_;
    float4 v[4];
    float s = 0.f;
    #pragma unroll
    for (int i = 0; i < 4; i++) {
        v[i] = *(const float4*)&x[(lane + i * 32) * 4];
        s += v[i].x + v[i].y + v[i].z + v[i].w;
    }
    #pragma unroll
    for (int o = 16; o; o >>= 1) s += __shfl_xor_sync(0xffffffffu, s, o);
    const float mean = s * (1.0f / 512.0f);

    float var = 0.f;
    #pragma unroll
    for (int i = 0; i < 4; i++) {
        float dx = v[i].x - mean; var += dx * dx;
        dx = v[i].y - mean; var += dx * dx;
        dx = v[i].z - mean; var += dx * dx;
        dx = v[i].w - mean; var += dx * dx;
    }
    #pragma unroll
    for (int o = 16; o; o >>= 1) var += __shfl_xor_sync(0xffffffffu, var, o);
    const float rstd = rsqrtf(var * (1.0f / 512.0f) + 1e-5f);

    #pragma unroll
    for (int i = 0; i < 4; i++) {
        const int c = (lane + i * 32) * 4;
        float4 gv = *(const float4*)&g[c];
        float4 bv = *(const float4*)&b[c];
        float4 o4;
        o4.x = (v[i].x - mean) * rstd * gv.x + bv.x;
        o4.y = (v[i].y - mean) * rstd * gv.y + bv.y;
        o4.z = (v[i].z - mean) * rstd * gv.z + bv.z;
        o4.w = (v[i].w - mean) * rstd * gv.w + bv.w;
        *(float4*)&out[(size_t)row * D_ + c] = o4;
        if (SPLIT) {
            __half h0,h1,h2,h3,l0,l1,l2,l3;
            h_split(o4.x,h0,l0); h_split(o4.y,h1,l1);
            h_split(o4.z,h2,l2); h_split(o4.w,h3,l3);
            const size_t off = tiled_off(row, c, D_);
            *(uint2*)((char*)oh + off) = make_uint2(pack2(h0,h1), pack2(h2,h3));
            *(uint2*)((char*)ol + off) = make_uint2(pack2(l0,l1), pack2(l2,l3));
        }
    }
}

// ============================================================
// Launch
// ============================================================
static void* sym(const void* symbol) {
    void* p = nullptr;
    cudaGetSymbolAddress(&p, symbol);
    return p;
}

extern "C" void kernel_launch(void* const* d_in, const int* in_sizes, int n_in,
                              void* d_out, int out_size)
{
    const float* cords   = (const float*)d_in[0];
    const float* spatial = (const float*)d_in[1];
    const float* speed   = (const float*)d_in[2];
    const float* wq1 = (const float*)d_in[3];
    const float* wk1 = (const float*)d_in[4];
    const float* wv1 = (const float*)d_in[5];
    const float* wo1 = (const float*)d_in[6];
    const float* bo1 = (const float*)d_in[7];
    const float* wq2 = (const float*)d_in[8];
    const float* wk2 = (const float*)d_in[9];
    const float* wv2 = (const float*)d_in[10];
    const float* wo2 = (const float*)d_in[11];
    const float* bo2 = (const float*)d_in[12];
    const float* ln1_g = (const float*)d_in[13];
    const float* ln1_b = (const float*)d_in[14];
    const float* ln2_g = (const float*)d_in[15];
    const float* ln2_b = (const float*)d_in[16];
    const float* ln3_g = (const float*)d_in[17];
    const float* ln3_b = (const float*)d_in[18];
    const float* ffn_w1 = (const float*)d_in[19];
    const float* ffn_b1 = (const float*)d_in[20];
    const float* ffn_w2 = (const float*)d_in[21];
    const float* ffn_b2 = (const float*)d_in[22];
    float* out = (float*)d_out;

    cudaFuncAttributes fa{};
    bool tc1 = false, tc2 = false;
    if (cudaFuncGetAttributes(&fa, (const void*)tc_gemm<1>) == cudaSuccess)
        tc1 = (fa.numRegs >= 32);
    if (cudaFuncGetAttributes(&fa, (const void*)tc_flash<1>) == cudaSuccess)
        tc2 = (fa.numRegs >= 32);
    const bool use_tc = tc1 && tc2;

    static cudaStream_t s1 = nullptr, s2 = nullptr, s3 = nullptr;
    static cudaEvent_t  evF = nullptr, ev1 = nullptr, ev2 = nullptr, ev3 = nullptr;
    static int sinit = 0;
    if (sinit == 0) {
        bool ok = true;
        ok &= (cudaStreamCreateWithFlags(&s1, cudaStreamNonBlocking) == cudaSuccess);
        ok &= (cudaStreamCreateWithFlags(&s2, cudaStreamNonBlocking) == cudaSuccess);
        ok &= (cudaStreamCreateWithFlags(&s3, cudaStreamNonBlocking) == cudaSuccess);
        ok &= (cudaEventCreateWithFlags(&evF, cudaEventDisableTiming) == cudaSuccess);
        ok &= (cudaEventCreateWithFlags(&ev1, cudaEventDisableTiming) == cudaSuccess);
        ok &= (cudaEventCreateWithFlags(&ev2, cudaEventDisableTiming) == cudaSuccess);
        ok &= (cudaEventCreateWithFlags(&ev3, cudaEventDisableTiming) == cudaSuccess);
        sinit = ok ? 1 : -1;
    }
    const bool multi = (sinit == 1) && use_tc;
    cudaStream_t t1 = multi ? s1 : 0;
    cudaStream_t t2 = multi ? s2 : 0;
    cudaStream_t t3 = multi ? s3 : 0;

    // R10 grids (BN=128)
    const dim3 gProj(D_ / 128, MQ_ / 128);     // (4, 48)
    const dim3 gKV1 (D_ / 128, MKV1_ / 128);   // (4, 64)
    const dim3 gFFN1(DF_ / 128, MQ_ / 128);    // (16, 48)
    const dim3 gFA  (SQ_ / 128, H_, B_);       // (6, 8, 8)
    const int  lnBlocks = MQ_ * 32 / 256;      // 768

    float* tmp = (float*)sym(g_tmp);
    float* x1  = (float*)sym(g_x1);
    float* x2  = (float*)sym(g_x2);

    if (use_tc) {
        cudaFuncSetAttribute((const void*)tc_gemm<1>, cudaFuncAttributeMaxDynamicSharedMemorySize, GT_SMEM_BYTES);
        cudaFuncSetAttribute((const void*)tc_gemm<2>, cudaFuncAttributeMaxDynamicSharedMemorySize, GT_SMEM_BYTES);
        cudaFuncSetAttribute((const void*)tc_gemm<3>, cudaFuncAttributeMaxDynamicSharedMemorySize, GT_SMEM_BYTES);
        cudaFuncSetAttribute((const void*)tc_gemm<4>, cudaFuncAttributeMaxDynamicSharedMemorySize, GT_SMEM_BYTES);
        cudaFuncSetAttribute((const void*)tc_flash<1>, cudaFuncAttributeMaxDynamicSharedMemorySize, TF_SMEM_BYTES);
        cudaFuncSetAttribute((const void*)tc_flash<2>, cudaFuncAttributeMaxDynamicSharedMemorySize, TF_SMEM_BYTES);

        // ---- split inputs + weights -> tiled f16 hi/lo (one launch) ----
        SplitJobs jb{};
        const float* srcs[NSPLIT] = {cords, spatial, speed,
                                     wq1, wk1, wv1, wo1, wq2, wk2, wv2, wo2,
                                     ffn_w1, ffn_w2};
        void* dsth[NSPLIT] = {sym(g_ca_h), sym(g_sp_h), sym(g_spd_h),
                              sym(g_wq1h), sym(g_wk1h), sym(g_wv1h), sym(g_wo1h),
                              sym(g_wq2h), sym(g_wk2h), sym(g_wv2h), sym(g_wo2h),
                              sym(g_fw1h), sym(g_fw2h)};
        void* dstl[NSPLIT] = {sym(g_ca_l), sym(g_sp_l), sym(g_spd_l),
                              sym(g_wq1l), sym(g_wk1l), sym(g_wv1l), sym(g_wo1l),
                              sym(g_wq2l), sym(g_wk2l), sym(g_wv2l), sym(g_wo2l),
                              sym(g_fw1l), sym(g_fw2l)};
        const int nelts[NSPLIT] = {MQ_*D_, MKV1_*D_, MQ_*D_,
                                   D_*D_, D_*D_, D_*D_, D_*D_,
                                   D_*D_, D_*D_, D_*D_, D_*D_,
                                   DF_*D_, DF_*D_};
        const int kshs[NSPLIT] = {9,9,9, 9,9,9,9, 9,9,9,9, 9,11};
        int acc = 0;
        for (int j = 0; j < NSPLIT; j++) {
            jb.s[j] = (const float4*)srcs[j];
            jb.h[j] = (char*)dsth[j];
            jb.l[j] = (char*)dstl[j];
            acc += nelts[j] / 1024;
            jb.end[j] = acc;
            jb.ksh[j] = kshs[j];
        }
        split_batch<<<acc, 256>>>(jb);

        __half* qh = (__half*)sym(g_q_h), *ql = (__half*)sym(g_q_l);
        __half* kh = (__half*)sym(g_k_h), *kl = (__half*)sym(g_k_l);
        __half* vv = (__half*)sym(g_v);
        __half* k2h = (__half*)sym(g_k2h), *k2l = (__half*)sym(g_k2l);
        __half* v2 = (__half*)sym(g_v2);
        __half* ath = (__half*)sym(g_at_h), *atl = (__half*)sym(g_at_l);
        __half* x1h = (__half*)sym(g_x1h), *x1l = (__half*)sym(g_x1l);
        __half* x2h = (__half*)sym(g_x2h), *x2l = (__half*)sym(g_x2l);
        __half* hh = (__half*)sym(g_h_h), *hl = (__half*)sym(g_h_l);

        // ---- Fork: q1 on 0; k1/v1 on s1/s2; k2/v2 on s3 ----
        if (multi) {
            cudaEventRecord(evF, 0);
            cudaStreamWaitEvent(s1, evF, 0);
            cudaStreamWaitEvent(s2, evF, 0);
            cudaStreamWaitEvent(s3, evF, 0);
        }
        tc_gemm<3><<<gProj, 256, GT_SMEM_BYTES, 0 >>>(qh, ql, (__half*)sym(g_ca_h), (__half*)sym(g_ca_l), (__half*)sym(g_wq1h), (__half*)sym(g_wq1l), nullptr, nullptr, MQ_, D_, D_);
        tc_gemm<3><<<gKV1,  256, GT_SMEM_BYTES, t1>>>(kh, kl, (__half*)sym(g_sp_h), (__half*)sym(g_sp_l), (__half*)sym(g_wk1h), (__half*)sym(g_wk1l), nullptr, nullptr, MKV1_, D_, D_);
        tc_gemm<4><<<gKV1,  256, GT_SMEM_BYTES, t2>>>(vv, nullptr, (__half*)sym(g_sp_h), (__half*)sym(g_sp_l), (__half*)sym(g_wv1h), (__half*)sym(g_wv1l), nullptr, nullptr, MKV1_, D_, D_);
        tc_gemm<3><<<gProj, 256, GT_SMEM_BYTES, t3>>>(k2h, k2l, (__half*)sym(g_spd_h), (__half*)sym(g_spd_l), (__half*)sym(g_wk2h), (__half*)sym(g_wk2l), nullptr, nullptr, MQ_, D_, D_);
        tc_gemm<4><<<gProj, 256, GT_SMEM_BYTES, t3>>>(v2, nullptr, (__half*)sym(g_spd_h), (__half*)sym(g_spd_l), (__half*)sym(g_wv2h), (__half*)sym(g_wv2l), nullptr, nullptr, MQ_, D_, D_);
        if (multi) {
            cudaEventRecord(ev1, s1);
            cudaEventRecord(ev2, s2);
            cudaEventRecord(ev3, s3);
            cudaStreamWaitEvent(0, ev1, 0);
            cudaStreamWaitEvent(0, ev2, 0);
        }

        // ---- Stage 1 tail ----
        tc_flash<1><<<gFA, 256, TF_SMEM_BYTES>>>(ath, atl, qh, ql, kh, kl, vv, SKV1_);
        tc_gemm<1><<<gProj, 256, GT_SMEM_BYTES>>>(tmp, nullptr, ath, atl, (__half*)sym(g_wo1h), (__half*)sym(g_wo1l), bo1, cords, MQ_, D_, D_);
        layernorm_kernel<1><<<lnBlocks, 256>>>(x1, x1h, x1l, tmp, ln1_g, ln1_b, MQ_);

        // ---- Stage 2 ----
        tc_gemm<3><<<gProj, 256, GT_SMEM_BYTES>>>(qh, ql, x1h, x1l, (__half*)sym(g_wq2h), (__half*)sym(g_wq2l), nullptr, nullptr, MQ_, D_, D_);
        if (multi) cudaStreamWaitEvent(0, ev3, 0);
        tc_flash<2><<<gFA, 256, TF_SMEM_BYTES>>>(ath, atl, qh, ql, k2h, k2l, v2, SQ_);
        tc_gemm<1><<<gProj, 256, GT_SMEM_BYTES>>>(tmp, nullptr, ath, atl, (__half*)sym(g_wo2h), (__half*)sym(g_wo2l), bo2, x1, MQ_, D_, D_);
        layernorm_kernel<1><<<lnBlocks, 256>>>(x2, x2h, x2l, tmp, ln2_g, ln2_b, MQ_);

        // ---- Stage 3: FFN ----
        tc_gemm<2><<<gFFN1, 256, GT_SMEM_BYTES>>>(hh, hl, x2h, x2l, (__half*)sym(g_fw1h), (__half*)sym(g_fw1l), ffn_b1, nullptr, MQ_, DF_, D_);
        tc_gemm<1><<<gProj, 256, GT_SMEM_BYTES>>>(tmp, nullptr, hh, hl, (__half*)sym(g_fw2h), (__half*)sym(g_fw2l), ffn_b2, x2, MQ_, D_, DF_);
        layernorm_kernel<0><<<lnBlocks, 256>>>(out, nullptr, nullptr, tmp, ln3_g, ln3_b, MQ_);
    } else {
        // -------- full SIMT fallback (round-1 proven path) --------
        cudaFuncSetAttribute((const void*)flash_kernel<1>, cudaFuncAttributeMaxDynamicSharedMemorySize, FA_SMEM_BYTES);
        cudaFuncSetAttribute((const void*)flash_kernel<2>, cudaFuncAttributeMaxDynamicSharedMemorySize, FA_SMEM_BYTES);
        float* q = (float*)sym(g_fa);
        float* k = (float*)sym(g_fb);
        float* v = (float*)sym(g_fc);
        float* attn = (float*)sym(g_fd);
        float* hbuf = (float*)sym(g_fd);

        sgemm_kernel<0><<<gProj, 256>>>(q, cords,   wq1, nullptr, nullptr, MQ_,   D_, D_);
        sgemm_kernel<0><<<gKV1,  256>>>(k, spatial, wk1, nullptr, nullptr, MKV1_, D_, D_);
        sgemm_kernel<0><<<gKV1,  256>>>(v, spatial, wv1, nullptr, nullptr, MKV1_, D_, D_);
        flash_kernel<1><<<gFA, 256, FA_SMEM_BYTES>>>(attn, q, k, v, SKV1_);
        sgemm_kernel<1><<<gProj, 256>>>(tmp, attn, wo1, bo1, cords, MQ_, D_, D_);
        layernorm_kernel<0><<<lnBlocks, 256>>>(x1, nullptr, nullptr, tmp, ln1_g, ln1_b, MQ_);

        sgemm_kernel<0><<<gProj, 256>>>(q, x1,    wq2, nullptr, nullptr, MQ_, D_, D_);
        sgemm_kernel<0><<<gProj, 256>>>(k, speed, wk2, nullptr, nullptr, MQ_, D_, D_);
        sgemm_kernel<0><<<gProj, 256>>>(v, speed, wv2, nullptr, nullptr, MQ_, D_, D_);
        flash_kernel<2><<<gFA, 256, FA_SMEM_BYTES>>>(attn, q, k, v, SQ_);
        sgemm_kernel<1><<<gProj, 256>>>(tmp, attn, wo2, bo2, x1, MQ_, D_, D_);
        layernorm_kernel<0><<<lnBlocks, 256>>>(x2, nullptr, nullptr, tmp, ln2_g, ln2_b, MQ_);

        sgemm_kernel<2><<<gFFN1, 256>>>(hbuf, x2, ffn_w1, ffn_b1, nullptr, MQ_, DF_, D_);
        sgemm_kernel<1><<<gProj, 256>>>(tmp, hbuf, ffn_w2, ffn_b2, x2, MQ_, D_, DF_);
        layernorm_kernel<0><<<lnBlocks, 256>>>(out, nullptr, nullptr, tmp, ln3_g, ln3_b, MQ_);
    }
}

// round 13
// speedup vs baseline: 1.2788x; 1.1044x over previous
#include <cuda_runtime.h>
#include <cuda_fp16.h>
#include <math.h>
#include <cstdint>

// ============================================================
// Problem constants
// ============================================================
#define B_      8
#define SQ_     768
#define SKV1_   1024
#define D_      512
#define DF_     2048
#define H_      8
#define DH_     64
#define MQ_     (B_*SQ_)      // 6144
#define MKV1_   (B_*SKV1_)    // 8192

#if defined(__CUDA_ARCH__) && (defined(__CUDA_ARCH_FEAT_SM103_ALL) || \
                               defined(__CUDA_ARCH_FEAT_SM100_ALL) || \
                               (defined(__CUDA_ARCH_SPECIFIC__) && \
                                (__CUDA_ARCH_SPECIFIC__ == 1030 || __CUDA_ARCH_SPECIFIC__ == 1000)))
#define HAS_TCGEN05 1
#else
#define HAS_TCGEN05 0
#endif

// ------------------------------------------------------------
// Scratch (device globals; 16B+ alignment for cp.async.bulk)
// f16 GEMM operands in TILED layout: 8KB SW64-swizzled blocks.
// V stored PRE-TRANSPOSED (8KB SW128 panels). 2-term compensated
// f16: activation operands carry hi+lo; WEIGHTS hi only.
// ------------------------------------------------------------
__device__ __align__(256) __half g_ca_h [MQ_  * D_];  __device__ __align__(256) __half g_ca_l [MQ_  * D_];
__device__ __align__(256) __half g_sp_h [MKV1_* D_];  __device__ __align__(256) __half g_sp_l [MKV1_* D_];
__device__ __align__(256) __half g_spd_h[MQ_  * D_];  __device__ __align__(256) __half g_spd_l[MQ_  * D_];
__device__ __align__(256) __half g_wq1h[D_*D_];
__device__ __align__(256) __half g_wk1h[D_*D_];
__device__ __align__(256) __half g_wv1h[D_*D_];
__device__ __align__(256) __half g_wo1h[D_*D_];
__device__ __align__(256) __half g_wq2h[D_*D_];
__device__ __align__(256) __half g_wk2h[D_*D_];
__device__ __align__(256) __half g_wv2h[D_*D_];
__device__ __align__(256) __half g_wo2h[D_*D_];
__device__ __align__(256) __half g_fw1h[DF_*D_];
__device__ __align__(256) __half g_fw2h[DF_*D_];
__device__ __align__(256) __half g_q_h [MQ_  * D_];  __device__ __align__(256) __half g_q_l [MQ_  * D_];
__device__ __align__(256) __half g_k_h [MKV1_* D_];   // hi only (K-lo unused)
__device__ __align__(256) __half g_v   [MKV1_* D_];   // vT panels
__device__ __align__(256) __half g_k2h [MQ_  * D_];
__device__ __align__(256) __half g_v2  [MQ_  * D_];   // vT panels
__device__ __align__(256) __half g_at_h[MQ_  * D_];  __device__ __align__(256) __half g_at_l[MQ_  * D_];
__device__ __align__(256) __half g_x1h [MQ_  * D_];  __device__ __align__(256) __half g_x1l [MQ_  * D_];
__device__ __align__(256) __half g_x2h [MQ_  * D_];  __device__ __align__(256) __half g_x2l [MQ_  * D_];
__device__ __align__(256) __half g_h_h [MQ_  * DF_]; __device__ __align__(256) __half g_h_l [MQ_  * DF_];
__device__ float g_tmp[MQ_ * D_];
__device__ float g_x1 [MQ_ * D_];
__device__ float g_x2 [MQ_ * D_];
// fp32 fallback scratch (SIMT path)
__device__ float g_fa[MKV1_*D_];
__device__ float g_fb[MKV1_*D_];
__device__ float g_fc[MKV1_*D_];
__device__ float g_fd[MQ_*DF_];

// ============================================================
// Common helpers
// ============================================================
__device__ __forceinline__ float gelu_exact(float x) {
    return 0.5f * x * (1.0f + erff(x * 0.70710678118654752f));
}
__device__ __forceinline__ void h_split(float x, __half& h, __half& l) {
    h = __float2half_rn(x);
    l = __float2half_rn(x - __half2float(h));
}
__device__ __forceinline__ uint32_t pack2(__half a, __half b) {
    __half2 t = __halves2half2(a, b);
    return *(const uint32_t*)&t;
}
// Tiled layout: byte offset of (row, kcol) in [rows x K] f16 tensor
// stored as 8KB SW64-swizzled panel blocks.
__device__ __forceinline__ size_t tiled_off(int row, int kcol, int K) {
    size_t blk = (size_t)(row >> 7) * (K >> 5) + (kcol >> 5);
    uint32_t ib = (uint32_t)((row & 127) * 64 + (kcol & 31) * 2);
    ib ^= (ib >> 3) & 0x30;      // SW64 swizzle
    return blk * 8192 + ib;
}
#define SWZ128(x) ((x) ^ (((x) >> 3) & 0x70))
// vT layout: 8KB SW128 panel per (64-row kv panel, head).
__device__ __forceinline__ size_t vt_off(int row, int col) {
    size_t blk = (size_t)(row >> 6) * 8 + (col >> 6);
    uint32_t ib = SWZ128((uint32_t)((col & 63) * 128 + (row & 63) * 2));
    return blk * 8192 + ib;
}

// ============================================================
// Batched hi/lo split kernel (13 jobs) -> TILED outputs
//   wlo=0 jobs (weights) write hi only.
// ============================================================
#define NSPLIT 13
struct SplitJobs {
    const float4* s[NSPLIT];
    char* h[NSPLIT];
    char* l[NSPLIT];
    int end[NSPLIT];
    int ksh[NSPLIT];   // log2(K)
    int wlo[NSPLIT];   // write lo?
};

__global__ __launch_bounds__(256)
void split_batch(SplitJobs jb)
{
    const int blk = blockIdx.x;
    int j = 0;
    #pragma unroll
    for (int t = 0; t < NSPLIT; t++) if (blk >= jb.end[t]) j = t + 1;
    const int b0 = (j == 0) ? 0 : jb.end[j - 1];
    const int idx = (blk - b0) * 256 + threadIdx.x;
    float4 x = jb.s[j][idx];
    __half h0, h1, h2, h3, l0, l1, l2, l3;
    h_split(x.x, h0, l0); h_split(x.y, h1, l1);
    h_split(x.z, h2, l2); h_split(x.w, h3, l3);
    const int ksh = jb.ksh[j];
    const int e0 = idx * 4;
    const int row = e0 >> ksh;
    const int kcol = e0 & ((1 << ksh) - 1);
    const size_t off = tiled_off(row, kcol, 1 << ksh);
    *(uint2*)(jb.h[j] + off) = make_uint2(pack2(h0, h1), pack2(h2, h3));
    if (jb.wlo[j])
        *(uint2*)(jb.l[j] + off) = make_uint2(pack2(l0, l1), pack2(l2, l3));
}

#if HAS_TCGEN05
// ------------------------------------------------------------
// PTX helpers (sm_103a pass only)
// ------------------------------------------------------------
__device__ __forceinline__ uint32_t smem_u32(const void* smem_ptr) {
    uint32_t addr;
    asm("{ .reg .u64 tmp; cvta.to.shared.u64 tmp, %1; cvt.u32.u64 %0, tmp; }"
        : "=r"(addr) : "l"(smem_ptr));
    return addr;
}

#define MBARRIER_INIT(mbar, count) \
    asm volatile("mbarrier.init.shared.b64 [%0], %1;" \
        :: "r"((uint32_t)(mbar)), "r"((uint32_t)(count)) : "memory")

#define MBARRIER_EXPECT_TX(mbar, bytes) \
    asm volatile("mbarrier.arrive.expect_tx.shared.b64 _, [%0], %1;" \
        :: "r"((uint32_t)(mbar)), "r"((uint32_t)(bytes)) : "memory")

#define CP_BULK_G2S(dst, src, bytes, mbar) \
    asm volatile("cp.async.bulk.shared::cluster.global.mbarrier::complete_tx::bytes [%0], [%1], %2, [%3];" \
        :: "r"((uint32_t)(dst)), "l"(src), "r"((uint32_t)(bytes)), "r"((uint32_t)(mbar)) : "memory")

#define MBARRIER_WAIT_PARITY(mbar_smem_addr, phase_parity) do { \
    uint32_t _mbar = (uint32_t)(mbar_smem_addr); \
    uint32_t _parity = (uint32_t)(phase_parity); \
    uint32_t _done; \
    asm volatile( \
        "{\n\t" \
        ".reg .pred p;\n\t" \
        "mbarrier.try_wait.parity.acquire.cta.shared::cta.b64 p, [%1], %2;\n\t" \
        "selp.b32 %0, 1, 0, p;\n\t" \
        "}" \
        : "=r"(_done) : "r"(_mbar), "r"(_parity) : "memory"); \
    if (!_done) { \
        asm volatile( \
            "{\n\t" \
            ".reg .pred P1;\n\t" \
            "WAIT_LOOP_%=:\n\t" \
            "mbarrier.try_wait.parity.acquire.cta.shared::cta.b64 P1, [%0], %1, 0x989680;\n\t" \
            "@P1 bra.uni WAIT_DONE_%=;\n\t" \
            "bra.uni WAIT_LOOP_%=;\n\t" \
            "WAIT_DONE_%=:\n\t" \
            "}" \
            :: "r"(_mbar), "r"(_parity) : "memory"); \
    } \
} while(0)

#define TCGEN05_ALLOC(smem_result_addr, nCols) \
    asm volatile("tcgen05.alloc.cta_group::1.sync.aligned.shared::cta.b32 [%0], %1;" \
        :: "r"((uint32_t)(smem_result_addr)), "r"((uint32_t)(nCols)) : "memory")
#define TCGEN05_DEALLOC(tmem_addr, nCols) \
    asm volatile("tcgen05.dealloc.cta_group::1.sync.aligned.b32 %0, %1;" \
        :: "r"(tmem_addr), "r"(nCols))
#define TCGEN05_RELINQUISH() \
    asm volatile("tcgen05.relinquish_alloc_permit.cta_group::1.sync.aligned;")
#define TCGEN05_COMMIT(mbar_smem_addr) \
    asm volatile("tcgen05.commit.cta_group::1.mbarrier::arrive::one.shared::cluster.b64 [%0];" \
        :: "r"((uint32_t)(mbar_smem_addr)) : "memory")
#define TCGEN05_FENCE_AFTER() \
    asm volatile("tcgen05.fence::after_thread_sync;" ::: "memory")
#define TCGEN05_FENCE_BEFORE() \
    asm volatile("tcgen05.fence::before_thread_sync;" ::: "memory")
#define TCGEN05_WAIT_LD() \
    asm volatile("tcgen05.wait::ld.sync.aligned;" ::: "memory")
#define FENCE_PROXY_ASYNC_SHARED_CTA() \
    asm volatile("fence.proxy.async.shared::cta;" ::: "memory")

#define TCGEN05_LD_32X32B_X32(r, tmem_addr) \
    asm volatile( \
        "tcgen05.ld.sync.aligned.32x32b.x32.b32 " \
        "{%0, %1, %2, %3, %4, %5, %6, %7, " \
        " %8, %9, %10, %11, %12, %13, %14, %15, " \
        " %16, %17, %18, %19, %20, %21, %22, %23, " \
        " %24, %25, %26, %27, %28, %29, %30, %31}, [%32];" \
        : "=r"((r)[0]),  "=r"((r)[1]),  "=r"((r)[2]),  "=r"((r)[3]), \
          "=r"((r)[4]),  "=r"((r)[5]),  "=r"((r)[6]),  "=r"((r)[7]), \
          "=r"((r)[8]),  "=r"((r)[9]),  "=r"((r)[10]), "=r"((r)[11]), \
          "=r"((r)[12]), "=r"((r)[13]), "=r"((r)[14]), "=r"((r)[15]), \
          "=r"((r)[16]), "=r"((r)[17]), "=r"((r)[18]), "=r"((r)[19]), \
          "=r"((r)[20]), "=r"((r)[21]), "=r"((r)[22]), "=r"((r)[23]), \
          "=r"((r)[24]), "=r"((r)[25]), "=r"((r)[26]), "=r"((r)[27]), \
          "=r"((r)[28]), "=r"((r)[29]), "=r"((r)[30]), "=r"((r)[31]) \
        : "r"(tmem_addr))

#define SMEM_DESC_BASE_SW128 \
    ((uint64_t(2)  << 61) | (uint64_t(1) << 46) | \
     (uint64_t(64) << 32) | (uint64_t(1) << 16))
#define MAKE_SMEM_DESC(base_addr) \
    (SMEM_DESC_BASE_SW128 | ((uint64_t)((base_addr) >> 4) & 0x3FFF))
#define SMEM_DESC_BASE_SW64 \
    ((uint64_t(4)  << 61) | (uint64_t(1) << 46) | \
     (uint64_t(32) << 32) | (uint64_t(1) << 16))
#define MAKE_SMEM_DESC_SW64(base_addr) \
    (SMEM_DESC_BASE_SW64 | ((uint64_t)((base_addr) >> 4) & 0x3FFF))

#define SMEM_SWIZZLE_128B(byte_offset) \
    ((byte_offset) ^ (((byte_offset) >> 3) & 0x70))

__device__ __forceinline__ void tcgen05_mma_f16_ss(
    uint32_t d_tmem, uint64_t a_desc, uint64_t b_desc,
    uint32_t idesc, uint32_t enable)
{
    asm volatile(
        "{\n\t"
        ".reg .pred p;\n\t"
        "setp.ne.u32 p, %6, 0;\n\t"
        "tcgen05.mma.cta_group::1.kind::f16 [%0], %1, %2, %3, "
        "{%4, %4, %4, %4}, p;\n\t"
        "}"
        :: "r"(d_tmem), "l"(a_desc), "l"(b_desc), "r"(idesc),
           "r"(0u), "r"(0u), "r"(enable)
        : "memory");
}

#define IDESC_G  0x8200010u   // M=128, N=128
#define IDESC_PV 0x8100010u   // M=128, N=64
#endif  // HAS_TCGEN05

// ============================================================
// tcgen05 F16 2-TERM GEMM: C = (Ah+Al) @ Wh^T (+ epilogue)
//   TILED A(h,l)/W(h) inputs, bulk-copy, BK=32, 3 stages of
//   24KB -> 73KB smem -> 3 CTAs/SM. 4 MMA dispatches per iter.
//   EPI: 1 +bias+res f32 | 2 gelu->tiled split | 3 tiled split |
//        4 -> vT panels | 5 -> tiled hi-only round (K operands)
// ============================================================
#define GT_TILE(buf, which) (1024 + (buf) * 24576 + (which) * 8192)
#define GT_SMEM_BYTES (1024 + 3 * 24576)   // 74752 -> 3 CTAs/SM

template<int EPI>
__global__ __launch_bounds__(256, 3)
void tc_gemm(void* __restrict__ Cp, void* __restrict__ C2p,
             const __half* __restrict__ Ah, const __half* __restrict__ Al,
             const __half* __restrict__ Wh,
             const float* __restrict__ bias, const float* __restrict__ res,
             int M, int N, int K)
{
#if HAS_TCGEN05
    extern __shared__ __align__(1024) char gsm[];
    const uint32_t sb = smem_u32(gsm);
    const int tid  = threadIdx.x;
    const int wid  = tid >> 5;
    const int lane = tid & 31;

    if (tid == 0) {
        MBARRIER_INIT(sb + 8, 1);   // mma buf0
        MBARRIER_INIT(sb + 16, 1);  // mma buf1
        MBARRIER_INIT(sb + 24, 1);  // mma buf2
        MBARRIER_INIT(sb + 32, 1);  // load buf0
        MBARRIER_INIT(sb + 40, 1);  // load buf1
        MBARRIER_INIT(sb + 48, 1);  // load buf2
        FENCE_PROXY_ASYNC_SHARED_CTA();
    }
    if (wid == 0) {
        TCGEN05_ALLOC(sb + 0, 128);
        TCGEN05_RELINQUISH();
    }
    __syncthreads();
    uint32_t tmem;
    asm volatile("ld.shared.b32 %0, [%1];" : "=r"(tmem) : "r"(sb + 0));

    const int iters = K >> 5;
    const int kb = K >> 5;

    if (tid == 0) {
        const char* Ahc = (const char*)Ah + (size_t)(blockIdx.y) * kb * 8192;
        const char* Alc = (const char*)Al + (size_t)(blockIdx.y) * kb * 8192;
        const char* Whc = (const char*)Wh + (size_t)(blockIdx.x) * kb * 8192;

        #pragma unroll
        for (int s = 0; s < 2; s++) {
            MBARRIER_EXPECT_TX(sb + 32 + s * 8, 24576);
            CP_BULK_G2S(sb + GT_TILE(s, 0), Ahc + (size_t)s * 8192, 8192, sb + 32 + s * 8);
            CP_BULK_G2S(sb + GT_TILE(s, 1), Alc + (size_t)s * 8192, 8192, sb + 32 + s * 8);
            CP_BULK_G2S(sb + GT_TILE(s, 2), Whc + (size_t)s * 8192, 8192, sb + 32 + s * 8);
        }

        for (int i = 0; i < iters; i++) {
            const int b = i % 3;
            MBARRIER_WAIT_PARITY(sb + 32 + b * 8, (i / 3) & 1);

            const uint64_t dAh = MAKE_SMEM_DESC_SW64(sb + GT_TILE(b, 0));
            const uint64_t dAl = MAKE_SMEM_DESC_SW64(sb + GT_TILE(b, 1));
            const uint64_t dBh = MAKE_SMEM_DESC_SW64(sb + GT_TILE(b, 2));
            #pragma unroll
            for (int kk = 0; kk < 2; kk++) {
                const uint64_t o = kk * 2;
                tcgen05_mma_f16_ss(tmem, dAh + o, dBh + o, IDESC_G,
                                   (i > 0 || kk > 0) ? 1u : 0u);
                tcgen05_mma_f16_ss(tmem, dAl + o, dBh + o, IDESC_G, 1u);
            }
            TCGEN05_COMMIT(sb + 8 + b * 8);

            const int j2 = i + 2;
            if (j2 < iters) {
                const int b2 = j2 % 3;
                if (i >= 1)
                    MBARRIER_WAIT_PARITY(sb + 8 + ((i - 1) % 3) * 8,
                                         ((i - 1) / 3) & 1);
                MBARRIER_EXPECT_TX(sb + 32 + b2 * 8, 24576);
                CP_BULK_G2S(sb + GT_TILE(b2, 0), Ahc + (size_t)j2 * 8192, 8192, sb + 32 + b2 * 8);
                CP_BULK_G2S(sb + GT_TILE(b2, 1), Alc + (size_t)j2 * 8192, 8192, sb + 32 + b2 * 8);
                CP_BULK_G2S(sb + GT_TILE(b2, 2), Whc + (size_t)j2 * 8192, 8192, sb + 32 + b2 * 8);
            }
        }
    }

    __syncthreads();
    MBARRIER_WAIT_PARITY(sb + 8 + ((iters - 1) % 3) * 8, ((iters - 1) / 3) & 1);
    TCGEN05_FENCE_AFTER();

    // Epilogue
    {
        const int bm = blockIdx.y * 128;
        const int bn = blockIdx.x * 128;
        const int sub = wid & 3;
        const int h2  = wid >> 2;
        const int row = bm + sub * 32 + lane;
        #pragma unroll
        for (int q = 0; q < 2; q++) {
            uint32_t r[32];
            TCGEN05_LD_32X32B_X32(r, tmem + h2 * 64 + q * 32);
            TCGEN05_WAIT_LD();
            #pragma unroll
            for (int c4 = 0; c4 < 8; c4++) {
                const int col = bn + h2 * 64 + q * 32 + c4 * 4;
                float4 v;
                v.x = __uint_as_float(r[c4 * 4 + 0]);
                v.y = __uint_as_float(r[c4 * 4 + 1]);
                v.z = __uint_as_float(r[c4 * 4 + 2]);
                v.w = __uint_as_float(r[c4 * 4 + 3]);
                if (EPI == 1 || EPI == 2) {
                    float4 bi = *(const float4*)&bias[col];
                    v.x += bi.x; v.y += bi.y; v.z += bi.z; v.w += bi.w;
                }
                if (EPI == 1) {
                    float4 rv = *(const float4*)&res[(size_t)row * N + col];
                    v.x += rv.x; v.y += rv.y; v.z += rv.z; v.w += rv.w;
                    *(float4*)((float*)Cp + (size_t)row * N + col) = v;
                }
                if (EPI == 2) {
                    v.x = gelu_exact(v.x); v.y = gelu_exact(v.y);
                    v.z = gelu_exact(v.z); v.w = gelu_exact(v.w);
                }
                if (EPI == 2 || EPI == 3) {   // tiled f16 split
                    __half h0,h1,h2_,h3,l0,l1,l2,l3;
                    h_split(v.x,h0,l0); h_split(v.y,h1,l1);
                    h_split(v.z,h2_,l2); h_split(v.w,h3,l3);
                    const size_t off = tiled_off(row, col, N);
                    *(uint2*)((char*)Cp  + off) = make_uint2(pack2(h0,h1), pack2(h2_,h3));
                    *(uint2*)((char*)C2p + off) = make_uint2(pack2(l0,l1), pack2(l2,l3));
                }
                if (EPI == 4) {   // pre-transposed vT panels (f16 round)
                    char* base = (char*)Cp;
                    *(__half*)(base + vt_off(row, col + 0)) = __float2half_rn(v.x);
                    *(__half*)(base + vt_off(row, col + 1)) = __float2half_rn(v.y);
                    *(__half*)(base + vt_off(row, col + 2)) = __float2half_rn(v.z);
                    *(__half*)(base + vt_off(row, col + 3)) = __float2half_rn(v.w);
                }
                if (EPI == 5) {   // tiled hi-only f16 round (K operands)
                    const size_t off = tiled_off(row, col, N);
                    *(uint2*)((char*)Cp + off) =
                        make_uint2(pack2(__float2half_rn(v.x), __float2half_rn(v.y)),
                                   pack2(__float2half_rn(v.z), __float2half_rn(v.w)));
                }
            }
        }
    }

    __syncthreads();
    if (wid == 0) TCGEN05_DEALLOC(tmem, 128);
#endif
}

// ============================================================
// tcgen05 f16 flash attention: 2-term S = (Qh+Ql)@Kh^T.
//   Q TILED bulk hi/lo, K TILED bulk hi-only, V^T pre-transposed
//   bulk. smem 97KB, occ 2 (TMEM-capped).
// ============================================================
#define TF_QH    1024
#define TF_QL    (TF_QH + 16384)
#define TF_KH    (TF_QH + 32768)
#define TF_VT    (TF_QH + 49152)   // 2 panels x 8 KB (SW128)
#define TF_P     (TF_QH + 65536)   // 2 panels x 16 KB (SW128)
#define TF_SMEM_BYTES (TF_P + 32768)  // 99328

template<int MASK>
__global__ __launch_bounds__(256, 2)
void tc_flash(__half* __restrict__ Oh, __half* __restrict__ Ol,
              const __half* __restrict__ Qh, const __half* __restrict__ Ql,
              const __half* __restrict__ Kh,
              const __half* __restrict__ Vp, int kvlen)
{
#if HAS_TCGEN05
    extern __shared__ __align__(1024) char fsm[];
    const uint32_t sb = smem_u32(fsm);
    const int tid  = threadIdx.x;
    const int wid  = tid >> 5;
    const int lane = tid & 31;
    const int sub  = wid & 3;
    const int h2   = wid >> 2;
    const int q0   = blockIdx.x * 128;
    const int h    = blockIdx.y;
    const int b    = blockIdx.z;

    if (tid == 0) {
        MBARRIER_INIT(sb + 8, 1);    // S done
        MBARRIER_INIT(sb + 16, 1);   // PV done
        MBARRIER_INIT(sb + 24, 1);   // Q loaded
        MBARRIER_INIT(sb + 32, 1);   // K loaded
        MBARRIER_INIT(sb + 48, 1);   // V loaded
        FENCE_PROXY_ASYNC_SHARED_CTA();
    }
    if (wid == 0) {
        TCGEN05_ALLOC(sb + 0, 256);
        TCGEN05_RELINQUISH();
    }
    __syncthreads();
    uint32_t tmem;
    asm volatile("ld.shared.b32 %0, [%1];" : "=r"(tmem) : "r"(sb + 0));

    const size_t qblk = ((size_t)((b * SQ_ + q0) >> 7) * 16 + 2 * h) * 8192;
    if (tid == 0) {
        MBARRIER_EXPECT_TX(sb + 24, 32768);
        CP_BULK_G2S(sb + TF_QH, (const char*)Qh + qblk, 16384, sb + 24);
        CP_BULK_G2S(sb + TF_QL, (const char*)Ql + qblk, 16384, sb + 24);
        const size_t kblk = ((size_t)((b * kvlen) >> 7) * 16 + 2 * h) * 8192;
        MBARRIER_EXPECT_TX(sb + 32, 16384);
        CP_BULK_G2S(sb + TF_KH, (const char*)Kh + kblk, 16384, sb + 32);
    }

    float lsum = 0.f;
    const int qrow = sub * 32 + lane;
    const int qg   = q0 + qrow;

    const int ntiles = kvlen >> 7;
    for (int t = 0; t < ntiles; t++) {
        const int kv0 = t << 7;

        // ---- S = (Qh+Ql) @ Kh^T (SW64 tiles, 8 dispatches) ----
        if (tid == 0) {
            if (t == 0) MBARRIER_WAIT_PARITY(sb + 24, 0);
            MBARRIER_WAIT_PARITY(sb + 32, t & 1);
            #pragma unroll
            for (int blk = 0; blk < 2; blk++) {
                const uint64_t dQh = MAKE_SMEM_DESC_SW64(sb + TF_QH + blk * 8192);
                const uint64_t dQl = MAKE_SMEM_DESC_SW64(sb + TF_QL + blk * 8192);
                const uint64_t dKh = MAKE_SMEM_DESC_SW64(sb + TF_KH + blk * 8192);
                #pragma unroll
                for (int kk = 0; kk < 2; kk++) {
                    const uint64_t o = kk * 2;
                    tcgen05_mma_f16_ss(tmem + 64, dQh + o, dKh + o, IDESC_G,
                                       (blk == 0 && kk == 0) ? 0u : 1u);
                    tcgen05_mma_f16_ss(tmem + 64, dQl + o, dKh + o, IDESC_G, 1u);
                }
            }
            TCGEN05_COMMIT(sb + 8);
        }

        // ---- PV(t-1) drain frees VT/P, then bulk-load V(t) ----
        if (t > 0) {
            MBARRIER_WAIT_PARITY(sb + 16, (t - 1) & 1);
        }
        if (tid == 0) {
            const size_t vblk = ((size_t)((b * kvlen + kv0) >> 6) * 8 + h) * 8192;
            MBARRIER_EXPECT_TX(sb + 48, 16384);
            CP_BULK_G2S(sb + TF_VT,        (const char*)Vp + vblk,             8192, sb + 48);
            CP_BULK_G2S(sb + TF_VT + 8192, (const char*)Vp + vblk + 8 * 8192,  8192, sb + 48);
        }

        // ---- Wait S (all); prefetch next K (tid0) ----
        MBARRIER_WAIT_PARITY(sb + 8, t & 1);
        TCGEN05_FENCE_AFTER();
        if (tid == 0 && t + 1 < ntiles) {
            const size_t kblk = ((size_t)((b * kvlen + kv0 + 128) >> 7) * 16 + 2 * h) * 8192;
            MBARRIER_EXPECT_TX(sb + 32, 16384);
            CP_BULK_G2S(sb + TF_KH, (const char*)Kh + kblk, 16384, sb + 32);
        }

        // ---- softmax (unnormalized) -> f16 P (SW128) ----
        #pragma unroll
        for (int chunk = 0; chunk < 2; chunk++) {
            uint32_t r[32];
            TCGEN05_LD_32X32B_X32(r, tmem + 64 + h2 * 64 + chunk * 32);
            TCGEN05_WAIT_LD();
            const int kvb = h2 * 64 + chunk * 32;
            char* Pp = fsm + TF_P + h2 * 16384;
            #pragma unroll
            for (int c16 = 0; c16 < 4; c16++) {
                uint32_t w[4];
                #pragma unroll
                for (int pr = 0; pr < 4; pr++) {
                    __half hs[2];
                    #pragma unroll
                    for (int j = 0; j < 2; j++) {
                        const float s = __uint_as_float(r[c16 * 8 + pr * 2 + j]);
                        const int kg = kv0 + kvb + c16 * 8 + pr * 2 + j;
                        float wm;
                        if (MASK == 1) wm = ((qg < 512) == (kg < 512)) ? 1.25f : 1.0f;
                        else           wm = ((qg >> 8)  == (kg >> 8))  ? 1.25f : 1.0f;
                        const float p = __expf(s * (0.125f * wm));
                        hs[j] = __float2half_rn(p);
                        lsum += __half2float(hs[j]);
                    }
                    w[pr] = pack2(hs[0], hs[1]);
                }
                const uint32_t sw = SMEM_SWIZZLE_128B(
                    (uint32_t)(qrow * 128 + chunk * 64 + c16 * 16));
                *(uint4*)(Pp + sw) = make_uint4(w[0], w[1], w[2], w[3]);
            }
        }
        TCGEN05_FENCE_BEFORE();
        __syncthreads();

        // ---- O += P @ V^T (SW128, 8 dispatches) ----
        if (tid == 0) {
            FENCE_PROXY_ASYNC_SHARED_CTA();
            MBARRIER_WAIT_PARITY(sb + 48, t & 1);   // V(t) landed
            #pragma unroll
            for (int p2 = 0; p2 < 2; p2++) {
                const uint64_t dP = MAKE_SMEM_DESC(sb + TF_P  + p2 * 16384);
                const uint64_t dV = MAKE_SMEM_DESC(sb + TF_VT + p2 * 8192);
                #pragma unroll
                for (int kk = 0; kk < 4; kk++) {
                    const uint64_t o = kk * 2;
                    tcgen05_mma_f16_ss(tmem, dP + o, dV + o, IDESC_PV,
                                       (t == 0 && p2 == 0 && kk == 0) ? 0u : 1u);
                }
            }
            TCGEN05_COMMIT(sb + 16);
        }
    }

    MBARRIER_WAIT_PARITY(sb + 16, (ntiles - 1) & 1);
    TCGEN05_FENCE_AFTER();

    // combine row sums across column-half warpgroups
    {
        float* lx = (float*)(fsm + TF_VT);
        lx[wid * 32 + lane] = lsum;
    }
    __syncthreads();
    const float lother = ((float*)(fsm + TF_VT))[(wid ^ 4) * 32 + lane];
    const float inv = 1.0f / (lsum + lother);

    // O epilogue: tiled f16 split (feeds wo GEMM)
    {
        uint32_t r[32];
        TCGEN05_LD_32X32B_X32(r, tmem + h2 * 32);
        TCGEN05_WAIT_LD();
        const int orow = b * SQ_ + qg;
        #pragma unroll
        for (int c4 = 0; c4 < 8; c4++) {
            __half h0,h1,h2_,h3,l0,l1,l2,l3;
            h_split(__uint_as_float(r[c4*4+0]) * inv, h0, l0);
            h_split(__uint_as_float(r[c4*4+1]) * inv, h1, l1);
            h_split(__uint_as_float(r[c4*4+2]) * inv, h2_, l2);
            h_split(__uint_as_float(r[c4*4+3]) * inv, h3, l3);
            const size_t off = tiled_off(orow, h * DH_ + h2 * 32 + c4 * 4, D_);
            *(uint2*)((char*)Oh + off) = make_uint2(pack2(h0,h1), pack2(h2_,h3));
            *(uint2*)((char*)Ol + off) = make_uint2(pack2(l0,l1), pack2(l2,l3));
        }
    }

    __syncthreads();
    if (wid == 0) TCGEN05_DEALLOC(tmem, 256);
#endif  // HAS_TCGEN05
}

// ============================================================
// SIMT SGEMM fallback (round-1 proven, fp32)
// ============================================================
template<int EPI>
__global__ __launch_bounds__(256)
void sgemm_kernel(float* __restrict__ C,
                  const float* __restrict__ A,
                  const float* __restrict__ W,
                  const float* __restrict__ bias,
                  const float* __restrict__ res,
                  int M, int N, int K)
{
    __shared__ float As[8][128];
    __shared__ float Bs[8][128];

    const int tid = threadIdx.x;
    const int bm  = blockIdx.y * 128;
    const int bn  = blockIdx.x * 128;

    const int lr = tid >> 1;
    const int lc = (tid & 1) * 4;
    const float* Aptr = A + (size_t)(bm + lr) * K + lc;
    const float* Wptr = W + (size_t)(bn + lr) * K + lc;

    const int ty = tid >> 4;
    const int tx = tid & 15;

    float acc[8][8];
    #pragma unroll
    for (int i = 0; i < 8; i++)
        #pragma unroll
        for (int j = 0; j < 8; j++) acc[i][j] = 0.f;

    for (int k0 = 0; k0 < K; k0 += 8) {
        float4 a4 = *(const float4*)(Aptr + k0);
        float4 b4 = *(const float4*)(Wptr + k0);
        As[lc + 0][lr] = a4.x; As[lc + 1][lr] = a4.y;
        As[lc + 2][lr] = a4.z; As[lc + 3][lr] = a4.w;
        Bs[lc + 0][lr] = b4.x; Bs[lc + 1][lr] = b4.y;
        Bs[lc + 2][lr] = b4.z; Bs[lc + 3][lr] = b4.w;
        __syncthreads();

        #pragma unroll
        for (int kk = 0; kk < 8; kk++) {
            float ra[8], rb[8];
            *(float4*)(ra)     = *(const float4*)&As[kk][ty * 4];
            *(float4*)(ra + 4) = *(const float4*)&As[kk][ty * 4 + 64];
            *(float4*)(rb)     = *(const float4*)&Bs[kk][tx * 4];
            *(float4*)(rb + 4) = *(const float4*)&Bs[kk][tx * 4 + 64];
            #pragma unroll
            for (int i = 0; i < 8; i++)
                #pragma unroll
                for (int j = 0; j < 8; j++)
                    acc[i][j] += ra[i] * rb[j];
        }
        __syncthreads();
    }

    #pragma unroll
    for (int i = 0; i < 8; i++) {
        const int row = bm + ty * 4 + (i & 3) + (i >> 2) * 64;
        #pragma unroll
        for (int jh = 0; jh < 2; jh++) {
            const int col = bn + tx * 4 + jh * 64;
            float4 v;
            v.x = acc[i][jh * 4 + 0];
            v.y = acc[i][jh * 4 + 1];
            v.z = acc[i][jh * 4 + 2];
            v.w = acc[i][jh * 4 + 3];
            if (EPI >= 1) {
                float4 bi = *(const float4*)&bias[col];
                v.x += bi.x; v.y += bi.y; v.z += bi.z; v.w += bi.w;
            }
            if (EPI == 1) {
                float4 rv = *(const float4*)&res[(size_t)row * N + col];
                v.x += rv.x; v.y += rv.y; v.z += rv.z; v.w += rv.w;
            }
            if (EPI == 2) {
                v.x = gelu_exact(v.x); v.y = gelu_exact(v.y);
                v.z = gelu_exact(v.z); v.w = gelu_exact(v.w);
            }
            *(float4*)&C[(size_t)row * N + col] = v;
        }
    }
}

// ============================================================
// SIMT flash attention fallback (round-1 proven, fp32)
// ============================================================
#define FA_STRIDE 68
#define FA_SMEM_FLOATS ((128 + 64 + 64 + 128) * FA_STRIDE)
#define FA_SMEM_BYTES  (FA_SMEM_FLOATS * 4)

template<int MASK>
__global__ __launch_bounds__(256)
void flash_kernel(float* __restrict__ O,
                  const float* __restrict__ Q,
                  const float* __restrict__ Kp,
                  const float* __restrict__ Vp,
                  int kvlen)
{
    extern __shared__ float fsm2[];
    float* Qs = fsm2;
    float* Ks = Qs + 128 * FA_STRIDE;
    float* Vt = Ks + 64  * FA_STRIDE;
    float* Ps = Vt + 64  * FA_STRIDE;

    const int tid = threadIdx.x;
    const int q0  = blockIdx.x * 128;
    const int h   = blockIdx.y;
    const int b   = blockIdx.z;
    const int rg  = tid >> 4;
    const int cg  = tid & 15;

    {
        const int qrow = tid >> 1;
        const int half = tid & 1;
        const float* qbase = Q + (size_t)(b * SQ_ + q0 + qrow) * D_ + h * DH_;
        #pragma unroll
        for (int i = 0; i < 8; i++) {
            const int f4 = half * 8 + i;
            *(float4*)&Qs[qrow * FA_STRIDE + f4 * 4] = *(const float4*)&qbase[f4 * 4];
        }
    }

    float m_i[8], l_i[8], oacc[8][4];
    #pragma unroll
    for (int u = 0; u < 8; u++) {
        m_i[u] = -1e30f; l_i[u] = 0.f;
        #pragma unroll
        for (int t = 0; t < 4; t++) oacc[u][t] = 0.f;
    }

    const int ntiles = kvlen >> 6;
    for (int t0 = 0; t0 < ntiles; t0++) {
        const int kv0 = t0 * 64;
        __syncthreads();

        {
            const int lrow = tid >> 2;
            const int lq   = tid & 3;
            const float* kbase = Kp + (size_t)(b * kvlen + kv0 + lrow) * D_ + h * DH_;
            const float* vbase = Vp + (size_t)(b * kvlen + kv0 + lrow) * D_ + h * DH_;
            #pragma unroll
            for (int i = 0; i < 4; i++) {
                const int f4 = lq * 4 + i;
                float4 k4 = *(const float4*)&kbase[f4 * 4];
                *(float4*)&Ks[lrow * FA_STRIDE + f4 * 4] = k4;
                float4 v4 = *(const float4*)&vbase[f4 * 4];
                const int d0 = f4 * 4;
                Vt[(d0 + 0) * FA_STRIDE + lrow] = v4.x;
                Vt[(d0 + 1) * FA_STRIDE + lrow] = v4.y;
                Vt[(d0 + 2) * FA_STRIDE + lrow] = v4.z;
                Vt[(d0 + 3) * FA_STRIDE + lrow] = v4.w;
            }
        }
        __syncthreads();

        float sacc[8][4];
        #pragma unroll
        for (int u = 0; u < 8; u++)
            #pragma unroll
            for (int t = 0; t < 4; t++) sacc[u][t] = 0.f;

        #pragma unroll
        for (int d4 = 0; d4 < 16; d4++) {
            float4 qv[8];
            #pragma unroll
            for (int u = 0; u < 8; u++)
                qv[u] = *(const float4*)&Qs[(rg + 16 * u) * FA_STRIDE + d4 * 4];
            #pragma unroll
            for (int t = 0; t < 4; t++) {
                float4 kk = *(const float4*)&Ks[(cg + 16 * t) * FA_STRIDE + d4 * 4];
                #pragma unroll
                for (int u = 0; u < 8; u++)
                    sacc[u][t] += qv[u].x * kk.x + qv[u].y * kk.y
                                + qv[u].z * kk.z + qv[u].w * kk.w;
            }
        }

        #pragma unroll
        for (int u = 0; u < 8; u++) {
            const int qg = q0 + rg + 16 * u;
            #pragma unroll
            for (int t = 0; t < 4; t++) {
                const int kg = kv0 + cg + 16 * t;
                float wm;
                if (MASK == 1) wm = ((qg < 512) == (kg < 512)) ? 1.25f : 1.0f;
                else           wm = ((qg >> 8)  == (kg >> 8))  ? 1.25f : 1.0f;
                sacc[u][t] *= 0.125f * wm;
            }
        }

        #pragma unroll
        for (int u = 0; u < 8; u++) {
            float rmax = fmaxf(fmaxf(sacc[u][0], sacc[u][1]),
                               fmaxf(sacc[u][2], sacc[u][3]));
            #pragma unroll
            for (int off = 8; off >= 1; off >>= 1)
                rmax = fmaxf(rmax, __shfl_xor_sync(0xffffffffu, rmax, off));
            const float mnew  = fmaxf(m_i[u], rmax);
            const float alpha = __expf(m_i[u] - mnew);
            m_i[u] = mnew;
            float rsum = 0.f;
            #pragma unroll
            for (int t = 0; t < 4; t++) {
                const float p = __expf(sacc[u][t] - mnew);
                Ps[(rg + 16 * u) * FA_STRIDE + cg + 16 * t] = p;
                rsum += p;
            }
            #pragma unroll
            for (int off = 8; off >= 1; off >>= 1)
                rsum += __shfl_xor_sync(0xffffffffu, rsum, off);
            l_i[u] = l_i[u] * alpha + rsum;
            #pragma unroll
            for (int t = 0; t < 4; t++) oacc[u][t] *= alpha;
        }
        __syncthreads();

        #pragma unroll
        for (int j4 = 0; j4 < 16; j4++) {
            float4 pv[8];
            #pragma unroll
            for (int u = 0; u < 8; u++)
                pv[u] = *(const float4*)&Ps[(rg + 16 * u) * FA_STRIDE + j4 * 4];
            #pragma unroll
            for (int t = 0; t < 4; t++) {
                float4 vv = *(const float4*)&Vt[(cg + 16 * t) * FA_STRIDE + j4 * 4];
                #pragma unroll
                for (int u = 0; u < 8; u++)
                    oacc[u][t] += pv[u].x * vv.x + pv[u].y * vv.y
                                + pv[u].z * vv.z + pv[u].w * vv.w;
            }
        }
    }

    #pragma unroll
    for (int u = 0; u < 8; u++) {
        const float inv = 1.0f / l_i[u];
        const size_t row = (size_t)(b * SQ_ + q0 + rg + 16 * u);
        #pragma unroll
        for (int t = 0; t < 4; t++)
            O[row * D_ + h * DH_ + cg + 16 * t] = oacc[u][t] * inv;
    }
}

// ============================================================
// LayerNorm over D=512; SPLIT=1 also emits TILED f16 hi/lo split
// ============================================================
template<int SPLIT>
__global__ __launch_bounds__(256)
void layernorm_kernel(float* __restrict__ out,
                      __half* __restrict__ oh, __half* __restrict__ ol,
                      const float* __restrict__ in,
                      const float* __restrict__ g, const float* __restrict__ b,
                      int rows)
{
    const int gt   = blockIdx.x * 256 + threadIdx.x;
    const int row  = gt >> 5;
    const int lane = gt & 31;
    if (row >= rows) return;

    const float* x = in + (size_t)row * D_;
    float4 v[4];
    float s = 0.f;
    #pragma unroll
    for (int i = 0; i < 4; i++) {
        v[i] = *(const float4*)&x[(lane + i * 32) * 4];
        s += v[i].x + v[i].y + v[i].z + v[i].w;
    }
    #pragma unroll
    for (int o = 16; o; o >>= 1) s += __shfl_xor_sync(0xffffffffu, s, o);
    const float mean = s * (1.0f / 512.0f);

    float var = 0.f;
    #pragma unroll
    for (int i = 0; i < 4; i++) {
        float dx = v[i].x - mean; var += dx * dx;
        dx = v[i].y - mean; var += dx * dx;
        dx = v[i].z - mean; var += dx * dx;
        dx = v[i].w - mean; var += dx * dx;
    }
    #pragma unroll
    for (int o = 16; o; o >>= 1) var += __shfl_xor_sync(0xffffffffu, var, o);
    const float rstd = rsqrtf(var * (1.0f / 512.0f) + 1e-5f);

    #pragma unroll
    for (int i = 0; i < 4; i++) {
        const int c = (lane + i * 32) * 4;
        float4 gv = *(const float4*)&g[c];
        float4 bv = *(const float4*)&b[c];
        float4 o4;
        o4.x = (v[i].x - mean) * rstd * gv.x + bv.x;
        o4.y = (v[i].y - mean) * rstd * gv.y + bv.y;
        o4.z = (v[i].z - mean) * rstd * gv.z + bv.z;
        o4.w = (v[i].w - mean) * rstd * gv.w + bv.w;
        *(float4*)&out[(size_t)row * D_ + c] = o4;
        if (SPLIT) {
            __half h0,h1,h2,h3,l0,l1,l2,l3;
            h_split(o4.x,h0,l0); h_split(o4.y,h1,l1);
            h_split(o4.z,h2,l2); h_split(o4.w,h3,l3);
            const size_t off = tiled_off(row, c, D_);
            *(uint2*)((char*)oh + off) = make_uint2(pack2(h0,h1), pack2(h2,h3));
            *(uint2*)((char*)ol + off) = make_uint2(pack2(l0,l1), pack2(l2,l3));
        }
    }
}

// ============================================================
// Launch
// ============================================================
static void* sym(const void* symbol) {
    void* p = nullptr;
    cudaGetSymbolAddress(&p, symbol);
    return p;
}

extern "C" void kernel_launch(void* const* d_in, const int* in_sizes, int n_in,
                              void* d_out, int out_size)
{
    const float* cords   = (const float*)d_in[0];
    const float* spatial = (const float*)d_in[1];
    const float* speed   = (const float*)d_in[2];
    const float* wq1 = (const float*)d_in[3];
    const float* wk1 = (const float*)d_in[4];
    const float* wv1 = (const float*)d_in[5];
    const float* wo1 = (const float*)d_in[6];
    const float* bo1 = (const float*)d_in[7];
    const float* wq2 = (const float*)d_in[8];
    const float* wk2 = (const float*)d_in[9];
    const float* wv2 = (const float*)d_in[10];
    const float* wo2 = (const float*)d_in[11];
    const float* bo2 = (const float*)d_in[12];
    const float* ln1_g = (const float*)d_in[13];
    const float* ln1_b = (const float*)d_in[14];
    const float* ln2_g = (const float*)d_in[15];
    const float* ln2_b = (const float*)d_in[16];
    const float* ln3_g = (const float*)d_in[17];
    const float* ln3_b = (const float*)d_in[18];
    const float* ffn_w1 = (const float*)d_in[19];
    const float* ffn_b1 = (const float*)d_in[20];
    const float* ffn_w2 = (const float*)d_in[21];
    const float* ffn_b2 = (const float*)d_in[22];
    float* out = (float*)d_out;

    cudaFuncAttributes fa{};
    bool tc1 = false, tc2 = false;
    if (cudaFuncGetAttributes(&fa, (const void*)tc_gemm<1>) == cudaSuccess)
        tc1 = (fa.numRegs >= 32);
    if (cudaFuncGetAttributes(&fa, (const void*)tc_flash<1>) == cudaSuccess)
        tc2 = (fa.numRegs >= 32);
    const bool use_tc = tc1 && tc2;

    static cudaStream_t s1 = nullptr, s2 = nullptr, s3 = nullptr;
    static cudaEvent_t  evF = nullptr, ev1 = nullptr, ev2 = nullptr, ev3 = nullptr;
    static int sinit = 0;
    if (sinit == 0) {
        bool ok = true;
        ok &= (cudaStreamCreateWithFlags(&s1, cudaStreamNonBlocking) == cudaSuccess);
        ok &= (cudaStreamCreateWithFlags(&s2, cudaStreamNonBlocking) == cudaSuccess);
        ok &= (cudaStreamCreateWithFlags(&s3, cudaStreamNonBlocking) == cudaSuccess);
        ok &= (cudaEventCreateWithFlags(&evF, cudaEventDisableTiming) == cudaSuccess);
        ok &= (cudaEventCreateWithFlags(&ev1, cudaEventDisableTiming) == cudaSuccess);
        ok &= (cudaEventCreateWithFlags(&ev2, cudaEventDisableTiming) == cudaSuccess);
        ok &= (cudaEventCreateWithFlags(&ev3, cudaEventDisableTiming) == cudaSuccess);
        sinit = ok ? 1 : -1;
    }
    const bool multi = (sinit == 1) && use_tc;
    cudaStream_t t1 = multi ? s1 : 0;
    cudaStream_t t2 = multi ? s2 : 0;
    cudaStream_t t3 = multi ? s3 : 0;

    // R10 grids (BN=128)
    const dim3 gProj(D_ / 128, MQ_ / 128);     // (4, 48)
    const dim3 gKV1 (D_ / 128, MKV1_ / 128);   // (4, 64)
    const dim3 gFFN1(DF_ / 128, MQ_ / 128);    // (16, 48)
    const dim3 gFA  (SQ_ / 128, H_, B_);       // (6, 8, 8)
    const int  lnBlocks = MQ_ * 32 / 256;      // 768

    float* tmp = (float*)sym(g_tmp);
    float* x1  = (float*)sym(g_x1);
    float* x2  = (float*)sym(g_x2);

    if (use_tc) {
        cudaFuncSetAttribute((const void*)tc_gemm<1>, cudaFuncAttributeMaxDynamicSharedMemorySize, GT_SMEM_BYTES);
        cudaFuncSetAttribute((const void*)tc_gemm<2>, cudaFuncAttributeMaxDynamicSharedMemorySize, GT_SMEM_BYTES);
        cudaFuncSetAttribute((const void*)tc_gemm<3>, cudaFuncAttributeMaxDynamicSharedMemorySize, GT_SMEM_BYTES);
        cudaFuncSetAttribute((const void*)tc_gemm<4>, cudaFuncAttributeMaxDynamicSharedMemorySize, GT_SMEM_BYTES);
        cudaFuncSetAttribute((const void*)tc_gemm<5>, cudaFuncAttributeMaxDynamicSharedMemorySize, GT_SMEM_BYTES);
        cudaFuncSetAttribute((const void*)tc_flash<1>, cudaFuncAttributeMaxDynamicSharedMemorySize, TF_SMEM_BYTES);
        cudaFuncSetAttribute((const void*)tc_flash<2>, cudaFuncAttributeMaxDynamicSharedMemorySize, TF_SMEM_BYTES);

        // ---- split inputs + weights -> tiled f16 (weights hi-only) ----
        SplitJobs jb{};
        const float* srcs[NSPLIT] = {cords, spatial, speed,
                                     wq1, wk1, wv1, wo1, wq2, wk2, wv2, wo2,
                                     ffn_w1, ffn_w2};
        void* dsth[NSPLIT] = {sym(g_ca_h), sym(g_sp_h), sym(g_spd_h),
                              sym(g_wq1h), sym(g_wk1h), sym(g_wv1h), sym(g_wo1h),
                              sym(g_wq2h), sym(g_wk2h), sym(g_wv2h), sym(g_wo2h),
                              sym(g_fw1h), sym(g_fw2h)};
        void* dstl[NSPLIT] = {sym(g_ca_l), sym(g_sp_l), sym(g_spd_l),
                              sym(g_ca_l), sym(g_ca_l), sym(g_ca_l), sym(g_ca_l),
                              sym(g_ca_l), sym(g_ca_l), sym(g_ca_l), sym(g_ca_l),
                              sym(g_ca_l), sym(g_ca_l)};   // unused when wlo=0
        const int nelts[NSPLIT] = {MQ_*D_, MKV1_*D_, MQ_*D_,
                                   D_*D_, D_*D_, D_*D_, D_*D_,
                                   D_*D_, D_*D_, D_*D_, D_*D_,
                                   DF_*D_, DF_*D_};
        const int kshs[NSPLIT] = {9,9,9, 9,9,9,9, 9,9,9,9, 9,11};
        const int wlos[NSPLIT] = {1,1,1, 0,0,0,0, 0,0,0,0, 0,0};
        int acc = 0;
        for (int j = 0; j < NSPLIT; j++) {
            jb.s[j] = (const float4*)srcs[j];
            jb.h[j] = (char*)dsth[j];
            jb.l[j] = (char*)dstl[j];
            acc += nelts[j] / 1024;
            jb.end[j] = acc;
            jb.ksh[j] = kshs[j];
            jb.wlo[j] = wlos[j];
        }
        split_batch<<<acc, 256>>>(jb);

        __half* qh = (__half*)sym(g_q_h), *ql = (__half*)sym(g_q_l);
        __half* kh = (__half*)sym(g_k_h);
        __half* vv = (__half*)sym(g_v);
        __half* k2h = (__half*)sym(g_k2h);
        __half* v2 = (__half*)sym(g_v2);
        __half* ath = (__half*)sym(g_at_h), *atl = (__half*)sym(g_at_l);
        __half* x1h = (__half*)sym(g_x1h), *x1l = (__half*)sym(g_x1l);
        __half* x2h = (__half*)sym(g_x2h), *x2l = (__half*)sym(g_x2l);
        __half* hh = (__half*)sym(g_h_h), *hl = (__half*)sym(g_h_l);

        // ---- Fork: q1 on 0; k1/v1 on s1/s2; k2/v2 on s3 ----
        if (multi) {
            cudaEventRecord(evF, 0);
            cudaStreamWaitEvent(s1, evF, 0);
            cudaStreamWaitEvent(s2, evF, 0);
            cudaStreamWaitEvent(s3, evF, 0);
        }
        tc_gemm<3><<<gProj, 256, GT_SMEM_BYTES, 0 >>>(qh, ql, (__half*)sym(g_ca_h), (__half*)sym(g_ca_l), (__half*)sym(g_wq1h), nullptr, nullptr, MQ_, D_, D_);
        tc_gemm<5><<<gKV1,  256, GT_SMEM_BYTES, t1>>>(kh, nullptr, (__half*)sym(g_sp_h), (__half*)sym(g_sp_l), (__half*)sym(g_wk1h), nullptr, nullptr, MKV1_, D_, D_);
        tc_gemm<4><<<gKV1,  256, GT_SMEM_BYTES, t2>>>(vv, nullptr, (__half*)sym(g_sp_h), (__half*)sym(g_sp_l), (__half*)sym(g_wv1h), nullptr, nullptr, MKV1_, D_, D_);
        tc_gemm<5><<<gProj, 256, GT_SMEM_BYTES, t3>>>(k2h, nullptr, (__half*)sym(g_spd_h), (__half*)sym(g_spd_l), (__half*)sym(g_wk2h), nullptr, nullptr, MQ_, D_, D_);
        tc_gemm<4><<<gProj, 256, GT_SMEM_BYTES, t3>>>(v2, nullptr, (__half*)sym(g_spd_h), (__half*)sym(g_spd_l), (__half*)sym(g_wv2h), nullptr, nullptr, MQ_, D_, D_);
        if (multi) {
            cudaEventRecord(ev1, s1);
            cudaEventRecord(ev2, s2);
            cudaEventRecord(ev3, s3);
            cudaStreamWaitEvent(0, ev1, 0);
            cudaStreamWaitEvent(0, ev2, 0);
        }

        // ---- Stage 1 tail ----
        tc_flash<1><<<gFA, 256, TF_SMEM_BYTES>>>(ath, atl, qh, ql, kh, vv, SKV1_);
        tc_gemm<1><<<gProj, 256, GT_SMEM_BYTES>>>(tmp, nullptr, ath, atl, (__half*)sym(g_wo1h), bo1, cords, MQ_, D_, D_);
        layernorm_kernel<1><<<lnBlocks, 256>>>(x1, x1h, x1l, tmp, ln1_g, ln1_b, MQ_);

        // ---- Stage 2 ----
        tc_gemm<3><<<gProj, 256, GT_SMEM_BYTES>>>(qh, ql, x1h, x1l, (__half*)sym(g_wq2h), nullptr, nullptr, MQ_, D_, D_);
        if (multi) cudaStreamWaitEvent(0, ev3, 0);
        tc_flash<2><<<gFA, 256, TF_SMEM_BYTES>>>(ath, atl, qh, ql, k2h, v2, SQ_);
        tc_gemm<1><<<gProj, 256, GT_SMEM_BYTES>>>(tmp, nullptr, ath, atl, (__half*)sym(g_wo2h), bo2, x1, MQ_, D_, D_);
        layernorm_kernel<1><<<lnBlocks, 256>>>(x2, x2h, x2l, tmp, ln2_g, ln2_b, MQ_);

        // ---- Stage 3: FFN ----
        tc_gemm<2><<<gFFN1, 256, GT_SMEM_BYTES>>>(hh, hl, x2h, x2l, (__half*)sym(g_fw1h), ffn_b1, nullptr, MQ_, DF_, D_);
        tc_gemm<1><<<gProj, 256, GT_SMEM_BYTES>>>(tmp, nullptr, hh, hl, (__half*)sym(g_fw2h), ffn_b2, x2, MQ_, D_, DF_);
        layernorm_kernel<0><<<lnBlocks, 256>>>(out, nullptr, nullptr, tmp, ln3_g, ln3_b, MQ_);
    } else {
        // -------- full SIMT fallback (round-1 proven path) --------
        cudaFuncSetAttribute((const void*)flash_kernel<1>, cudaFuncAttributeMaxDynamicSharedMemorySize, FA_SMEM_BYTES);
        cudaFuncSetAttribute((const void*)flash_kernel<2>, cudaFuncAttributeMaxDynamicSharedMemorySize, FA_SMEM_BYTES);
        float* q = (float*)sym(g_fa);
        float* k = (float*)sym(g_fb);
        float* v = (float*)sym(g_fc);
        float* attn = (float*)sym(g_fd);
        float* hbuf = (float*)sym(g_fd);

        sgemm_kernel<0><<<gProj, 256>>>(q, cords,   wq1, nullptr, nullptr, MQ_,   D_, D_);
        sgemm_kernel<0><<<gKV1,  256>>>(k, spatial, wk1, nullptr, nullptr, MKV1_, D_, D_);
        sgemm_kernel<0><<<gKV1,  256>>>(v, spatial, wv1, nullptr, nullptr, MKV1_, D_, D_);
        flash_kernel<1><<<gFA, 256, FA_SMEM_BYTES>>>(attn, q, k, v, SKV1_);
        sgemm_kernel<1><<<gProj, 256>>>(tmp, attn, wo1, bo1, cords, MQ_, D_, D_);
        layernorm_kernel<0><<<lnBlocks, 256>>>(x1, nullptr, nullptr, tmp, ln1_g, ln1_b, MQ_);

        sgemm_kernel<0><<<gProj, 256>>>(q, x1,    wq2, nullptr, nullptr, MQ_, D_, D_);
        sgemm_kernel<0><<<gProj, 256>>>(k, speed, wk2, nullptr, nullptr, MQ_, D_, D_);
        sgemm_kernel<0><<<gProj, 256>>>(v, speed, wv2, nullptr, nullptr, MQ_, D_, D_);
        flash_kernel<2><<<gFA, 256, FA_SMEM_BYTES>>>(attn, q, k, v, SQ_);
        sgemm_kernel<1><<<gProj, 256>>>(tmp, attn, wo2, bo2, x1, MQ_, D_, D_);
        layernorm_kernel<0><<<lnBlocks, 256>>>(x2, nullptr, nullptr, tmp, ln2_g, ln2_b, MQ_);

        sgemm_kernel<2><<<gFFN1, 256>>>(hbuf, x2, ffn_w1, ffn_b1, nullptr, MQ_, DF_, D_);
        sgemm_kernel<1><<<gProj, 256>>>(tmp, hbuf, ffn_w2, ffn_b2, x2, MQ_, D_, DF_);
        layernorm_kernel<0><<<lnBlocks, 256>>>(out, nullptr, nullptr, tmp, ln3_g, ln3_b, MQ_);
    }
}

// round 14
// speedup vs baseline: 1.6247x; 1.2705x over previous
#include <cuda_runtime.h>
#include <cuda_fp16.h>
#include <math.h>
#include <cstdint>

// ============================================================
// Problem constants
// ============================================================
#define B_      8
#define SQ_     768
#define SKV1_   1024
#define D_      512
#define DF_     2048
#define H_      8
#define DH_     64
#define MQ_     (B_*SQ_)      // 6144
#define MKV1_   (B_*SKV1_)    // 8192

#if defined(__CUDA_ARCH__) && (defined(__CUDA_ARCH_FEAT_SM103_ALL) || \
                               defined(__CUDA_ARCH_FEAT_SM100_ALL) || \
                               (defined(__CUDA_ARCH_SPECIFIC__) && \
                                (__CUDA_ARCH_SPECIFIC__ == 1030 || __CUDA_ARCH_SPECIFIC__ == 1000)))
#define HAS_TCGEN05 1
#else
#define HAS_TCGEN05 0
#endif

// ------------------------------------------------------------
// Scratch (device globals; 16B+ alignment for cp.async.bulk)
// PLAIN F16 operands, TILED layout: 8KB SW64-swizzled blocks.
// V stored PRE-TRANSPOSED (8KB SW128 panels).
// ------------------------------------------------------------
__device__ __align__(256) __half g_ca_h [MQ_  * D_];
__device__ __align__(256) __half g_sp_h [MKV1_* D_];
__device__ __align__(256) __half g_spd_h[MQ_  * D_];
__device__ __align__(256) __half g_wq1h[D_*D_];
__device__ __align__(256) __half g_wk1h[D_*D_];
__device__ __align__(256) __half g_wv1h[D_*D_];
__device__ __align__(256) __half g_wo1h[D_*D_];
__device__ __align__(256) __half g_wq2h[D_*D_];
__device__ __align__(256) __half g_wk2h[D_*D_];
__device__ __align__(256) __half g_wv2h[D_*D_];
__device__ __align__(256) __half g_wo2h[D_*D_];
__device__ __align__(256) __half g_fw1h[DF_*D_];
__device__ __align__(256) __half g_fw2h[DF_*D_];
__device__ __align__(256) __half g_q_h [MQ_  * D_];
__device__ __align__(256) __half g_k_h [MKV1_* D_];
__device__ __align__(256) __half g_v   [MKV1_* D_];   // vT panels
__device__ __align__(256) __half g_k2h [MQ_  * D_];
__device__ __align__(256) __half g_v2  [MQ_  * D_];   // vT panels
__device__ __align__(256) __half g_at_h[MQ_  * D_];
__device__ __align__(256) __half g_x1h [MQ_  * D_];
__device__ __align__(256) __half g_x2h [MQ_  * D_];
__device__ __align__(256) __half g_h_h [MQ_  * DF_];
__device__ float g_tmp[MQ_ * D_];
__device__ float g_x1 [MQ_ * D_];
__device__ float g_x2 [MQ_ * D_];
// fp32 fallback scratch (SIMT path)
__device__ float g_fa[MKV1_*D_];
__device__ float g_fb[MKV1_*D_];
__device__ float g_fc[MKV1_*D_];
__device__ float g_fd[MQ_*DF_];

// ============================================================
// Common helpers
// ============================================================
__device__ __forceinline__ float gelu_exact(float x) {
    return 0.5f * x * (1.0f + erff(x * 0.70710678118654752f));
}
__device__ __forceinline__ uint32_t pack2(__half a, __half b) {
    __half2 t = __halves2half2(a, b);
    return *(const uint32_t*)&t;
}
// Tiled layout: byte offset of (row, kcol) in [rows x K] f16 tensor
// stored as 8KB SW64-swizzled panel blocks.
__device__ __forceinline__ size_t tiled_off(int row, int kcol, int K) {
    size_t blk = (size_t)(row >> 7) * (K >> 5) + (kcol >> 5);
    uint32_t ib = (uint32_t)((row & 127) * 64 + (kcol & 31) * 2);
    ib ^= (ib >> 3) & 0x30;      // SW64 swizzle
    return blk * 8192 + ib;
}
#define SWZ128(x) ((x) ^ (((x) >> 3) & 0x70))
// vT layout: 8KB SW128 panel per (64-row kv panel, head).
__device__ __forceinline__ size_t vt_off(int row, int col) {
    size_t blk = (size_t)(row >> 6) * 8 + (col >> 6);
    uint32_t ib = SWZ128((uint32_t)((col & 63) * 128 + (row & 63) * 2));
    return blk * 8192 + ib;
}

// ============================================================
// Batched f16-round kernel (13 jobs) -> TILED hi-only outputs
// ============================================================
#define NSPLIT 13
struct SplitJobs {
    const float4* s[NSPLIT];
    char* h[NSPLIT];
    int end[NSPLIT];
    int ksh[NSPLIT];   // log2(K)
};

__global__ __launch_bounds__(256)
void split_batch(SplitJobs jb)
{
    const int blk = blockIdx.x;
    int j = 0;
    #pragma unroll
    for (int t = 0; t < NSPLIT; t++) if (blk >= jb.end[t]) j = t + 1;
    const int b0 = (j == 0) ? 0 : jb.end[j - 1];
    const int idx = (blk - b0) * 256 + threadIdx.x;
    float4 x = jb.s[j][idx];
    const int ksh = jb.ksh[j];
    const int e0 = idx * 4;
    const int row = e0 >> ksh;
    const int kcol = e0 & ((1 << ksh) - 1);
    const size_t off = tiled_off(row, kcol, 1 << ksh);
    *(uint2*)(jb.h[j] + off) =
        make_uint2(pack2(__float2half_rn(x.x), __float2half_rn(x.y)),
                   pack2(__float2half_rn(x.z), __float2half_rn(x.w)));
}

#if HAS_TCGEN05
// ------------------------------------------------------------
// PTX helpers (sm_103a pass only)
// ------------------------------------------------------------
__device__ __forceinline__ uint32_t smem_u32(const void* smem_ptr) {
    uint32_t addr;
    asm("{ .reg .u64 tmp; cvta.to.shared.u64 tmp, %1; cvt.u32.u64 %0, tmp; }"
        : "=r"(addr) : "l"(smem_ptr));
    return addr;
}

#define MBARRIER_INIT(mbar, count) \
    asm volatile("mbarrier.init.shared.b64 [%0], %1;" \
        :: "r"((uint32_t)(mbar)), "r"((uint32_t)(count)) : "memory")

#define MBARRIER_EXPECT_TX(mbar, bytes) \
    asm volatile("mbarrier.arrive.expect_tx.shared.b64 _, [%0], %1;" \
        :: "r"((uint32_t)(mbar)), "r"((uint32_t)(bytes)) : "memory")

#define CP_BULK_G2S(dst, src, bytes, mbar) \
    asm volatile("cp.async.bulk.shared::cluster.global.mbarrier::complete_tx::bytes [%0], [%1], %2, [%3];" \
        :: "r"((uint32_t)(dst)), "l"(src), "r"((uint32_t)(bytes)), "r"((uint32_t)(mbar)) : "memory")

#define MBARRIER_WAIT_PARITY(mbar_smem_addr, phase_parity) do { \
    uint32_t _mbar = (uint32_t)(mbar_smem_addr); \
    uint32_t _parity = (uint32_t)(phase_parity); \
    uint32_t _done; \
    asm volatile( \
        "{\n\t" \
        ".reg .pred p;\n\t" \
        "mbarrier.try_wait.parity.acquire.cta.shared::cta.b64 p, [%1], %2;\n\t" \
        "selp.b32 %0, 1, 0, p;\n\t" \
        "}" \
        : "=r"(_done) : "r"(_mbar), "r"(_parity) : "memory"); \
    if (!_done) { \
        asm volatile( \
            "{\n\t" \
            ".reg .pred P1;\n\t" \
            "WAIT_LOOP_%=:\n\t" \
            "mbarrier.try_wait.parity.acquire.cta.shared::cta.b64 P1, [%0], %1, 0x989680;\n\t" \
            "@P1 bra.uni WAIT_DONE_%=;\n\t" \
            "bra.uni WAIT_LOOP_%=;\n\t" \
            "WAIT_DONE_%=:\n\t" \
            "}" \
            :: "r"(_mbar), "r"(_parity) : "memory"); \
    } \
} while(0)

#define TCGEN05_ALLOC(smem_result_addr, nCols) \
    asm volatile("tcgen05.alloc.cta_group::1.sync.aligned.shared::cta.b32 [%0], %1;" \
        :: "r"((uint32_t)(smem_result_addr)), "r"((uint32_t)(nCols)) : "memory")
#define TCGEN05_DEALLOC(tmem_addr, nCols) \
    asm volatile("tcgen05.dealloc.cta_group::1.sync.aligned.b32 %0, %1;" \
        :: "r"(tmem_addr), "r"(nCols))
#define TCGEN05_RELINQUISH() \
    asm volatile("tcgen05.relinquish_alloc_permit.cta_group::1.sync.aligned;")
#define TCGEN05_COMMIT(mbar_smem_addr) \
    asm volatile("tcgen05.commit.cta_group::1.mbarrier::arrive::one.shared::cluster.b64 [%0];" \
        :: "r"((uint32_t)(mbar_smem_addr)) : "memory")
#define TCGEN05_FENCE_AFTER() \
    asm volatile("tcgen05.fence::after_thread_sync;" ::: "memory")
#define TCGEN05_FENCE_BEFORE() \
    asm volatile("tcgen05.fence::before_thread_sync;" ::: "memory")
#define TCGEN05_WAIT_LD() \
    asm volatile("tcgen05.wait::ld.sync.aligned;" ::: "memory")
#define FENCE_PROXY_ASYNC_SHARED_CTA() \
    asm volatile("fence.proxy.async.shared::cta;" ::: "memory")

#define TCGEN05_LD_32X32B_X32(r, tmem_addr) \
    asm volatile( \
        "tcgen05.ld.sync.aligned.32x32b.x32.b32 " \
        "{%0, %1, %2, %3, %4, %5, %6, %7, " \
        " %8, %9, %10, %11, %12, %13, %14, %15, " \
        " %16, %17, %18, %19, %20, %21, %22, %23, " \
        " %24, %25, %26, %27, %28, %29, %30, %31}, [%32];" \
        : "=r"((r)[0]),  "=r"((r)[1]),  "=r"((r)[2]),  "=r"((r)[3]), \
          "=r"((r)[4]),  "=r"((r)[5]),  "=r"((r)[6]),  "=r"((r)[7]), \
          "=r"((r)[8]),  "=r"((r)[9]),  "=r"((r)[10]), "=r"((r)[11]), \
          "=r"((r)[12]), "=r"((r)[13]), "=r"((r)[14]), "=r"((r)[15]), \
          "=r"((r)[16]), "=r"((r)[17]), "=r"((r)[18]), "=r"((r)[19]), \
          "=r"((r)[20]), "=r"((r)[21]), "=r"((r)[22]), "=r"((r)[23]), \
          "=r"((r)[24]), "=r"((r)[25]), "=r"((r)[26]), "=r"((r)[27]), \
          "=r"((r)[28]), "=r"((r)[29]), "=r"((r)[30]), "=r"((r)[31]) \
        : "r"(tmem_addr))

#define SMEM_DESC_BASE_SW128 \
    ((uint64_t(2)  << 61) | (uint64_t(1) << 46) | \
     (uint64_t(64) << 32) | (uint64_t(1) << 16))
#define MAKE_SMEM_DESC(base_addr) \
    (SMEM_DESC_BASE_SW128 | ((uint64_t)((base_addr) >> 4) & 0x3FFF))
#define SMEM_DESC_BASE_SW64 \
    ((uint64_t(4)  << 61) | (uint64_t(1) << 46) | \
     (uint64_t(32) << 32) | (uint64_t(1) << 16))
#define MAKE_SMEM_DESC_SW64(base_addr) \
    (SMEM_DESC_BASE_SW64 | ((uint64_t)((base_addr) >> 4) & 0x3FFF))

#define SMEM_SWIZZLE_128B(byte_offset) \
    ((byte_offset) ^ (((byte_offset) >> 3) & 0x70))

__device__ __forceinline__ void tcgen05_mma_f16_ss(
    uint32_t d_tmem, uint64_t a_desc, uint64_t b_desc,
    uint32_t idesc, uint32_t enable)
{
    asm volatile(
        "{\n\t"
        ".reg .pred p;\n\t"
        "setp.ne.u32 p, %6, 0;\n\t"
        "tcgen05.mma.cta_group::1.kind::f16 [%0], %1, %2, %3, "
        "{%4, %4, %4, %4}, p;\n\t"
        "}"
        :: "r"(d_tmem), "l"(a_desc), "l"(b_desc), "r"(idesc),
           "r"(0u), "r"(0u), "r"(enable)
        : "memory");
}

#define IDESC_G  0x8200010u   // M=128, N=128
#define IDESC_PV 0x8100010u   // M=128, N=64
#endif  // HAS_TCGEN05

// ============================================================
// tcgen05 PLAIN F16 GEMM: C = Ah @ Wh^T (+ epilogue)
//   TILED inputs, bulk-copy, BK=32, 3 stages of 16KB -> 49KB,
//   occ 3, 2 MMA dispatches per iter.
//   EPI: 1 +bias+res f32 | 2 gelu(+bias)->tiled f16 |
//        3 tiled f16 | 4 -> vT panels
// ============================================================
#define GT_TILE(buf, which) (1024 + (buf) * 16384 + (which) * 8192)
#define GT_SMEM_BYTES (1024 + 3 * 16384)   // 50176 -> 3 CTAs/SM

template<int EPI>
__global__ __launch_bounds__(256, 3)
void tc_gemm(void* __restrict__ Cp,
             const __half* __restrict__ Ah,
             const __half* __restrict__ Wh,
             const float* __restrict__ bias, const float* __restrict__ res,
             int M, int N, int K)
{
#if HAS_TCGEN05
    extern __shared__ __align__(1024) char gsm[];
    const uint32_t sb = smem_u32(gsm);
    const int tid  = threadIdx.x;
    const int wid  = tid >> 5;
    const int lane = tid & 31;

    if (tid == 0) {
        MBARRIER_INIT(sb + 8, 1);   // mma buf0
        MBARRIER_INIT(sb + 16, 1);  // mma buf1
        MBARRIER_INIT(sb + 24, 1);  // mma buf2
        MBARRIER_INIT(sb + 32, 1);  // load buf0
        MBARRIER_INIT(sb + 40, 1);  // load buf1
        MBARRIER_INIT(sb + 48, 1);  // load buf2
        FENCE_PROXY_ASYNC_SHARED_CTA();
    }
    if (wid == 0) {
        TCGEN05_ALLOC(sb + 0, 128);
        TCGEN05_RELINQUISH();
    }
    __syncthreads();
    uint32_t tmem;
    asm volatile("ld.shared.b32 %0, [%1];" : "=r"(tmem) : "r"(sb + 0));

    const int iters = K >> 5;
    const int kb = K >> 5;

    if (tid == 0) {
        const char* Ahc = (const char*)Ah + (size_t)(blockIdx.y) * kb * 8192;
        const char* Whc = (const char*)Wh + (size_t)(blockIdx.x) * kb * 8192;

        #pragma unroll
        for (int s = 0; s < 2; s++) {
            MBARRIER_EXPECT_TX(sb + 32 + s * 8, 16384);
            CP_BULK_G2S(sb + GT_TILE(s, 0), Ahc + (size_t)s * 8192, 8192, sb + 32 + s * 8);
            CP_BULK_G2S(sb + GT_TILE(s, 1), Whc + (size_t)s * 8192, 8192, sb + 32 + s * 8);
        }

        for (int i = 0; i < iters; i++) {
            const int b = i % 3;
            MBARRIER_WAIT_PARITY(sb + 32 + b * 8, (i / 3) & 1);

            const uint64_t dAh = MAKE_SMEM_DESC_SW64(sb + GT_TILE(b, 0));
            const uint64_t dBh = MAKE_SMEM_DESC_SW64(sb + GT_TILE(b, 1));
            #pragma unroll
            for (int kk = 0; kk < 2; kk++) {
                const uint64_t o = kk * 2;
                tcgen05_mma_f16_ss(tmem, dAh + o, dBh + o, IDESC_G,
                                   (i > 0 || kk > 0) ? 1u : 0u);
            }
            TCGEN05_COMMIT(sb + 8 + b * 8);

            const int j2 = i + 2;
            if (j2 < iters) {
                const int b2 = j2 % 3;
                if (i >= 1)
                    MBARRIER_WAIT_PARITY(sb + 8 + ((i - 1) % 3) * 8,
                                         ((i - 1) / 3) & 1);
                MBARRIER_EXPECT_TX(sb + 32 + b2 * 8, 16384);
                CP_BULK_G2S(sb + GT_TILE(b2, 0), Ahc + (size_t)j2 * 8192, 8192, sb + 32 + b2 * 8);
                CP_BULK_G2S(sb + GT_TILE(b2, 1), Whc + (size_t)j2 * 8192, 8192, sb + 32 + b2 * 8);
            }
        }
    }

    __syncthreads();
    MBARRIER_WAIT_PARITY(sb + 8 + ((iters - 1) % 3) * 8, ((iters - 1) / 3) & 1);
    TCGEN05_FENCE_AFTER();

    // Epilogue
    {
        const int bm = blockIdx.y * 128;
        const int bn = blockIdx.x * 128;
        const int sub = wid & 3;
        const int h2  = wid >> 2;
        const int row = bm + sub * 32 + lane;
        #pragma unroll
        for (int q = 0; q < 2; q++) {
            uint32_t r[32];
            TCGEN05_LD_32X32B_X32(r, tmem + h2 * 64 + q * 32);
            TCGEN05_WAIT_LD();
            #pragma unroll
            for (int c4 = 0; c4 < 8; c4++) {
                const int col = bn + h2 * 64 + q * 32 + c4 * 4;
                float4 v;
                v.x = __uint_as_float(r[c4 * 4 + 0]);
                v.y = __uint_as_float(r[c4 * 4 + 1]);
                v.z = __uint_as_float(r[c4 * 4 + 2]);
                v.w = __uint_as_float(r[c4 * 4 + 3]);
                if (EPI == 1 || EPI == 2) {
                    float4 bi = *(const float4*)&bias[col];
                    v.x += bi.x; v.y += bi.y; v.z += bi.z; v.w += bi.w;
                }
                if (EPI == 1) {
                    float4 rv = *(const float4*)&res[(size_t)row * N + col];
                    v.x += rv.x; v.y += rv.y; v.z += rv.z; v.w += rv.w;
                    *(float4*)((float*)Cp + (size_t)row * N + col) = v;
                }
                if (EPI == 2) {
                    v.x = gelu_exact(v.x); v.y = gelu_exact(v.y);
                    v.z = gelu_exact(v.z); v.w = gelu_exact(v.w);
                }
                if (EPI == 2 || EPI == 3) {   // tiled f16
                    const size_t off = tiled_off(row, col, N);
                    *(uint2*)((char*)Cp + off) =
                        make_uint2(pack2(__float2half_rn(v.x), __float2half_rn(v.y)),
                                   pack2(__float2half_rn(v.z), __float2half_rn(v.w)));
                }
                if (EPI == 4) {   // pre-transposed vT panels (f16 round)
                    char* base = (char*)Cp;
                    *(__half*)(base + vt_off(row, col + 0)) = __float2half_rn(v.x);
                    *(__half*)(base + vt_off(row, col + 1)) = __float2half_rn(v.y);
                    *(__half*)(base + vt_off(row, col + 2)) = __float2half_rn(v.z);
                    *(__half*)(base + vt_off(row, col + 3)) = __float2half_rn(v.w);
                }
            }
        }
    }

    __syncthreads();
    if (wid == 0) TCGEN05_DEALLOC(tmem, 128);
#endif
}

// ============================================================
// tcgen05 f16 flash attention: plain-f16 S = Qh@Kh^T.
//   Q/K TILED bulk hi-only, V^T pre-transposed bulk.
//   smem 81KB, occ 2 (TMEM-capped).
// ============================================================
#define TF_QH    1024
#define TF_KH    (TF_QH + 16384)
#define TF_VT    (TF_QH + 32768)   // 2 panels x 8 KB (SW128)
#define TF_P     (TF_QH + 49152)   // 2 panels x 16 KB (SW128)
#define TF_SMEM_BYTES (TF_P + 32768)  // 82944

template<int MASK>
__global__ __launch_bounds__(256, 2)
void tc_flash(__half* __restrict__ Oh,
              const __half* __restrict__ Qh,
              const __half* __restrict__ Kh,
              const __half* __restrict__ Vp, int kvlen)
{
#if HAS_TCGEN05
    extern __shared__ __align__(1024) char fsm[];
    const uint32_t sb = smem_u32(fsm);
    const int tid  = threadIdx.x;
    const int wid  = tid >> 5;
    const int lane = tid & 31;
    const int sub  = wid & 3;
    const int h2   = wid >> 2;
    const int q0   = blockIdx.x * 128;
    const int h    = blockIdx.y;
    const int b    = blockIdx.z;

    if (tid == 0) {
        MBARRIER_INIT(sb + 8, 1);    // S done
        MBARRIER_INIT(sb + 16, 1);   // PV done
        MBARRIER_INIT(sb + 24, 1);   // Q loaded
        MBARRIER_INIT(sb + 32, 1);   // K loaded
        MBARRIER_INIT(sb + 48, 1);   // V loaded
        FENCE_PROXY_ASYNC_SHARED_CTA();
    }
    if (wid == 0) {
        TCGEN05_ALLOC(sb + 0, 256);
        TCGEN05_RELINQUISH();
    }
    __syncthreads();
    uint32_t tmem;
    asm volatile("ld.shared.b32 %0, [%1];" : "=r"(tmem) : "r"(sb + 0));

    const size_t qblk = ((size_t)((b * SQ_ + q0) >> 7) * 16 + 2 * h) * 8192;
    if (tid == 0) {
        MBARRIER_EXPECT_TX(sb + 24, 16384);
        CP_BULK_G2S(sb + TF_QH, (const char*)Qh + qblk, 16384, sb + 24);
        const size_t kblk = ((size_t)((b * kvlen) >> 7) * 16 + 2 * h) * 8192;
        MBARRIER_EXPECT_TX(sb + 32, 16384);
        CP_BULK_G2S(sb + TF_KH, (const char*)Kh + kblk, 16384, sb + 32);
    }

    float lsum = 0.f;
    const int qrow = sub * 32 + lane;
    const int qg   = q0 + qrow;

    const int ntiles = kvlen >> 7;
    for (int t = 0; t < ntiles; t++) {
        const int kv0 = t << 7;

        // ---- S = Qh @ Kh^T (SW64 tiles, 4 dispatches) ----
        if (tid == 0) {
            if (t == 0) MBARRIER_WAIT_PARITY(sb + 24, 0);
            MBARRIER_WAIT_PARITY(sb + 32, t & 1);
            #pragma unroll
            for (int blk = 0; blk < 2; blk++) {
                const uint64_t dQh = MAKE_SMEM_DESC_SW64(sb + TF_QH + blk * 8192);
                const uint64_t dKh = MAKE_SMEM_DESC_SW64(sb + TF_KH + blk * 8192);
                #pragma unroll
                for (int kk = 0; kk < 2; kk++) {
                    const uint64_t o = kk * 2;
                    tcgen05_mma_f16_ss(tmem + 64, dQh + o, dKh + o, IDESC_G,
                                       (blk == 0 && kk == 0) ? 0u : 1u);
                }
            }
            TCGEN05_COMMIT(sb + 8);
        }

        // ---- PV(t-1) drain frees VT/P, then bulk-load V(t) ----
        if (t > 0) {
            MBARRIER_WAIT_PARITY(sb + 16, (t - 1) & 1);
        }
        if (tid == 0) {
            const size_t vblk = ((size_t)((b * kvlen + kv0) >> 6) * 8 + h) * 8192;
            MBARRIER_EXPECT_TX(sb + 48, 16384);
            CP_BULK_G2S(sb + TF_VT,        (const char*)Vp + vblk,             8192, sb + 48);
            CP_BULK_G2S(sb + TF_VT + 8192, (const char*)Vp + vblk + 8 * 8192,  8192, sb + 48);
        }

        // ---- Wait S (all); prefetch next K (tid0) ----
        MBARRIER_WAIT_PARITY(sb + 8, t & 1);
        TCGEN05_FENCE_AFTER();
        if (tid == 0 && t + 1 < ntiles) {
            const size_t kblk = ((size_t)((b * kvlen + kv0 + 128) >> 7) * 16 + 2 * h) * 8192;
            MBARRIER_EXPECT_TX(sb + 32, 16384);
            CP_BULK_G2S(sb + TF_KH, (const char*)Kh + kblk, 16384, sb + 32);
        }

        // ---- softmax (unnormalized) -> f16 P (SW128) ----
        #pragma unroll
        for (int chunk = 0; chunk < 2; chunk++) {
            uint32_t r[32];
            TCGEN05_LD_32X32B_X32(r, tmem + 64 + h2 * 64 + chunk * 32);
            TCGEN05_WAIT_LD();
            const int kvb = h2 * 64 + chunk * 32;
            char* Pp = fsm + TF_P + h2 * 16384;
            #pragma unroll
            for (int c16 = 0; c16 < 4; c16++) {
                uint32_t w[4];
                #pragma unroll
                for (int pr = 0; pr < 4; pr++) {
                    __half hs[2];
                    #pragma unroll
                    for (int j = 0; j < 2; j++) {
                        const float s = __uint_as_float(r[c16 * 8 + pr * 2 + j]);
                        const int kg = kv0 + kvb + c16 * 8 + pr * 2 + j;
                        float wm;
                        if (MASK == 1) wm = ((qg < 512) == (kg < 512)) ? 1.25f : 1.0f;
                        else           wm = ((qg >> 8)  == (kg >> 8))  ? 1.25f : 1.0f;
                        const float p = __expf(s * (0.125f * wm));
                        hs[j] = __float2half_rn(p);
                        lsum += __half2float(hs[j]);
                    }
                    w[pr] = pack2(hs[0], hs[1]);
                }
                const uint32_t sw = SMEM_SWIZZLE_128B(
                    (uint32_t)(qrow * 128 + chunk * 64 + c16 * 16));
                *(uint4*)(Pp + sw) = make_uint4(w[0], w[1], w[2], w[3]);
            }
        }
        TCGEN05_FENCE_BEFORE();
        __syncthreads();

        // ---- O += P @ V^T (SW128, 8 dispatches) ----
        if (tid == 0) {
            FENCE_PROXY_ASYNC_SHARED_CTA();
            MBARRIER_WAIT_PARITY(sb + 48, t & 1);   // V(t) landed
            #pragma unroll
            for (int p2 = 0; p2 < 2; p2++) {
                const uint64_t dP = MAKE_SMEM_DESC(sb + TF_P  + p2 * 16384);
                const uint64_t dV = MAKE_SMEM_DESC(sb + TF_VT + p2 * 8192);
                #pragma unroll
                for (int kk = 0; kk < 4; kk++) {
                    const uint64_t o = kk * 2;
                    tcgen05_mma_f16_ss(tmem, dP + o, dV + o, IDESC_PV,
                                       (t == 0 && p2 == 0 && kk == 0) ? 0u : 1u);
                }
            }
            TCGEN05_COMMIT(sb + 16);
        }
    }

    MBARRIER_WAIT_PARITY(sb + 16, (ntiles - 1) & 1);
    TCGEN05_FENCE_AFTER();

    // combine row sums across column-half warpgroups
    {
        float* lx = (float*)(fsm + TF_VT);
        lx[wid * 32 + lane] = lsum;
    }
    __syncthreads();
    const float lother = ((float*)(fsm + TF_VT))[(wid ^ 4) * 32 + lane];
    const float inv = 1.0f / (lsum + lother);

    // O epilogue: tiled f16 (feeds wo GEMM)
    {
        uint32_t r[32];
        TCGEN05_LD_32X32B_X32(r, tmem + h2 * 32);
        TCGEN05_WAIT_LD();
        const int orow = b * SQ_ + qg;
        #pragma unroll
        for (int c4 = 0; c4 < 8; c4++) {
            const size_t off = tiled_off(orow, h * DH_ + h2 * 32 + c4 * 4, D_);
            *(uint2*)((char*)Oh + off) = make_uint2(
                pack2(__float2half_rn(__uint_as_float(r[c4*4+0]) * inv),
                      __float2half_rn(__uint_as_float(r[c4*4+1]) * inv)),
                pack2(__float2half_rn(__uint_as_float(r[c4*4+2]) * inv),
                      __float2half_rn(__uint_as_float(r[c4*4+3]) * inv)));
        }
    }

    __syncthreads();
    if (wid == 0) TCGEN05_DEALLOC(tmem, 256);
#endif  // HAS_TCGEN05
}

// ============================================================
// SIMT SGEMM fallback (round-1 proven, fp32)
// ============================================================
template<int EPI>
__global__ __launch_bounds__(256)
void sgemm_kernel(float* __restrict__ C,
                  const float* __restrict__ A,
                  const float* __restrict__ W,
                  const float* __restrict__ bias,
                  const float* __restrict__ res,
                  int M, int N, int K)
{
    __shared__ float As[8][128];
    __shared__ float Bs[8][128];

    const int tid = threadIdx.x;
    const int bm  = blockIdx.y * 128;
    const int bn  = blockIdx.x * 128;

    const int lr = tid >> 1;
    const int lc = (tid & 1) * 4;
    const float* Aptr = A + (size_t)(bm + lr) * K + lc;
    const float* Wptr = W + (size_t)(bn + lr) * K + lc;

    const int ty = tid >> 4;
    const int tx = tid & 15;

    float acc[8][8];
    #pragma unroll
    for (int i = 0; i < 8; i++)
        #pragma unroll
        for (int j = 0; j < 8; j++) acc[i][j] = 0.f;

    for (int k0 = 0; k0 < K; k0 += 8) {
        float4 a4 = *(const float4*)(Aptr + k0);
        float4 b4 = *(const float4*)(Wptr + k0);
        As[lc + 0][lr] = a4.x; As[lc + 1][lr] = a4.y;
        As[lc + 2][lr] = a4.z; As[lc + 3][lr] = a4.w;
        Bs[lc + 0][lr] = b4.x; Bs[lc + 1][lr] = b4.y;
        Bs[lc + 2][lr] = b4.z; Bs[lc + 3][lr] = b4.w;
        __syncthreads();

        #pragma unroll
        for (int kk = 0; kk < 8; kk++) {
            float ra[8], rb[8];
            *(float4*)(ra)     = *(const float4*)&As[kk][ty * 4];
            *(float4*)(ra + 4) = *(const float4*)&As[kk][ty * 4 + 64];
            *(float4*)(rb)     = *(const float4*)&Bs[kk][tx * 4];
            *(float4*)(rb + 4) = *(const float4*)&Bs[kk][tx * 4 + 64];
            #pragma unroll
            for (int i = 0; i < 8; i++)
                #pragma unroll
                for (int j = 0; j < 8; j++)
                    acc[i][j] += ra[i] * rb[j];
        }
        __syncthreads();
    }

    #pragma unroll
    for (int i = 0; i < 8; i++) {
        const int row = bm + ty * 4 + (i & 3) + (i >> 2) * 64;
        #pragma unroll
        for (int jh = 0; jh < 2; jh++) {
            const int col = bn + tx * 4 + jh * 64;
            float4 v;
            v.x = acc[i][jh * 4 + 0];
            v.y = acc[i][jh * 4 + 1];
            v.z = acc[i][jh * 4 + 2];
            v.w = acc[i][jh * 4 + 3];
            if (EPI >= 1) {
                float4 bi = *(const float4*)&bias[col];
                v.x += bi.x; v.y += bi.y; v.z += bi.z; v.w += bi.w;
            }
            if (EPI == 1) {
                float4 rv = *(const float4*)&res[(size_t)row * N + col];
                v.x += rv.x; v.y += rv.y; v.z += rv.z; v.w += rv.w;
            }
            if (EPI == 2) {
                v.x = gelu_exact(v.x); v.y = gelu_exact(v.y);
                v.z = gelu_exact(v.z); v.w = gelu_exact(v.w);
            }
            *(float4*)&C[(size_t)row * N + col] = v;
        }
    }
}

// ============================================================
// SIMT flash attention fallback (round-1 proven, fp32)
// ============================================================
#define FA_STRIDE 68
#define FA_SMEM_FLOATS ((128 + 64 + 64 + 128) * FA_STRIDE)
#define FA_SMEM_BYTES  (FA_SMEM_FLOATS * 4)

template<int MASK>
__global__ __launch_bounds__(256)
void flash_kernel(float* __restrict__ O,
                  const float* __restrict__ Q,
                  const float* __restrict__ Kp,
                  const float* __restrict__ Vp,
                  int kvlen)
{
    extern __shared__ float fsm2[];
    float* Qs = fsm2;
    float* Ks = Qs + 128 * FA_STRIDE;
    float* Vt = Ks + 64  * FA_STRIDE;
    float* Ps = Vt + 64  * FA_STRIDE;

    const int tid = threadIdx.x;
    const int q0  = blockIdx.x * 128;
    const int h   = blockIdx.y;
    const int b   = blockIdx.z;
    const int rg  = tid >> 4;
    const int cg  = tid & 15;

    {
        const int qrow = tid >> 1;
        const int half = tid & 1;
        const float* qbase = Q + (size_t)(b * SQ_ + q0 + qrow) * D_ + h * DH_;
        #pragma unroll
        for (int i = 0; i < 8; i++) {
            const int f4 = half * 8 + i;
            *(float4*)&Qs[qrow * FA_STRIDE + f4 * 4] = *(const float4*)&qbase[f4 * 4];
        }
    }

    float m_i[8], l_i[8], oacc[8][4];
    #pragma unroll
    for (int u = 0; u < 8; u++) {
        m_i[u] = -1e30f; l_i[u] = 0.f;
        #pragma unroll
        for (int t = 0; t < 4; t++) oacc[u][t] = 0.f;
    }

    const int ntiles = kvlen >> 6;
    for (int t0 = 0; t0 < ntiles; t0++) {
        const int kv0 = t0 * 64;
        __syncthreads();

        {
            const int lrow = tid >> 2;
            const int lq   = tid & 3;
            const float* kbase = Kp + (size_t)(b * kvlen + kv0 + lrow) * D_ + h * DH_;
            const float* vbase = Vp + (size_t)(b * kvlen + kv0 + lrow) * D_ + h * DH_;
            #pragma unroll
            for (int i = 0; i < 4; i++) {
                const int f4 = lq * 4 + i;
                float4 k4 = *(const float4*)&kbase[f4 * 4];
                *(float4*)&Ks[lrow * FA_STRIDE + f4 * 4] = k4;
                float4 v4 = *(const float4*)&vbase[f4 * 4];
                const int d0 = f4 * 4;
                Vt[(d0 + 0) * FA_STRIDE + lrow] = v4.x;
                Vt[(d0 + 1) * FA_STRIDE + lrow] = v4.y;
                Vt[(d0 + 2) * FA_STRIDE + lrow] = v4.z;
                Vt[(d0 + 3) * FA_STRIDE + lrow] = v4.w;
            }
        }
        __syncthreads();

        float sacc[8][4];
        #pragma unroll
        for (int u = 0; u < 8; u++)
            #pragma unroll
            for (int t = 0; t < 4; t++) sacc[u][t] = 0.f;

        #pragma unroll
        for (int d4 = 0; d4 < 16; d4++) {
            float4 qv[8];
            #pragma unroll
            for (int u = 0; u < 8; u++)
                qv[u] = *(const float4*)&Qs[(rg + 16 * u) * FA_STRIDE + d4 * 4];
            #pragma unroll
            for (int t = 0; t < 4; t++) {
                float4 kk = *(const float4*)&Ks[(cg + 16 * t) * FA_STRIDE + d4 * 4];
                #pragma unroll
                for (int u = 0; u < 8; u++)
                    sacc[u][t] += qv[u].x * kk.x + qv[u].y * kk.y
                                + qv[u].z * kk.z + qv[u].w * kk.w;
            }
        }

        #pragma unroll
        for (int u = 0; u < 8; u++) {
            const int qg = q0 + rg + 16 * u;
            #pragma unroll
            for (int t = 0; t < 4; t++) {
                const int kg = kv0 + cg + 16 * t;
                float wm;
                if (MASK == 1) wm = ((qg < 512) == (kg < 512)) ? 1.25f : 1.0f;
                else           wm = ((qg >> 8)  == (kg >> 8))  ? 1.25f : 1.0f;
                sacc[u][t] *= 0.125f * wm;
            }
        }

        #pragma unroll
        for (int u = 0; u < 8; u++) {
            float rmax = fmaxf(fmaxf(sacc[u][0], sacc[u][1]),
                               fmaxf(sacc[u][2], sacc[u][3]));
            #pragma unroll
            for (int off = 8; off >= 1; off >>= 1)
                rmax = fmaxf(rmax, __shfl_xor_sync(0xffffffffu, rmax, off));
            const float mnew  = fmaxf(m_i[u], rmax);
            const float alpha = __expf(m_i[u] - mnew);
            m_i[u] = mnew;
            float rsum = 0.f;
            #pragma unroll
            for (int t = 0; t < 4; t++) {
                const float p = __expf(sacc[u][t] - mnew);
                Ps[(rg + 16 * u) * FA_STRIDE + cg + 16 * t] = p;
                rsum += p;
            }
            #pragma unroll
            for (int off = 8; off >= 1; off >>= 1)
                rsum += __shfl_xor_sync(0xffffffffu, rsum, off);
            l_i[u] = l_i[u] * alpha + rsum;
            #pragma unroll
            for (int t = 0; t < 4; t++) oacc[u][t] *= alpha;
        }
        __syncthreads();

        #pragma unroll
        for (int j4 = 0; j4 < 16; j4++) {
            float4 pv[8];
            #pragma unroll
            for (int u = 0; u < 8; u++)
                pv[u] = *(const float4*)&Ps[(rg + 16 * u) * FA_STRIDE + j4 * 4];
            #pragma unroll
            for (int t = 0; t < 4; t++) {
                float4 vv = *(const float4*)&Vt[(cg + 16 * t) * FA_STRIDE + j4 * 4];
                #pragma unroll
                for (int u = 0; u < 8; u++)
                    oacc[u][t] += pv[u].x * vv.x + pv[u].y * vv.y
                                + pv[u].z * vv.z + pv[u].w * vv.w;
            }
        }
    }

    #pragma unroll
    for (int u = 0; u < 8; u++) {
        const float inv = 1.0f / l_i[u];
        const size_t row = (size_t)(b * SQ_ + q0 + rg + 16 * u);
        #pragma unroll
        for (int t = 0; t < 4; t++)
            O[row * D_ + h * DH_ + cg + 16 * t] = oacc[u][t] * inv;
    }
}

// ============================================================
// LayerNorm over D=512; SPLIT=1 also emits TILED f16 (hi only)
// ============================================================
template<int SPLIT>
__global__ __launch_bounds__(256)
void layernorm_kernel(float* __restrict__ out,
                      __half* __restrict__ oh,
                      const float* __restrict__ in,
                      const float* __restrict__ g, const float* __restrict__ b,
                      int rows)
{
    const int gt   = blockIdx.x * 256 + threadIdx.x;
    const int row  = gt >> 5;
    const int lane = gt & 31;
    if (row >= rows) return;

    const float* x = in + (size_t)row * D_;
    float4 v[4];
    float s = 0.f;
    #pragma unroll
    for (int i = 0; i < 4; i++) {
        v[i] = *(const float4*)&x[(lane + i * 32) * 4];
        s += v[i].x + v[i].y + v[i].z + v[i].w;
    }
    #pragma unroll
    for (int o = 16; o; o >>= 1) s += __shfl_xor_sync(0xffffffffu, s, o);
    const float mean = s * (1.0f / 512.0f);

    float var = 0.f;
    #pragma unroll
    for (int i = 0; i < 4; i++) {
        float dx = v[i].x - mean; var += dx * dx;
        dx = v[i].y - mean; var += dx * dx;
        dx = v[i].z - mean; var += dx * dx;
        dx = v[i].w - mean; var += dx * dx;
    }
    #pragma unroll
    for (int o = 16; o; o >>= 1) var += __shfl_xor_sync(0xffffffffu, var, o);
    const float rstd = rsqrtf(var * (1.0f / 512.0f) + 1e-5f);

    #pragma unroll
    for (int i = 0; i < 4; i++) {
        const int c = (lane + i * 32) * 4;
        float4 gv = *(const float4*)&g[c];
        float4 bv = *(const float4*)&b[c];
        float4 o4;
        o4.x = (v[i].x - mean) * rstd * gv.x + bv.x;
        o4.y = (v[i].y - mean) * rstd * gv.y + bv.y;
        o4.z = (v[i].z - mean) * rstd * gv.z + bv.z;
        o4.w = (v[i].w - mean) * rstd * gv.w + bv.w;
        *(float4*)&out[(size_t)row * D_ + c] = o4;
        if (SPLIT) {
            const size_t off = tiled_off(row, c, D_);
            *(uint2*)((char*)oh + off) =
                make_uint2(pack2(__float2half_rn(o4.x), __float2half_rn(o4.y)),
                           pack2(__float2half_rn(o4.z), __float2half_rn(o4.w)));
        }
    }
}

// ============================================================
// Launch
// ============================================================
static void* sym(const void* symbol) {
    void* p = nullptr;
    cudaGetSymbolAddress(&p, symbol);
    return p;
}

extern "C" void kernel_launch(void* const* d_in, const int* in_sizes, int n_in,
                              void* d_out, int out_size)
{
    const float* cords   = (const float*)d_in[0];
    const float* spatial = (const float*)d_in[1];
    const float* speed   = (const float*)d_in[2];
    const float* wq1 = (const float*)d_in[3];
    const float* wk1 = (const float*)d_in[4];
    const float* wv1 = (const float*)d_in[5];
    const float* wo1 = (const float*)d_in[6];
    const float* bo1 = (const float*)d_in[7];
    const float* wq2 = (const float*)d_in[8];
    const float* wk2 = (const float*)d_in[9];
    const float* wv2 = (const float*)d_in[10];
    const float* wo2 = (const float*)d_in[11];
    const float* bo2 = (const float*)d_in[12];
    const float* ln1_g = (const float*)d_in[13];
    const float* ln1_b = (const float*)d_in[14];
    const float* ln2_g = (const float*)d_in[15];
    const float* ln2_b = (const float*)d_in[16];
    const float* ln3_g = (const float*)d_in[17];
    const float* ln3_b = (const float*)d_in[18];
    const float* ffn_w1 = (const float*)d_in[19];
    const float* ffn_b1 = (const float*)d_in[20];
    const float* ffn_w2 = (const float*)d_in[21];
    const float* ffn_b2 = (const float*)d_in[22];
    float* out = (float*)d_out;

    cudaFuncAttributes fa{};
    bool tc1 = false, tc2 = false;
    if (cudaFuncGetAttributes(&fa, (const void*)tc_gemm<1>) == cudaSuccess)
        tc1 = (fa.numRegs >= 32);
    if (cudaFuncGetAttributes(&fa, (const void*)tc_flash<1>) == cudaSuccess)
        tc2 = (fa.numRegs >= 32);
    const bool use_tc = tc1 && tc2;

    static cudaStream_t s1 = nullptr, s2 = nullptr, s3 = nullptr;
    static cudaEvent_t  evF = nullptr, ev1 = nullptr, ev2 = nullptr, ev3 = nullptr;
    static int sinit = 0;
    if (sinit == 0) {
        bool ok = true;
        ok &= (cudaStreamCreateWithFlags(&s1, cudaStreamNonBlocking) == cudaSuccess);
        ok &= (cudaStreamCreateWithFlags(&s2, cudaStreamNonBlocking) == cudaSuccess);
        ok &= (cudaStreamCreateWithFlags(&s3, cudaStreamNonBlocking) == cudaSuccess);
        ok &= (cudaEventCreateWithFlags(&evF, cudaEventDisableTiming) == cudaSuccess);
        ok &= (cudaEventCreateWithFlags(&ev1, cudaEventDisableTiming) == cudaSuccess);
        ok &= (cudaEventCreateWithFlags(&ev2, cudaEventDisableTiming) == cudaSuccess);
        ok &= (cudaEventCreateWithFlags(&ev3, cudaEventDisableTiming) == cudaSuccess);
        sinit = ok ? 1 : -1;
    }
    const bool multi = (sinit == 1) && use_tc;
    cudaStream_t t1 = multi ? s1 : 0;
    cudaStream_t t2 = multi ? s2 : 0;
    cudaStream_t t3 = multi ? s3 : 0;

    const dim3 gProj(D_ / 128, MQ_ / 128);     // (4, 48)
    const dim3 gKV1 (D_ / 128, MKV1_ / 128);   // (4, 64)
    const dim3 gFFN1(DF_ / 128, MQ_ / 128);    // (16, 48)
    const dim3 gFA  (SQ_ / 128, H_, B_);       // (6, 8, 8)
    const int  lnBlocks = MQ_ * 32 / 256;      // 768

    float* tmp = (float*)sym(g_tmp);
    float* x1  = (float*)sym(g_x1);
    float* x2  = (float*)sym(g_x2);

    if (use_tc) {
        cudaFuncSetAttribute((const void*)tc_gemm<1>, cudaFuncAttributeMaxDynamicSharedMemorySize, GT_SMEM_BYTES);
        cudaFuncSetAttribute((const void*)tc_gemm<2>, cudaFuncAttributeMaxDynamicSharedMemorySize, GT_SMEM_BYTES);
        cudaFuncSetAttribute((const void*)tc_gemm<3>, cudaFuncAttributeMaxDynamicSharedMemorySize, GT_SMEM_BYTES);
        cudaFuncSetAttribute((const void*)tc_gemm<4>, cudaFuncAttributeMaxDynamicSharedMemorySize, GT_SMEM_BYTES);
        cudaFuncSetAttribute((const void*)tc_flash<1>, cudaFuncAttributeMaxDynamicSharedMemorySize, TF_SMEM_BYTES);
        cudaFuncSetAttribute((const void*)tc_flash<2>, cudaFuncAttributeMaxDynamicSharedMemorySize, TF_SMEM_BYTES);

        // ---- round inputs + weights -> tiled f16 (one launch) ----
        SplitJobs jb{};
        const float* srcs[NSPLIT] = {cords, spatial, speed,
                                     wq1, wk1, wv1, wo1, wq2, wk2, wv2, wo2,
                                     ffn_w1, ffn_w2};
        void* dsth[NSPLIT] = {sym(g_ca_h), sym(g_sp_h), sym(g_spd_h),
                              sym(g_wq1h), sym(g_wk1h), sym(g_wv1h), sym(g_wo1h),
                              sym(g_wq2h), sym(g_wk2h), sym(g_wv2h), sym(g_wo2h),
                              sym(g_fw1h), sym(g_fw2h)};
        const int nelts[NSPLIT] = {MQ_*D_, MKV1_*D_, MQ_*D_,
                                   D_*D_, D_*D_, D_*D_, D_*D_,
                                   D_*D_, D_*D_, D_*D_, D_*D_,
                                   DF_*D_, DF_*D_};
        const int kshs[NSPLIT] = {9,9,9, 9,9,9,9, 9,9,9,9, 9,11};
        int acc = 0;
        for (int j = 0; j < NSPLIT; j++) {
            jb.s[j] = (const float4*)srcs[j];
            jb.h[j] = (char*)dsth[j];
            acc += nelts[j] / 1024;
            jb.end[j] = acc;
            jb.ksh[j] = kshs[j];
        }
        split_batch<<<acc, 256>>>(jb);

        __half* qh = (__half*)sym(g_q_h);
        __half* kh = (__half*)sym(g_k_h);
        __half* vv = (__half*)sym(g_v);
        __half* k2h = (__half*)sym(g_k2h);
        __half* v2 = (__half*)sym(g_v2);
        __half* ath = (__half*)sym(g_at_h);
        __half* x1h = (__half*)sym(g_x1h);
        __half* x2h = (__half*)sym(g_x2h);
        __half* hh = (__half*)sym(g_h_h);

        // ---- Fork: q1 on 0; k1/v1 on s1/s2; k2/v2 on s3 ----
        if (multi) {
            cudaEventRecord(evF, 0);
            cudaStreamWaitEvent(s1, evF, 0);
            cudaStreamWaitEvent(s2, evF, 0);
            cudaStreamWaitEvent(s3, evF, 0);
        }
        tc_gemm<3><<<gProj, 256, GT_SMEM_BYTES, 0 >>>(qh, (__half*)sym(g_ca_h), (__half*)sym(g_wq1h), nullptr, nullptr, MQ_, D_, D_);
        tc_gemm<3><<<gKV1,  256, GT_SMEM_BYTES, t1>>>(kh, (__half*)sym(g_sp_h), (__half*)sym(g_wk1h), nullptr, nullptr, MKV1_, D_, D_);
        tc_gemm<4><<<gKV1,  256, GT_SMEM_BYTES, t2>>>(vv, (__half*)sym(g_sp_h), (__half*)sym(g_wv1h), nullptr, nullptr, MKV1_, D_, D_);
        tc_gemm<3><<<gProj, 256, GT_SMEM_BYTES, t3>>>(k2h, (__half*)sym(g_spd_h), (__half*)sym(g_wk2h), nullptr, nullptr, MQ_, D_, D_);
        tc_gemm<4><<<gProj, 256, GT_SMEM_BYTES, t3>>>(v2, (__half*)sym(g_spd_h), (__half*)sym(g_wv2h), nullptr, nullptr, MQ_, D_, D_);
        if (multi) {
            cudaEventRecord(ev1, s1);
            cudaEventRecord(ev2, s2);
            cudaEventRecord(ev3, s3);
            cudaStreamWaitEvent(0, ev1, 0);
            cudaStreamWaitEvent(0, ev2, 0);
        }

        // ---- Stage 1 tail ----
        tc_flash<1><<<gFA, 256, TF_SMEM_BYTES>>>(ath, qh, kh, vv, SKV1_);
        tc_gemm<1><<<gProj, 256, GT_SMEM_BYTES>>>(tmp, ath, (__half*)sym(g_wo1h), bo1, cords, MQ_, D_, D_);
        layernorm_kernel<1><<<lnBlocks, 256>>>(x1, x1h, tmp, ln1_g, ln1_b, MQ_);

        // ---- Stage 2 ----
        tc_gemm<3><<<gProj, 256, GT_SMEM_BYTES>>>(qh, x1h, (__half*)sym(g_wq2h), nullptr, nullptr, MQ_, D_, D_);
        if (multi) cudaStreamWaitEvent(0, ev3, 0);
        tc_flash<2><<<gFA, 256, TF_SMEM_BYTES>>>(ath, qh, k2h, v2, SQ_);
        tc_gemm<1><<<gProj, 256, GT_SMEM_BYTES>>>(tmp, ath, (__half*)sym(g_wo2h), bo2, x1, MQ_, D_, D_);
        layernorm_kernel<1><<<lnBlocks, 256>>>(x2, x2h, tmp, ln2_g, ln2_b, MQ_);

        // ---- Stage 3: FFN ----
        tc_gemm<2><<<gFFN1, 256, GT_SMEM_BYTES>>>(hh, x2h, (__half*)sym(g_fw1h), ffn_b1, nullptr, MQ_, DF_, D_);
        tc_gemm<1><<<gProj, 256, GT_SMEM_BYTES>>>(tmp, hh, (__half*)sym(g_fw2h), ffn_b2, x2, MQ_, D_, DF_);
        layernorm_kernel<0><<<lnBlocks, 256>>>(out, nullptr, tmp, ln3_g, ln3_b, MQ_);
    } else {
        // -------- full SIMT fallback (round-1 proven path) --------
        cudaFuncSetAttribute((const void*)flash_kernel<1>, cudaFuncAttributeMaxDynamicSharedMemorySize, FA_SMEM_BYTES);
        cudaFuncSetAttribute((const void*)flash_kernel<2>, cudaFuncAttributeMaxDynamicSharedMemorySize, FA_SMEM_BYTES);
        float* q = (float*)sym(g_fa);
        float* k = (float*)sym(g_fb);
        float* v = (float*)sym(g_fc);
        float* attn = (float*)sym(g_fd);
        float* hbuf = (float*)sym(g_fd);

        sgemm_kernel<0><<<gProj, 256>>>(q, cords,   wq1, nullptr, nullptr, MQ_,   D_, D_);
        sgemm_kernel<0><<<gKV1,  256>>>(k, spatial, wk1, nullptr, nullptr, MKV1_, D_, D_);
        sgemm_kernel<0><<<gKV1,  256>>>(v, spatial, wv1, nullptr, nullptr, MKV1_, D_, D_);
        flash_kernel<1><<<gFA, 256, FA_SMEM_BYTES>>>(attn, q, k, v, SKV1_);
        sgemm_kernel<1><<<gProj, 256>>>(tmp, attn, wo1, bo1, cords, MQ_, D_, D_);
        layernorm_kernel<0><<<lnBlocks, 256>>>(x1, nullptr, tmp, ln1_g, ln1_b, MQ_);

        sgemm_kernel<0><<<gProj, 256>>>(q, x1,    wq2, nullptr, nullptr, MQ_, D_, D_);
        sgemm_kernel<0><<<gProj, 256>>>(k, speed, wk2, nullptr, nullptr, MQ_, D_, D_);
        sgemm_kernel<0><<<gProj, 256>>>(v, speed, wv2, nullptr, nullptr, MQ_, D_, D_);
        flash_kernel<2><<<gFA, 256, FA_SMEM_BYTES>>>(attn, q, k, v, SQ_);
        sgemm_kernel<1><<<gProj, 256>>>(tmp, attn, wo2, bo2, x1, MQ_, D_, D_);
        layernorm_kernel<0><<<lnBlocks, 256>>>(x2, nullptr, tmp, ln2_g, ln2_b, MQ_);

        sgemm_kernel<2><<<gFFN1, 256>>>(hbuf, x2, ffn_w1, ffn_b1, nullptr, MQ_, DF_, D_);
        sgemm_kernel<1><<<gProj, 256>>>(tmp, hbuf, ffn_w2, ffn_b2, x2, MQ_, D_, DF_);
        layernorm_kernel<0><<<lnBlocks, 256>>>(out, nullptr, tmp, ln3_g, ln3_b, MQ_);
    }
}

// round 15
// speedup vs baseline: 1.7476x; 1.0756x over previous
#include <cuda_runtime.h>
#include <cuda_fp16.h>
#include <math.h>
#include <cstdint>

// ============================================================
// Problem constants
// ============================================================
#define B_      8
#define SQ_     768
#define SKV1_   1024
#define D_      512
#define DF_     2048
#define H_      8
#define DH_     64
#define MQ_     (B_*SQ_)      // 6144
#define MKV1_   (B_*SKV1_)    // 8192

#if defined(__CUDA_ARCH__) && (defined(__CUDA_ARCH_FEAT_SM103_ALL) || \
                               defined(__CUDA_ARCH_FEAT_SM100_ALL) || \
                               (defined(__CUDA_ARCH_SPECIFIC__) && \
                                (__CUDA_ARCH_SPECIFIC__ == 1030 || __CUDA_ARCH_SPECIFIC__ == 1000)))
#define HAS_TCGEN05 1
#else
#define HAS_TCGEN05 0
#endif

// ------------------------------------------------------------
// Scratch (device globals; 16B+ alignment for cp.async.bulk)
// PLAIN F16 operands, TILED layout: 8KB SW64-swizzled blocks.
// V stored PRE-TRANSPOSED (8KB SW128 panels).
// ------------------------------------------------------------
__device__ __align__(256) __half g_ca_h [MQ_  * D_];
__device__ __align__(256) __half g_sp_h [MKV1_* D_];
__device__ __align__(256) __half g_spd_h[MQ_  * D_];
__device__ __align__(256) __half g_wq1h[D_*D_];
__device__ __align__(256) __half g_wk1h[D_*D_];
__device__ __align__(256) __half g_wv1h[D_*D_];
__device__ __align__(256) __half g_wo1h[D_*D_];
__device__ __align__(256) __half g_wq2h[D_*D_];
__device__ __align__(256) __half g_wk2h[D_*D_];
__device__ __align__(256) __half g_wv2h[D_*D_];
__device__ __align__(256) __half g_wo2h[D_*D_];
__device__ __align__(256) __half g_fw1h[DF_*D_];
__device__ __align__(256) __half g_fw2h[DF_*D_];
__device__ __align__(256) __half g_q_h [MQ_  * D_];
__device__ __align__(256) __half g_k_h [MKV1_* D_];
__device__ __align__(256) __half g_v   [MKV1_* D_];   // vT panels
__device__ __align__(256) __half g_k2h [MQ_  * D_];
__device__ __align__(256) __half g_v2  [MQ_  * D_];   // vT panels
__device__ __align__(256) __half g_at_h[MQ_  * D_];
__device__ __align__(256) __half g_x1h [MQ_  * D_];
__device__ __align__(256) __half g_x2h [MQ_  * D_];
__device__ __align__(256) __half g_h_h [MQ_  * DF_];
__device__ float g_tmp[MQ_ * D_];
__device__ float g_x1 [MQ_ * D_];
__device__ float g_x2 [MQ_ * D_];
// fp32 fallback scratch (SIMT path)
__device__ float g_fa[MKV1_*D_];
__device__ float g_fb[MKV1_*D_];
__device__ float g_fc[MKV1_*D_];
__device__ float g_fd[MQ_*DF_];

// ============================================================
// Common helpers
// ============================================================
__device__ __forceinline__ float gelu_exact(float x) {
    return 0.5f * x * (1.0f + erff(x * 0.70710678118654752f));
}
__device__ __forceinline__ uint32_t pack2(__half a, __half b) {
    __half2 t = __halves2half2(a, b);
    return *(const uint32_t*)&t;
}
// Tiled layout: byte offset of (row, kcol) in [rows x K] f16 tensor
// stored as 8KB SW64-swizzled panel blocks.
__device__ __forceinline__ size_t tiled_off(int row, int kcol, int K) {
    size_t blk = (size_t)(row >> 7) * (K >> 5) + (kcol >> 5);
    uint32_t ib = (uint32_t)((row & 127) * 64 + (kcol & 31) * 2);
    ib ^= (ib >> 3) & 0x30;      // SW64 swizzle
    return blk * 8192 + ib;
}
#define SWZ128(x) ((x) ^ (((x) >> 3) & 0x70))
// vT layout: 8KB SW128 panel per (64-row kv panel, head).
__device__ __forceinline__ size_t vt_off(int row, int col) {
    size_t blk = (size_t)(row >> 6) * 8 + (col >> 6);
    uint32_t ib = SWZ128((uint32_t)((col & 63) * 128 + (row & 63) * 2));
    return blk * 8192 + ib;
}

// ============================================================
// Batched f16-round kernel (13 jobs) -> TILED hi-only outputs
// ============================================================
#define NSPLIT 13
struct SplitJobs {
    const float4* s[NSPLIT];
    char* h[NSPLIT];
    int end[NSPLIT];
    int ksh[NSPLIT];   // log2(K)
};

__global__ __launch_bounds__(256)
void split_batch(SplitJobs jb)
{
    const int blk = blockIdx.x;
    int j = 0;
    #pragma unroll
    for (int t = 0; t < NSPLIT; t++) if (blk >= jb.end[t]) j = t + 1;
    const int b0 = (j == 0) ? 0 : jb.end[j - 1];
    const int idx = (blk - b0) * 256 + threadIdx.x;
    float4 x = jb.s[j][idx];
    const int ksh = jb.ksh[j];
    const int e0 = idx * 4;
    const int row = e0 >> ksh;
    const int kcol = e0 & ((1 << ksh) - 1);
    const size_t off = tiled_off(row, kcol, 1 << ksh);
    *(uint2*)(jb.h[j] + off) =
        make_uint2(pack2(__float2half_rn(x.x), __float2half_rn(x.y)),
                   pack2(__float2half_rn(x.z), __float2half_rn(x.w)));
}

#if HAS_TCGEN05
// ------------------------------------------------------------
// PTX helpers (sm_103a pass only)
// ------------------------------------------------------------
__device__ __forceinline__ uint32_t smem_u32(const void* smem_ptr) {
    uint32_t addr;
    asm("{ .reg .u64 tmp; cvta.to.shared.u64 tmp, %1; cvt.u32.u64 %0, tmp; }"
        : "=r"(addr) : "l"(smem_ptr));
    return addr;
}

#define MBARRIER_INIT(mbar, count) \
    asm volatile("mbarrier.init.shared.b64 [%0], %1;" \
        :: "r"((uint32_t)(mbar)), "r"((uint32_t)(count)) : "memory")

#define MBARRIER_EXPECT_TX(mbar, bytes) \
    asm volatile("mbarrier.arrive.expect_tx.shared.b64 _, [%0], %1;" \
        :: "r"((uint32_t)(mbar)), "r"((uint32_t)(bytes)) : "memory")

#define CP_BULK_G2S(dst, src, bytes, mbar) \
    asm volatile("cp.async.bulk.shared::cluster.global.mbarrier::complete_tx::bytes [%0], [%1], %2, [%3];" \
        :: "r"((uint32_t)(dst)), "l"(src), "r"((uint32_t)(bytes)), "r"((uint32_t)(mbar)) : "memory")

#define MBARRIER_WAIT_PARITY(mbar_smem_addr, phase_parity) do { \
    uint32_t _mbar = (uint32_t)(mbar_smem_addr); \
    uint32_t _parity = (uint32_t)(phase_parity); \
    uint32_t _done; \
    asm volatile( \
        "{\n\t" \
        ".reg .pred p;\n\t" \
        "mbarrier.try_wait.parity.acquire.cta.shared::cta.b64 p, [%1], %2;\n\t" \
        "selp.b32 %0, 1, 0, p;\n\t" \
        "}" \
        : "=r"(_done) : "r"(_mbar), "r"(_parity) : "memory"); \
    if (!_done) { \
        asm volatile( \
            "{\n\t" \
            ".reg .pred P1;\n\t" \
            "WAIT_LOOP_%=:\n\t" \
            "mbarrier.try_wait.parity.acquire.cta.shared::cta.b64 P1, [%0], %1, 0x989680;\n\t" \
            "@P1 bra.uni WAIT_DONE_%=;\n\t" \
            "bra.uni WAIT_LOOP_%=;\n\t" \
            "WAIT_DONE_%=:\n\t" \
            "}" \
            :: "r"(_mbar), "r"(_parity) : "memory"); \
    } \
} while(0)

#define TCGEN05_ALLOC(smem_result_addr, nCols) \
    asm volatile("tcgen05.alloc.cta_group::1.sync.aligned.shared::cta.b32 [%0], %1;" \
        :: "r"((uint32_t)(smem_result_addr)), "r"((uint32_t)(nCols)) : "memory")
#define TCGEN05_DEALLOC(tmem_addr, nCols) \
    asm volatile("tcgen05.dealloc.cta_group::1.sync.aligned.b32 %0, %1;" \
        :: "r"(tmem_addr), "r"(nCols))
#define TCGEN05_RELINQUISH() \
    asm volatile("tcgen05.relinquish_alloc_permit.cta_group::1.sync.aligned;")
#define TCGEN05_COMMIT(mbar_smem_addr) \
    asm volatile("tcgen05.commit.cta_group::1.mbarrier::arrive::one.shared::cluster.b64 [%0];" \
        :: "r"((uint32_t)(mbar_smem_addr)) : "memory")
#define TCGEN05_FENCE_AFTER() \
    asm volatile("tcgen05.fence::after_thread_sync;" ::: "memory")
#define TCGEN05_FENCE_BEFORE() \
    asm volatile("tcgen05.fence::before_thread_sync;" ::: "memory")
#define TCGEN05_WAIT_LD() \
    asm volatile("tcgen05.wait::ld.sync.aligned;" ::: "memory")
#define FENCE_PROXY_ASYNC_SHARED_CTA() \
    asm volatile("fence.proxy.async.shared::cta;" ::: "memory")

#define TCGEN05_LD_32X32B_X32(r, tmem_addr) \
    asm volatile( \
        "tcgen05.ld.sync.aligned.32x32b.x32.b32 " \
        "{%0, %1, %2, %3, %4, %5, %6, %7, " \
        " %8, %9, %10, %11, %12, %13, %14, %15, " \
        " %16, %17, %18, %19, %20, %21, %22, %23, " \
        " %24, %25, %26, %27, %28, %29, %30, %31}, [%32];" \
        : "=r"((r)[0]),  "=r"((r)[1]),  "=r"((r)[2]),  "=r"((r)[3]), \
          "=r"((r)[4]),  "=r"((r)[5]),  "=r"((r)[6]),  "=r"((r)[7]), \
          "=r"((r)[8]),  "=r"((r)[9]),  "=r"((r)[10]), "=r"((r)[11]), \
          "=r"((r)[12]), "=r"((r)[13]), "=r"((r)[14]), "=r"((r)[15]), \
          "=r"((r)[16]), "=r"((r)[17]), "=r"((r)[18]), "=r"((r)[19]), \
          "=r"((r)[20]), "=r"((r)[21]), "=r"((r)[22]), "=r"((r)[23]), \
          "=r"((r)[24]), "=r"((r)[25]), "=r"((r)[26]), "=r"((r)[27]), \
          "=r"((r)[28]), "=r"((r)[29]), "=r"((r)[30]), "=r"((r)[31]) \
        : "r"(tmem_addr))

#define SMEM_DESC_BASE_SW128 \
    ((uint64_t(2)  << 61) | (uint64_t(1) << 46) | \
     (uint64_t(64) << 32) | (uint64_t(1) << 16))
#define MAKE_SMEM_DESC(base_addr) \
    (SMEM_DESC_BASE_SW128 | ((uint64_t)((base_addr) >> 4) & 0x3FFF))
#define SMEM_DESC_BASE_SW64 \
    ((uint64_t(4)  << 61) | (uint64_t(1) << 46) | \
     (uint64_t(32) << 32) | (uint64_t(1) << 16))
#define MAKE_SMEM_DESC_SW64(base_addr) \
    (SMEM_DESC_BASE_SW64 | ((uint64_t)((base_addr) >> 4) & 0x3FFF))

#define SMEM_SWIZZLE_128B(byte_offset) \
    ((byte_offset) ^ (((byte_offset) >> 3) & 0x70))

__device__ __forceinline__ void tcgen05_mma_f16_ss(
    uint32_t d_tmem, uint64_t a_desc, uint64_t b_desc,
    uint32_t idesc, uint32_t enable)
{
    asm volatile(
        "{\n\t"
        ".reg .pred p;\n\t"
        "setp.ne.u32 p, %6, 0;\n\t"
        "tcgen05.mma.cta_group::1.kind::f16 [%0], %1, %2, %3, "
        "{%4, %4, %4, %4}, p;\n\t"
        "}"
        :: "r"(d_tmem), "l"(a_desc), "l"(b_desc), "r"(idesc),
           "r"(0u), "r"(0u), "r"(enable)
        : "memory");
}

#define IDESC_G  0x8200010u   // M=128, N=128
#define IDESC_PV 0x8100010u   // M=128, N=64
#endif  // HAS_TCGEN05

// ============================================================
// tcgen05 PLAIN F16 GEMM, BK=64: C = Ah @ Wh^T (+ epilogue)
//   TILED inputs; per iter ONE 16KB bulk per operand (2 contig
//   8KB k-blocks) and 4 MMA dispatches. 3 stages x 32KB -> 97KB,
//   occ 2. Chain length halves vs BK=32 (iters = K/64).
//   EPI: 1 +bias+res f32 | 2 gelu(+bias)->tiled f16 |
//        3 tiled f16 | 4 -> vT panels
// ============================================================
#define GT_TILE(buf, which) (1024 + (buf) * 32768 + (which) * 16384)
#define GT_SMEM_BYTES (1024 + 3 * 32768)   // 99328 -> 2 CTAs/SM

template<int EPI>
__global__ __launch_bounds__(256, 2)
void tc_gemm(void* __restrict__ Cp,
             const __half* __restrict__ Ah,
             const __half* __restrict__ Wh,
             const float* __restrict__ bias, const float* __restrict__ res,
             int M, int N, int K)
{
#if HAS_TCGEN05
    extern __shared__ __align__(1024) char gsm[];
    const uint32_t sb = smem_u32(gsm);
    const int tid  = threadIdx.x;
    const int wid  = tid >> 5;
    const int lane = tid & 31;

    if (tid == 0) {
        MBARRIER_INIT(sb + 8, 1);   // mma buf0
        MBARRIER_INIT(sb + 16, 1);  // mma buf1
        MBARRIER_INIT(sb + 24, 1);  // mma buf2
        MBARRIER_INIT(sb + 32, 1);  // load buf0
        MBARRIER_INIT(sb + 40, 1);  // load buf1
        MBARRIER_INIT(sb + 48, 1);  // load buf2
        FENCE_PROXY_ASYNC_SHARED_CTA();
    }
    if (wid == 0) {
        TCGEN05_ALLOC(sb + 0, 128);
        TCGEN05_RELINQUISH();
    }
    __syncthreads();
    uint32_t tmem;
    asm volatile("ld.shared.b32 %0, [%1];" : "=r"(tmem) : "r"(sb + 0));

    const int iters = K >> 6;              // BK=64

    if (tid == 0) {
        // 16KB per operand per iter = 2 contiguous 8KB k-blocks
        const char* Ahc = (const char*)Ah + (size_t)(blockIdx.y) * (K >> 5) * 8192;
        const char* Whc = (const char*)Wh + (size_t)(blockIdx.x) * (K >> 5) * 8192;

        #pragma unroll
        for (int s = 0; s < 2; s++) {
            MBARRIER_EXPECT_TX(sb + 32 + s * 8, 32768);
            CP_BULK_G2S(sb + GT_TILE(s, 0), Ahc + (size_t)s * 16384, 16384, sb + 32 + s * 8);
            CP_BULK_G2S(sb + GT_TILE(s, 1), Whc + (size_t)s * 16384, 16384, sb + 32 + s * 8);
        }

        for (int i = 0; i < iters; i++) {
            const int b = i % 3;
            MBARRIER_WAIT_PARITY(sb + 32 + b * 8, (i / 3) & 1);

            #pragma unroll
            for (int blk = 0; blk < 2; blk++) {
                const uint64_t dA = MAKE_SMEM_DESC_SW64(sb + GT_TILE(b, 0) + blk * 8192);
                const uint64_t dB = MAKE_SMEM_DESC_SW64(sb + GT_TILE(b, 1) + blk * 8192);
                #pragma unroll
                for (int kk = 0; kk < 2; kk++) {
                    const uint64_t o = kk * 2;
                    tcgen05_mma_f16_ss(tmem, dA + o, dB + o, IDESC_G,
                                       (i > 0 || blk > 0 || kk > 0) ? 1u : 0u);
                }
            }
            TCGEN05_COMMIT(sb + 8 + b * 8);

            const int j2 = i + 2;
            if (j2 < iters) {
                const int b2 = j2 % 3;
                if (i >= 1)
                    MBARRIER_WAIT_PARITY(sb + 8 + ((i - 1) % 3) * 8,
                                         ((i - 1) / 3) & 1);
                MBARRIER_EXPECT_TX(sb + 32 + b2 * 8, 32768);
                CP_BULK_G2S(sb + GT_TILE(b2, 0), Ahc + (size_t)j2 * 16384, 16384, sb + 32 + b2 * 8);
                CP_BULK_G2S(sb + GT_TILE(b2, 1), Whc + (size_t)j2 * 16384, 16384, sb + 32 + b2 * 8);
            }
        }
    }

    __syncthreads();
    MBARRIER_WAIT_PARITY(sb + 8 + ((iters - 1) % 3) * 8, ((iters - 1) / 3) & 1);
    TCGEN05_FENCE_AFTER();

    // Epilogue
    {
        const int bm = blockIdx.y * 128;
        const int bn = blockIdx.x * 128;
        const int sub = wid & 3;
        const int h2  = wid >> 2;
        const int row = bm + sub * 32 + lane;
        #pragma unroll
        for (int q = 0; q < 2; q++) {
            uint32_t r[32];
            TCGEN05_LD_32X32B_X32(r, tmem + h2 * 64 + q * 32);
            TCGEN05_WAIT_LD();
            #pragma unroll
            for (int c4 = 0; c4 < 8; c4++) {
                const int col = bn + h2 * 64 + q * 32 + c4 * 4;
                float4 v;
                v.x = __uint_as_float(r[c4 * 4 + 0]);
                v.y = __uint_as_float(r[c4 * 4 + 1]);
                v.z = __uint_as_float(r[c4 * 4 + 2]);
                v.w = __uint_as_float(r[c4 * 4 + 3]);
                if (EPI == 1 || EPI == 2) {
                    float4 bi = *(const float4*)&bias[col];
                    v.x += bi.x; v.y += bi.y; v.z += bi.z; v.w += bi.w;
                }
                if (EPI == 1) {
                    float4 rv = *(const float4*)&res[(size_t)row * N + col];
                    v.x += rv.x; v.y += rv.y; v.z += rv.z; v.w += rv.w;
                    *(float4*)((float*)Cp + (size_t)row * N + col) = v;
                }
                if (EPI == 2) {
                    v.x = gelu_exact(v.x); v.y = gelu_exact(v.y);
                    v.z = gelu_exact(v.z); v.w = gelu_exact(v.w);
                }
                if (EPI == 2 || EPI == 3) {   // tiled f16
                    const size_t off = tiled_off(row, col, N);
                    *(uint2*)((char*)Cp + off) =
                        make_uint2(pack2(__float2half_rn(v.x), __float2half_rn(v.y)),
                                   pack2(__float2half_rn(v.z), __float2half_rn(v.w)));
                }
                if (EPI == 4) {   // pre-transposed vT panels (f16 round)
                    char* base = (char*)Cp;
                    *(__half*)(base + vt_off(row, col + 0)) = __float2half_rn(v.x);
                    *(__half*)(base + vt_off(row, col + 1)) = __float2half_rn(v.y);
                    *(__half*)(base + vt_off(row, col + 2)) = __float2half_rn(v.z);
                    *(__half*)(base + vt_off(row, col + 3)) = __float2half_rn(v.w);
                }
            }
        }
    }

    __syncthreads();
    if (wid == 0) TCGEN05_DEALLOC(tmem, 128);
#endif
}

// ============================================================
// tcgen05 f16 flash attention — unchanged R14 (plain f16,
// bulk Q/K hi-only, pre-transposed V, unnormalized softmax).
// ============================================================
#define TF_QH    1024
#define TF_KH    (TF_QH + 16384)
#define TF_VT    (TF_QH + 32768)   // 2 panels x 8 KB (SW128)
#define TF_P     (TF_QH + 49152)   // 2 panels x 16 KB (SW128)
#define TF_SMEM_BYTES (TF_P + 32768)  // 82944

template<int MASK>
__global__ __launch_bounds__(256, 2)
void tc_flash(__half* __restrict__ Oh,
              const __half* __restrict__ Qh,
              const __half* __restrict__ Kh,
              const __half* __restrict__ Vp, int kvlen)
{
#if HAS_TCGEN05
    extern __shared__ __align__(1024) char fsm[];
    const uint32_t sb = smem_u32(fsm);
    const int tid  = threadIdx.x;
    const int wid  = tid >> 5;
    const int lane = tid & 31;
    const int sub  = wid & 3;
    const int h2   = wid >> 2;
    const int q0   = blockIdx.x * 128;
    const int h    = blockIdx.y;
    const int b    = blockIdx.z;

    if (tid == 0) {
        MBARRIER_INIT(sb + 8, 1);    // S done
        MBARRIER_INIT(sb + 16, 1);   // PV done
        MBARRIER_INIT(sb + 24, 1);   // Q loaded
        MBARRIER_INIT(sb + 32, 1);   // K loaded
        MBARRIER_INIT(sb + 48, 1);   // V loaded
        FENCE_PROXY_ASYNC_SHARED_CTA();
    }
    if (wid == 0) {
        TCGEN05_ALLOC(sb + 0, 256);
        TCGEN05_RELINQUISH();
    }
    __syncthreads();
    uint32_t tmem;
    asm volatile("ld.shared.b32 %0, [%1];" : "=r"(tmem) : "r"(sb + 0));

    const size_t qblk = ((size_t)((b * SQ_ + q0) >> 7) * 16 + 2 * h) * 8192;
    if (tid == 0) {
        MBARRIER_EXPECT_TX(sb + 24, 16384);
        CP_BULK_G2S(sb + TF_QH, (const char*)Qh + qblk, 16384, sb + 24);
        const size_t kblk = ((size_t)((b * kvlen) >> 7) * 16 + 2 * h) * 8192;
        MBARRIER_EXPECT_TX(sb + 32, 16384);
        CP_BULK_G2S(sb + TF_KH, (const char*)Kh + kblk, 16384, sb + 32);
    }

    float lsum = 0.f;
    const int qrow = sub * 32 + lane;
    const int qg   = q0 + qrow;

    const int ntiles = kvlen >> 7;
    for (int t = 0; t < ntiles; t++) {
        const int kv0 = t << 7;

        // ---- S = Qh @ Kh^T (SW64 tiles, 4 dispatches) ----
        if (tid == 0) {
            if (t == 0) MBARRIER_WAIT_PARITY(sb + 24, 0);
            MBARRIER_WAIT_PARITY(sb + 32, t & 1);
            #pragma unroll
            for (int blk = 0; blk < 2; blk++) {
                const uint64_t dQh = MAKE_SMEM_DESC_SW64(sb + TF_QH + blk * 8192);
                const uint64_t dKh = MAKE_SMEM_DESC_SW64(sb + TF_KH + blk * 8192);
                #pragma unroll
                for (int kk = 0; kk < 2; kk++) {
                    const uint64_t o = kk * 2;
                    tcgen05_mma_f16_ss(tmem + 64, dQh + o, dKh + o, IDESC_G,
                                       (blk == 0 && kk == 0) ? 0u : 1u);
                }
            }
            TCGEN05_COMMIT(sb + 8);
        }

        // ---- PV(t-1) drain frees VT/P, then bulk-load V(t) ----
        if (t > 0) {
            MBARRIER_WAIT_PARITY(sb + 16, (t - 1) & 1);
        }
        if (tid == 0) {
            const size_t vblk = ((size_t)((b * kvlen + kv0) >> 6) * 8 + h) * 8192;
            MBARRIER_EXPECT_TX(sb + 48, 16384);
            CP_BULK_G2S(sb + TF_VT,        (const char*)Vp + vblk,             8192, sb + 48);
            CP_BULK_G2S(sb + TF_VT + 8192, (const char*)Vp + vblk + 8 * 8192,  8192, sb + 48);
        }

        // ---- Wait S (all); prefetch next K (tid0) ----
        MBARRIER_WAIT_PARITY(sb + 8, t & 1);
        TCGEN05_FENCE_AFTER();
        if (tid == 0 && t + 1 < ntiles) {
            const size_t kblk = ((size_t)((b * kvlen + kv0 + 128) >> 7) * 16 + 2 * h) * 8192;
            MBARRIER_EXPECT_TX(sb + 32, 16384);
            CP_BULK_G2S(sb + TF_KH, (const char*)Kh + kblk, 16384, sb + 32);
        }

        // ---- softmax (unnormalized) -> f16 P (SW128) ----
        #pragma unroll
        for (int chunk = 0; chunk < 2; chunk++) {
            uint32_t r[32];
            TCGEN05_LD_32X32B_X32(r, tmem + 64 + h2 * 64 + chunk * 32);
            TCGEN05_WAIT_LD();
            const int kvb = h2 * 64 + chunk * 32;
            char* Pp = fsm + TF_P + h2 * 16384;
            #pragma unroll
            for (int c16 = 0; c16 < 4; c16++) {
                uint32_t w[4];
                #pragma unroll
                for (int pr = 0; pr < 4; pr++) {
                    __half hs[2];
                    #pragma unroll
                    for (int j = 0; j < 2; j++) {
                        const float s = __uint_as_float(r[c16 * 8 + pr * 2 + j]);
                        const int kg = kv0 + kvb + c16 * 8 + pr * 2 + j;
                        float wm;
                        if (MASK == 1) wm = ((qg < 512) == (kg < 512)) ? 1.25f : 1.0f;
                        else           wm = ((qg >> 8)  == (kg >> 8))  ? 1.25f : 1.0f;
                        const float p = __expf(s * (0.125f * wm));
                        hs[j] = __float2half_rn(p);
                        lsum += __half2float(hs[j]);
                    }
                    w[pr] = pack2(hs[0], hs[1]);
                }
                const uint32_t sw = SMEM_SWIZZLE_128B(
                    (uint32_t)(qrow * 128 + chunk * 64 + c16 * 16));
                *(uint4*)(Pp + sw) = make_uint4(w[0], w[1], w[2], w[3]);
            }
        }
        TCGEN05_FENCE_BEFORE();
        __syncthreads();

        // ---- O += P @ V^T (SW128, 8 dispatches) ----
        if (tid == 0) {
            FENCE_PROXY_ASYNC_SHARED_CTA();
            MBARRIER_WAIT_PARITY(sb + 48, t & 1);   // V(t) landed
            #pragma unroll
            for (int p2 = 0; p2 < 2; p2++) {
                const uint64_t dP = MAKE_SMEM_DESC(sb + TF_P  + p2 * 16384);
                const uint64_t dV = MAKE_SMEM_DESC(sb + TF_VT + p2 * 8192);
                #pragma unroll
                for (int kk = 0; kk < 4; kk++) {
                    const uint64_t o = kk * 2;
                    tcgen05_mma_f16_ss(tmem, dP + o, dV + o, IDESC_PV,
                                       (t == 0 && p2 == 0 && kk == 0) ? 0u : 1u);
                }
            }
            TCGEN05_COMMIT(sb + 16);
        }
    }

    MBARRIER_WAIT_PARITY(sb + 16, (ntiles - 1) & 1);
    TCGEN05_FENCE_AFTER();

    // combine row sums across column-half warpgroups
    {
        float* lx = (float*)(fsm + TF_VT);
        lx[wid * 32 + lane] = lsum;
    }
    __syncthreads();
    const float lother = ((float*)(fsm + TF_VT))[(wid ^ 4) * 32 + lane];
    const float inv = 1.0f / (lsum + lother);

    // O epilogue: tiled f16 (feeds wo GEMM)
    {
        uint32_t r[32];
        TCGEN05_LD_32X32B_X32(r, tmem + h2 * 32);
        TCGEN05_WAIT_LD();
        const int orow = b * SQ_ + qg;
        #pragma unroll
        for (int c4 = 0; c4 < 8; c4++) {
            const size_t off = tiled_off(orow, h * DH_ + h2 * 32 + c4 * 4, D_);
            *(uint2*)((char*)Oh + off) = make_uint2(
                pack2(__float2half_rn(__uint_as_float(r[c4*4+0]) * inv),
                      __float2half_rn(__uint_as_float(r[c4*4+1]) * inv)),
                pack2(__float2half_rn(__uint_as_float(r[c4*4+2]) * inv),
                      __float2half_rn(__uint_as_float(r[c4*4+3]) * inv)));
        }
    }

    __syncthreads();
    if (wid == 0) TCGEN05_DEALLOC(tmem, 256);
#endif  // HAS_TCGEN05
}

// ============================================================
// SIMT SGEMM fallback (round-1 proven, fp32)
// ============================================================
template<int EPI>
__global__ __launch_bounds__(256)
void sgemm_kernel(float* __restrict__ C,
                  const float* __restrict__ A,
                  const float* __restrict__ W,
                  const float* __restrict__ bias,
                  const float* __restrict__ res,
                  int M, int N, int K)
{
    __shared__ float As[8][128];
    __shared__ float Bs[8][128];

    const int tid = threadIdx.x;
    const int bm  = blockIdx.y * 128;
    const int bn  = blockIdx.x * 128;

    const int lr = tid >> 1;
    const int lc = (tid & 1) * 4;
    const float* Aptr = A + (size_t)(bm + lr) * K + lc;
    const float* Wptr = W + (size_t)(bn + lr) * K + lc;

    const int ty = tid >> 4;
    const int tx = tid & 15;

    float acc[8][8];
    #pragma unroll
    for (int i = 0; i < 8; i++)
        #pragma unroll
        for (int j = 0; j < 8; j++) acc[i][j] = 0.f;

    for (int k0 = 0; k0 < K; k0 += 8) {
        float4 a4 = *(const float4*)(Aptr + k0);
        float4 b4 = *(const float4*)(Wptr + k0);
        As[lc + 0][lr] = a4.x; As[lc + 1][lr] = a4.y;
        As[lc + 2][lr] = a4.z; As[lc + 3][lr] = a4.w;
        Bs[lc + 0][lr] = b4.x; Bs[lc + 1][lr] = b4.y;
        Bs[lc + 2][lr] = b4.z; Bs[lc + 3][lr] = b4.w;
        __syncthreads();

        #pragma unroll
        for (int kk = 0; kk < 8; kk++) {
            float ra[8], rb[8];
            *(float4*)(ra)     = *(const float4*)&As[kk][ty * 4];
            *(float4*)(ra + 4) = *(const float4*)&As[kk][ty * 4 + 64];
            *(float4*)(rb)     = *(const float4*)&Bs[kk][tx * 4];
            *(float4*)(rb + 4) = *(const float4*)&Bs[kk][tx * 4 + 64];
            #pragma unroll
            for (int i = 0; i < 8; i++)
                #pragma unroll
                for (int j = 0; j < 8; j++)
                    acc[i][j] += ra[i] * rb[j];
        }
        __syncthreads();
    }

    #pragma unroll
    for (int i = 0; i < 8; i++) {
        const int row = bm + ty * 4 + (i & 3) + (i >> 2) * 64;
        #pragma unroll
        for (int jh = 0; jh < 2; jh++) {
            const int col = bn + tx * 4 + jh * 64;
            float4 v;
            v.x = acc[i][jh * 4 + 0];
            v.y = acc[i][jh * 4 + 1];
            v.z = acc[i][jh * 4 + 2];
            v.w = acc[i][jh * 4 + 3];
            if (EPI >= 1) {
                float4 bi = *(const float4*)&bias[col];
                v.x += bi.x; v.y += bi.y; v.z += bi.z; v.w += bi.w;
            }
            if (EPI == 1) {
                float4 rv = *(const float4*)&res[(size_t)row * N + col];
                v.x += rv.x; v.y += rv.y; v.z += rv.z; v.w += rv.w;
            }
            if (EPI == 2) {
                v.x = gelu_exact(v.x); v.y = gelu_exact(v.y);
                v.z = gelu_exact(v.z); v.w = gelu_exact(v.w);
            }
            *(float4*)&C[(size_t)row * N + col] = v;
        }
    }
}

// ============================================================
// SIMT flash attention fallback (round-1 proven, fp32)
// ============================================================
#define FA_STRIDE 68
#define FA_SMEM_FLOATS ((128 + 64 + 64 + 128) * FA_STRIDE)
#define FA_SMEM_BYTES  (FA_SMEM_FLOATS * 4)

template<int MASK>
__global__ __launch_bounds__(256)
void flash_kernel(float* __restrict__ O,
                  const float* __restrict__ Q,
                  const float* __restrict__ Kp,
                  const float* __restrict__ Vp,
                  int kvlen)
{
    extern __shared__ float fsm2[];
    float* Qs = fsm2;
    float* Ks = Qs + 128 * FA_STRIDE;
    float* Vt = Ks + 64  * FA_STRIDE;
    float* Ps = Vt + 64  * FA_STRIDE;

    const int tid = threadIdx.x;
    const int q0  = blockIdx.x * 128;
    const int h   = blockIdx.y;
    const int b   = blockIdx.z;
    const int rg  = tid >> 4;
    const int cg  = tid & 15;

    {
        const int qrow = tid >> 1;
        const int half = tid & 1;
        const float* qbase = Q + (size_t)(b * SQ_ + q0 + qrow) * D_ + h * DH_;
        #pragma unroll
        for (int i = 0; i < 8; i++) {
            const int f4 = half * 8 + i;
            *(float4*)&Qs[qrow * FA_STRIDE + f4 * 4] = *(const float4*)&qbase[f4 * 4];
        }
    }

    float m_i[8], l_i[8], oacc[8][4];
    #pragma unroll
    for (int u = 0; u < 8; u++) {
        m_i[u] = -1e30f; l_i[u] = 0.f;
        #pragma unroll
        for (int t = 0; t < 4; t++) oacc[u][t] = 0.f;
    }

    const int ntiles = kvlen >> 6;
    for (int t0 = 0; t0 < ntiles; t0++) {
        const int kv0 = t0 * 64;
        __syncthreads();

        {
            const int lrow = tid >> 2;
            const int lq   = tid & 3;
            const float* kbase = Kp + (size_t)(b * kvlen + kv0 + lrow) * D_ + h * DH_;
            const float* vbase = Vp + (size_t)(b * kvlen + kv0 + lrow) * D_ + h * DH_;
            #pragma unroll
            for (int i = 0; i < 4; i++) {
                const int f4 = lq * 4 + i;
                float4 k4 = *(const float4*)&kbase[f4 * 4];
                *(float4*)&Ks[lrow * FA_STRIDE + f4 * 4] = k4;
                float4 v4 = *(const float4*)&vbase[f4 * 4];
                const int d0 = f4 * 4;
                Vt[(d0 + 0) * FA_STRIDE + lrow] = v4.x;
                Vt[(d0 + 1) * FA_STRIDE + lrow] = v4.y;
                Vt[(d0 + 2) * FA_STRIDE + lrow] = v4.z;
                Vt[(d0 + 3) * FA_STRIDE + lrow] = v4.w;
            }
        }
        __syncthreads();

        float sacc[8][4];
        #pragma unroll
        for (int u = 0; u < 8; u++)
            #pragma unroll
            for (int t = 0; t < 4; t++) sacc[u][t] = 0.f;

        #pragma unroll
        for (int d4 = 0; d4 < 16; d4++) {
            float4 qv[8];
            #pragma unroll
            for (int u = 0; u < 8; u++)
                qv[u] = *(const float4*)&Qs[(rg + 16 * u) * FA_STRIDE + d4 * 4];
            #pragma unroll
            for (int t = 0; t < 4; t++) {
                float4 kk = *(const float4*)&Ks[(cg + 16 * t) * FA_STRIDE + d4 * 4];
                #pragma unroll
                for (int u = 0; u < 8; u++)
                    sacc[u][t] += qv[u].x * kk.x + qv[u].y * kk.y
                                + qv[u].z * kk.z + qv[u].w * kk.w;
            }
        }

        #pragma unroll
        for (int u = 0; u < 8; u++) {
            const int qg = q0 + rg + 16 * u;
            #pragma unroll
            for (int t = 0; t < 4; t++) {
                const int kg = kv0 + cg + 16 * t;
                float wm;
                if (MASK == 1) wm = ((qg < 512) == (kg < 512)) ? 1.25f : 1.0f;
                else           wm = ((qg >> 8)  == (kg >> 8))  ? 1.25f : 1.0f;
                sacc[u][t] *= 0.125f * wm;
            }
        }

        #pragma unroll
        for (int u = 0; u < 8; u++) {
            float rmax = fmaxf(fmaxf(sacc[u][0], sacc[u][1]),
                               fmaxf(sacc[u][2], sacc[u][3]));
            #pragma unroll
            for (int off = 8; off >= 1; off >>= 1)
                rmax = fmaxf(rmax, __shfl_xor_sync(0xffffffffu, rmax, off));
            const float mnew  = fmaxf(m_i[u], rmax);
            const float alpha = __expf(m_i[u] - mnew);
            m_i[u] = mnew;
            float rsum = 0.f;
            #pragma unroll
            for (int t = 0; t < 4; t++) {
                const float p = __expf(sacc[u][t] - mnew);
                Ps[(rg + 16 * u) * FA_STRIDE + cg + 16 * t] = p;
                rsum += p;
            }
            #pragma unroll
            for (int off = 8; off >= 1; off >>= 1)
                rsum += __shfl_xor_sync(0xffffffffu, rsum, off);
            l_i[u] = l_i[u] * alpha + rsum;
            #pragma unroll
            for (int t = 0; t < 4; t++) oacc[u][t] *= alpha;
        }
        __syncthreads();

        #pragma unroll
        for (int j4 = 0; j4 < 16; j4++) {
            float4 pv[8];
            #pragma unroll
            for (int u = 0; u < 8; u++)
                pv[u] = *(const float4*)&Ps[(rg + 16 * u) * FA_STRIDE + j4 * 4];
            #pragma unroll
            for (int t = 0; t < 4; t++) {
                float4 vv = *(const float4*)&Vt[(cg + 16 * t) * FA_STRIDE + j4 * 4];
                #pragma unroll
                for (int u = 0; u < 8; u++)
                    oacc[u][t] += pv[u].x * vv.x + pv[u].y * vv.y
                                + pv[u].z * vv.z + pv[u].w * vv.w;
            }
        }
    }

    #pragma unroll
    for (int u = 0; u < 8; u++) {
        const float inv = 1.0f / l_i[u];
        const size_t row = (size_t)(b * SQ_ + q0 + rg + 16 * u);
        #pragma unroll
        for (int t = 0; t < 4; t++)
            O[row * D_ + h * DH_ + cg + 16 * t] = oacc[u][t] * inv;
    }
}

// ============================================================
// LayerNorm over D=512; SPLIT=1 also emits TILED f16 (hi only)
// ============================================================
template<int SPLIT>
__global__ __launch_bounds__(256)
void layernorm_kernel(float* __restrict__ out,
                      __half* __restrict__ oh,
                      const float* __restrict__ in,
                      const float* __restrict__ g, const float* __restrict__ b,
                      int rows)
{
    const int gt   = blockIdx.x * 256 + threadIdx.x;
    const int row  = gt >> 5;
    const int lane = gt & 31;
    if (row >= rows) return;

    const float* x = in + (size_t)row * D_;
    float4 v[4];
    float s = 0.f;
    #pragma unroll
    for (int i = 0; i < 4; i++) {
        v[i] = *(const float4*)&x[(lane + i * 32) * 4];
        s += v[i].x + v[i].y + v[i].z + v[i].w;
    }
    #pragma unroll
    for (int o = 16; o; o >>= 1) s += __shfl_xor_sync(0xffffffffu, s, o);
    const float mean = s * (1.0f / 512.0f);

    float var = 0.f;
    #pragma unroll
    for (int i = 0; i < 4; i++) {
        float dx = v[i].x - mean; var += dx * dx;
        dx = v[i].y - mean; var += dx * dx;
        dx = v[i].z - mean; var += dx * dx;
        dx = v[i].w - mean; var += dx * dx;
    }
    #pragma unroll
    for (int o = 16; o; o >>= 1) var += __shfl_xor_sync(0xffffffffu, var, o);
    const float rstd = rsqrtf(var * (1.0f / 512.0f) + 1e-5f);

    #pragma unroll
    for (int i = 0; i < 4; i++) {
        const int c = (lane + i * 32) * 4;
        float4 gv = *(const float4*)&g[c];
        float4 bv = *(const float4*)&b[c];
        float4 o4;
        o4.x = (v[i].x - mean) * rstd * gv.x + bv.x;
        o4.y = (v[i].y - mean) * rstd * gv.y + bv.y;
        o4.z = (v[i].z - mean) * rstd * gv.z + bv.z;
        o4.w = (v[i].w - mean) * rstd * gv.w + bv.w;
        *(float4*)&out[(size_t)row * D_ + c] = o4;
        if (SPLIT) {
            const size_t off = tiled_off(row, c, D_);
            *(uint2*)((char*)oh + off) =
                make_uint2(pack2(__float2half_rn(o4.x), __float2half_rn(o4.y)),
                           pack2(__float2half_rn(o4.z), __float2half_rn(o4.w)));
        }
    }
}

// ============================================================
// Launch
// ============================================================
static void* sym(const void* symbol) {
    void* p = nullptr;
    cudaGetSymbolAddress(&p, symbol);
    return p;
}

extern "C" void kernel_launch(void* const* d_in, const int* in_sizes, int n_in,
                              void* d_out, int out_size)
{
    const float* cords   = (const float*)d_in[0];
    const float* spatial = (const float*)d_in[1];
    const float* speed   = (const float*)d_in[2];
    const float* wq1 = (const float*)d_in[3];
    const float* wk1 = (const float*)d_in[4];
    const float* wv1 = (const float*)d_in[5];
    const float* wo1 = (const float*)d_in[6];
    const float* bo1 = (const float*)d_in[7];
    const float* wq2 = (const float*)d_in[8];
    const float* wk2 = (const float*)d_in[9];
    const float* wv2 = (const float*)d_in[10];
    const float* wo2 = (const float*)d_in[11];
    const float* bo2 = (const float*)d_in[12];
    const float* ln1_g = (const float*)d_in[13];
    const float* ln1_b = (const float*)d_in[14];
    const float* ln2_g = (const float*)d_in[15];
    const float* ln2_b = (const float*)d_in[16];
    const float* ln3_g = (const float*)d_in[17];
    const float* ln3_b = (const float*)d_in[18];
    const float* ffn_w1 = (const float*)d_in[19];
    const float* ffn_b1 = (const float*)d_in[20];
    const float* ffn_w2 = (const float*)d_in[21];
    const float* ffn_b2 = (const float*)d_in[22];
    float* out = (float*)d_out;

    cudaFuncAttributes fa{};
    bool tc1 = false, tc2 = false;
    if (cudaFuncGetAttributes(&fa, (const void*)tc_gemm<1>) == cudaSuccess)
        tc1 = (fa.numRegs >= 32);
    if (cudaFuncGetAttributes(&fa, (const void*)tc_flash<1>) == cudaSuccess)
        tc2 = (fa.numRegs >= 32);
    const bool use_tc = tc1 && tc2;

    static cudaStream_t s1 = nullptr, s2 = nullptr, s3 = nullptr;
    static cudaEvent_t  evF = nullptr, ev1 = nullptr, ev2 = nullptr, ev3 = nullptr;
    static int sinit = 0;
    if (sinit == 0) {
        bool ok = true;
        ok &= (cudaStreamCreateWithFlags(&s1, cudaStreamNonBlocking) == cudaSuccess);
        ok &= (cudaStreamCreateWithFlags(&s2, cudaStreamNonBlocking) == cudaSuccess);
        ok &= (cudaStreamCreateWithFlags(&s3, cudaStreamNonBlocking) == cudaSuccess);
        ok &= (cudaEventCreateWithFlags(&evF, cudaEventDisableTiming) == cudaSuccess);
        ok &= (cudaEventCreateWithFlags(&ev1, cudaEventDisableTiming) == cudaSuccess);
        ok &= (cudaEventCreateWithFlags(&ev2, cudaEventDisableTiming) == cudaSuccess);
        ok &= (cudaEventCreateWithFlags(&ev3, cudaEventDisableTiming) == cudaSuccess);
        sinit = ok ? 1 : -1;
    }
    const bool multi = (sinit == 1) && use_tc;
    cudaStream_t t1 = multi ? s1 : 0;
    cudaStream_t t2 = multi ? s2 : 0;
    cudaStream_t t3 = multi ? s3 : 0;

    const dim3 gProj(D_ / 128, MQ_ / 128);     // (4, 48)
    const dim3 gKV1 (D_ / 128, MKV1_ / 128);   // (4, 64)
    const dim3 gFFN1(DF_ / 128, MQ_ / 128);    // (16, 48)
    const dim3 gFA  (SQ_ / 128, H_, B_);       // (6, 8, 8)
    const int  lnBlocks = MQ_ * 32 / 256;      // 768

    float* tmp = (float*)sym(g_tmp);
    float* x1  = (float*)sym(g_x1);
    float* x2  = (float*)sym(g_x2);

    if (use_tc) {
        cudaFuncSetAttribute((const void*)tc_gemm<1>, cudaFuncAttributeMaxDynamicSharedMemorySize, GT_SMEM_BYTES);
        cudaFuncSetAttribute((const void*)tc_gemm<2>, cudaFuncAttributeMaxDynamicSharedMemorySize, GT_SMEM_BYTES);
        cudaFuncSetAttribute((const void*)tc_gemm<3>, cudaFuncAttributeMaxDynamicSharedMemorySize, GT_SMEM_BYTES);
        cudaFuncSetAttribute((const void*)tc_gemm<4>, cudaFuncAttributeMaxDynamicSharedMemorySize, GT_SMEM_BYTES);
        cudaFuncSetAttribute((const void*)tc_flash<1>, cudaFuncAttributeMaxDynamicSharedMemorySize, TF_SMEM_BYTES);
        cudaFuncSetAttribute((const void*)tc_flash<2>, cudaFuncAttributeMaxDynamicSharedMemorySize, TF_SMEM_BYTES);

        // ---- round inputs + weights -> tiled f16 (one launch) ----
        SplitJobs jb{};
        const float* srcs[NSPLIT] = {cords, spatial, speed,
                                     wq1, wk1, wv1, wo1, wq2, wk2, wv2, wo2,
                                     ffn_w1, ffn_w2};
        void* dsth[NSPLIT] = {sym(g_ca_h), sym(g_sp_h), sym(g_spd_h),
                              sym(g_wq1h), sym(g_wk1h), sym(g_wv1h), sym(g_wo1h),
                              sym(g_wq2h), sym(g_wk2h), sym(g_wv2h), sym(g_wo2h),
                              sym(g_fw1h), sym(g_fw2h)};
        const int nelts[NSPLIT] = {MQ_*D_, MKV1_*D_, MQ_*D_,
                                   D_*D_, D_*D_, D_*D_, D_*D_,
                                   D_*D_, D_*D_, D_*D_, D_*D_,
                                   DF_*D_, DF_*D_};
        const int kshs[NSPLIT] = {9,9,9, 9,9,9,9, 9,9,9,9, 9,11};
        int acc = 0;
        for (int j = 0; j < NSPLIT; j++) {
            jb.s[j] = (const float4*)srcs[j];
            jb.h[j] = (char*)dsth[j];
            acc += nelts[j] / 1024;
            jb.end[j] = acc;
            jb.ksh[j] = kshs[j];
        }
        split_batch<<<acc, 256>>>(jb);

        __half* qh = (__half*)sym(g_q_h);
        __half* kh = (__half*)sym(g_k_h);
        __half* vv = (__half*)sym(g_v);
        __half* k2h = (__half*)sym(g_k2h);
        __half* v2 = (__half*)sym(g_v2);
        __half* ath = (__half*)sym(g_at_h);
        __half* x1h = (__half*)sym(g_x1h);
        __half* x2h = (__half*)sym(g_x2h);
        __half* hh = (__half*)sym(g_h_h);

        // ---- Fork: q1 on 0; k1/v1 on s1/s2; k2/v2 on s3 ----
        if (multi) {
            cudaEventRecord(evF, 0);
            cudaStreamWaitEvent(s1, evF, 0);
            cudaStreamWaitEvent(s2, evF, 0);
            cudaStreamWaitEvent(s3, evF, 0);
        }
        tc_gemm<3><<<gProj, 256, GT_SMEM_BYTES, 0 >>>(qh, (__half*)sym(g_ca_h), (__half*)sym(g_wq1h), nullptr, nullptr, MQ_, D_, D_);
        tc_gemm<3><<<gKV1,  256, GT_SMEM_BYTES, t1>>>(kh, (__half*)sym(g_sp_h), (__half*)sym(g_wk1h), nullptr, nullptr, MKV1_, D_, D_);
        tc_gemm<4><<<gKV1,  256, GT_SMEM_BYTES, t2>>>(vv, (__half*)sym(g_sp_h), (__half*)sym(g_wv1h), nullptr, nullptr, MKV1_, D_, D_);
        tc_gemm<3><<<gProj, 256, GT_SMEM_BYTES, t3>>>(k2h, (__half*)sym(g_spd_h), (__half*)sym(g_wk2h), nullptr, nullptr, MQ_, D_, D_);
        tc_gemm<4><<<gProj, 256, GT_SMEM_BYTES, t3>>>(v2, (__half*)sym(g_spd_h), (__half*)sym(g_wv2h), nullptr, nullptr, MQ_, D_, D_);
        if (multi) {
            cudaEventRecord(ev1, s1);
            cudaEventRecord(ev2, s2);
            cudaEventRecord(ev3, s3);
            cudaStreamWaitEvent(0, ev1, 0);
            cudaStreamWaitEvent(0, ev2, 0);
        }

        // ---- Stage 1 tail ----
        tc_flash<1><<<gFA, 256, TF_SMEM_BYTES>>>(ath, qh, kh, vv, SKV1_);
        tc_gemm<1><<<gProj, 256, GT_SMEM_BYTES>>>(tmp, ath, (__half*)sym(g_wo1h), bo1, cords, MQ_, D_, D_);
        layernorm_kernel<1><<<lnBlocks, 256>>>(x1, x1h, tmp, ln1_g, ln1_b, MQ_);

        // ---- Stage 2 ----
        tc_gemm<3><<<gProj, 256, GT_SMEM_BYTES>>>(qh, x1h, (__half*)sym(g_wq2h), nullptr, nullptr, MQ_, D_, D_);
        if (multi) cudaStreamWaitEvent(0, ev3, 0);
        tc_flash<2><<<gFA, 256, TF_SMEM_BYTES>>>(ath, qh, k2h, v2, SQ_);
        tc_gemm<1><<<gProj, 256, GT_SMEM_BYTES>>>(tmp, ath, (__half*)sym(g_wo2h), bo2, x1, MQ_, D_, D_);
        layernorm_kernel<1><<<lnBlocks, 256>>>(x2, x2h, tmp, ln2_g, ln2_b, MQ_);

        // ---- Stage 3: FFN ----
        tc_gemm<2><<<gFFN1, 256, GT_SMEM_BYTES>>>(hh, x2h, (__half*)sym(g_fw1h), ffn_b1, nullptr, MQ_, DF_, D_);
        tc_gemm<1><<<gProj, 256, GT_SMEM_BYTES>>>(tmp, hh, (__half*)sym(g_fw2h), ffn_b2, x2, MQ_, D_, DF_);
        layernorm_kernel<0><<<lnBlocks, 256>>>(out, nullptr, tmp, ln3_g, ln3_b, MQ_);
    } else {
        // -------- full SIMT fallback (round-1 proven path) --------
        cudaFuncSetAttribute((const void*)flash_kernel<1>, cudaFuncAttributeMaxDynamicSharedMemorySize, FA_SMEM_BYTES);
        cudaFuncSetAttribute((const void*)flash_kernel<2>, cudaFuncAttributeMaxDynamicSharedMemorySize, FA_SMEM_BYTES);
        float* q = (float*)sym(g_fa);
        float* k = (float*)sym(g_fb);
        float* v = (float*)sym(g_fc);
        float* attn = (float*)sym(g_fd);
        float* hbuf = (float*)sym(g_fd);

        sgemm_kernel<0><<<gProj, 256>>>(q, cords,   wq1, nullptr, nullptr, MQ_,   D_, D_);
        sgemm_kernel<0><<<gKV1,  256>>>(k, spatial, wk1, nullptr, nullptr, MKV1_, D_, D_);
        sgemm_kernel<0><<<gKV1,  256>>>(v, spatial, wv1, nullptr, nullptr, MKV1_, D_, D_);
        flash_kernel<1><<<gFA, 256, FA_SMEM_BYTES>>>(attn, q, k, v, SKV1_);
        sgemm_kernel<1><<<gProj, 256>>>(tmp, attn, wo1, bo1, cords, MQ_, D_, D_);
        layernorm_kernel<0><<<lnBlocks, 256>>>(x1, nullptr, tmp, ln1_g, ln1_b, MQ_);

        sgemm_kernel<0><<<gProj, 256>>>(q, x1,    wq2, nullptr, nullptr, MQ_, D_, D_);
        sgemm_kernel<0><<<gProj, 256>>>(k, speed, wk2, nullptr, nullptr, MQ_, D_, D_);
        sgemm_kernel<0><<<gProj, 256>>>(v, speed, wv2, nullptr, nullptr, MQ_, D_, D_);
        flash_kernel<2><<<gFA, 256, FA_SMEM_BYTES>>>(attn, q, k, v, SQ_);
        sgemm_kernel<1><<<gProj, 256>>>(tmp, attn, wo2, bo2, x1, MQ_, D_, D_);
        layernorm_kernel<0><<<lnBlocks, 256>>>(x2, nullptr, tmp, ln2_g, ln2_b, MQ_);

        sgemm_kernel<2><<<gFFN1, 256>>>(hbuf, x2, ffn_w1, ffn_b1, nullptr, MQ_, DF_, D_);
        sgemm_kernel<1><<<gProj, 256>>>(tmp, hbuf, ffn_w2, ffn_b2, x2, MQ_, D_, DF_);
        layernorm_kernel<0><<<lnBlocks, 256>>>(out, nullptr, tmp, ln3_g, ln3_b, MQ_);
    }
}